// round 6
// baseline (speedup 1.0000x reference)
#include <cuda_runtime.h>
#include <math.h>

#define NMAX 25000
#define EMAX 400000
#define HID 128
#define INNER 160
#define EB 64      // edges per block
#define NB 32      // nodes per block (k_node)

// ---------------- scratch ----------------
__device__ float g_m[(size_t)EMAX * 160];      // per-edge message m
__device__ float g_logits[(size_t)EMAX * 8];
__device__ float g_msgx[(size_t)EMAX * 3];
__device__ float g_hagg[(size_t)NMAX * 128];
__device__ float g_P[(size_t)NMAX * 320];      // precomputed h@We1 (src half | dst half)
__device__ int g_deg[NMAX];
__device__ int g_cursor[NMAX];
__device__ int g_start[NMAX + 1];
__device__ int g_eid[EMAX];

// ---------------- helpers ----------------
typedef unsigned long long ull;
__device__ __forceinline__ ull pk2(float a, float b) {
    ull r;
    asm("mov.b64 %0, {%1, %2};" : "=l"(r) : "r"(__float_as_uint(a)), "r"(__float_as_uint(b)));
    return r;
}
__device__ __forceinline__ void upk2(ull v, float &a, float &b) {
    unsigned int lo, hi;
    asm("mov.b64 {%0, %1}, %2;" : "=r"(lo), "=r"(hi) : "l"(v));
    a = __uint_as_float(lo); b = __uint_as_float(hi);
}
__device__ __forceinline__ void ffma2(ull &d, ull a, ull b) {
    asm("fma.rn.f32x2 %0, %1, %2, %3;" : "=l"(d) : "l"(a), "l"(b), "l"(d));
}
__device__ __forceinline__ float siluf(float x) { return x / (1.0f + __expf(-x)); }
__device__ __forceinline__ float getc(const float4& v, int kk) {
    return kk == 0 ? v.x : kk == 1 ? v.y : kk == 2 ? v.z : v.w;
}

// ---------------- CSR build ----------------
__global__ void k_zero(int n) {
    int i = blockIdx.x * blockDim.x + threadIdx.x;
    if (i < n) { g_deg[i] = 0; g_cursor[i] = 0; }
}
__global__ void k_deg(const int* __restrict__ dst, int E) {
    int e = blockIdx.x * blockDim.x + threadIdx.x;
    if (e < E) atomicAdd(&g_deg[dst[e]], 1);
}
__global__ void k_scan(int n) {
    __shared__ int sh[1024];
    int carry = 0;
    for (int base = 0; base < n; base += 1024) {
        int i = base + threadIdx.x;
        int x = (i < n) ? g_deg[i] : 0;
        sh[threadIdx.x] = x;
        __syncthreads();
        for (int off = 1; off < 1024; off <<= 1) {
            int v = (threadIdx.x >= off) ? sh[threadIdx.x - off] : 0;
            __syncthreads();
            sh[threadIdx.x] += v;
            __syncthreads();
        }
        if (i < n) g_start[i] = carry + sh[threadIdx.x] - x;
        carry += sh[1023];
        __syncthreads();
    }
    if (threadIdx.x == 0) g_start[n] = carry;
}
__global__ void k_fill(const int* __restrict__ dst, int E) {
    int e = blockIdx.x * blockDim.x + threadIdx.x;
    if (e < E) {
        int d = dst[e];
        int p = atomicAdd(&g_cursor[d], 1);
        g_eid[g_start[d] + p] = e;
    }
}

// ---------------- precompute P[n] = [h@We1[0:128] | h@We1[128:256]] ----------------
__global__ void __launch_bounds__(256) k_pre(const float* __restrict__ h,
                                             const float* __restrict__ We1, int N)
{
    __shared__ float sH[32][132];
    const int nb = blockIdx.x * 32;
    const int tid = threadIdx.x;
    for (int idx = tid; idx < 32 * 128; idx += 256) {
        int r = idx >> 7, c = idx & 127;
        int n = min(nb + r, N - 1);
        sH[r][c] = h[(size_t)n * 128 + c];
    }
    __syncthreads();

    const int ecg = tid >> 5, jcg = tid & 31;
    ull accA[4][3], accB[4][3];
    #pragma unroll
    for (int i = 0; i < 4; i++)
        #pragma unroll
        for (int p = 0; p < 3; p++) { accA[i][p] = 0; accB[i][p] = 0; }

    for (int k = 0; k < 128; k++) {
        ull fa[4];
        #pragma unroll
        for (int i = 0; i < 4; i++) { float c = sH[ecg + 8 * i][k]; fa[i] = pk2(c, c); }
        const float* w1 = We1 + (size_t)k * INNER;
        const float* w2 = We1 + (size_t)(128 + k) * INNER;
        float4 wa = __ldg((const float4*)(w1 + 4 * jcg));
        float4 wb = __ldg((const float4*)(w2 + 4 * jcg));
        ull A0 = pk2(wa.x, wa.y), A1 = pk2(wa.z, wa.w);
        ull B0 = pk2(wb.x, wb.y), B1 = pk2(wb.z, wb.w);
        ull A2 = 0, B2 = 0;
        if (jcg < 16) {
            float2 ta = __ldg((const float2*)(w1 + 128 + 2 * jcg));
            float2 tb = __ldg((const float2*)(w2 + 128 + 2 * jcg));
            A2 = pk2(ta.x, ta.y); B2 = pk2(tb.x, tb.y);
        }
        #pragma unroll
        for (int i = 0; i < 4; i++) {
            ffma2(accA[i][0], fa[i], A0); ffma2(accA[i][1], fa[i], A1);
            ffma2(accB[i][0], fa[i], B0); ffma2(accB[i][1], fa[i], B1);
            if (jcg < 16) { ffma2(accA[i][2], fa[i], A2); ffma2(accB[i][2], fa[i], B2); }
        }
    }
    #pragma unroll
    for (int i = 0; i < 4; i++) {
        int n = nb + ecg + 8 * i;
        if (n < N) {
            float* out = g_P + (size_t)n * 320;
            float x0, x1, x2, x3;
            upk2(accA[i][0], x0, x1); upk2(accA[i][1], x2, x3);
            *(float4*)(out + 4 * jcg) = make_float4(x0, x1, x2, x3);
            upk2(accB[i][0], x0, x1); upk2(accB[i][1], x2, x3);
            *(float4*)(out + 160 + 4 * jcg) = make_float4(x0, x1, x2, x3);
            if (jcg < 16) {
                upk2(accA[i][2], x0, x1);
                *(float2*)(out + 128 + 2 * jcg) = make_float2(x0, x1);
                upk2(accB[i][2], x0, x1);
                *(float2*)(out + 288 + 2 * jcg) = make_float2(x0, x1);
            }
        }
    }
}

// ---------------- fused edge kernel (128 threads, 8 rows x 10 cols per thread) ----------------
__global__ void __launch_bounds__(128, 4) k_edge(
    const float* __restrict__ coords, const float* __restrict__ a,
    const int* __restrict__ src, const int* __restrict__ dst,
    const float* __restrict__ We1, const float* __restrict__ be1,
    const float* __restrict__ We2, const float* __restrict__ be2,
    const float* __restrict__ Wc, const float* __restrict__ Wa,
    int E)
{
    extern __shared__ float sm_e[];
    float* sm1  = sm_e;               // [64][164]
    float* sA   = sm1 + 64 * 164;     // [64][16]
    float* sRad = sA + 64 * 16;       // [64]
    float* sDx  = sRad + 64;          // [64]
    float* sDy  = sDx + 64;
    float* sDz  = sDy + 64;
    int*   sSrc = (int*)(sDz + 64);   // [64]
    int*   sDst = sSrc + 64;          // [64]

    const int tid = threadIdx.x;
    const int eg = blockIdx.x * EB;
    const int warp = tid >> 5, lane = tid & 31;

    // ---- gather edge extras ----
    for (int e = warp; e < EB; e += 4) {
        int ed = eg + e; if (ed > E - 1) ed = E - 1;
        if (lane < 16) sA[e * 16 + lane] = __ldg(a + (size_t)ed * 16 + lane);
        if (lane == 0) {
            int si = src[ed], di = dst[ed];
            sSrc[e] = si; sDst[e] = di;
            float dx = coords[si * 3 + 0] - coords[di * 3 + 0];
            float dy = coords[si * 3 + 1] - coords[di * 3 + 1];
            float dz = coords[si * 3 + 2] - coords[di * 3 + 2];
            sRad[e] = dx * dx + dy * dy + dz * dz;
            sDx[e] = dx; sDy[e] = dy; sDz[e] = dz;
        }
    }
    __syncthreads();

    const int ecg = tid >> 4;   // 0..7, rows 8*ecg + i (i 0..7)
    const int jcg = tid & 15;   // cols 4jcg..+3, 64+4jcg..+3, 128+2jcg,+1

    // ---- GEMM1-lite: m1 = silu(P1[src] + P2[dst] + [rad,a]@We1[256:273] + be1) ----
    {
        ull acc[8][5];
        #pragma unroll
        for (int i = 0; i < 8; i++) {
            int r = 8 * ecg + i;
            const float* Ps = g_P + (size_t)sSrc[r] * 320;
            const float* Pd = g_P + (size_t)sDst[r] * 320 + 160;
            float4 a0 = __ldg((const float4*)(Ps + 4 * jcg));
            float4 b0 = __ldg((const float4*)(Pd + 4 * jcg));
            acc[i][0] = pk2(a0.x + b0.x, a0.y + b0.y);
            acc[i][1] = pk2(a0.z + b0.z, a0.w + b0.w);
            float4 a1 = __ldg((const float4*)(Ps + 64 + 4 * jcg));
            float4 b1 = __ldg((const float4*)(Pd + 64 + 4 * jcg));
            acc[i][2] = pk2(a1.x + b1.x, a1.y + b1.y);
            acc[i][3] = pk2(a1.z + b1.z, a1.w + b1.w);
            float2 a2 = __ldg((const float2*)(Ps + 128 + 2 * jcg));
            float2 b2 = __ldg((const float2*)(Pd + 128 + 2 * jcg));
            acc[i][4] = pk2(a2.x + b2.x, a2.y + b2.y);
        }
        // k = 0..16: radial + edge attrs (We1 rows 256..272)
        #pragma unroll 4
        for (int k = 0; k < 17; k++) {
            const float* wr = We1 + (size_t)(256 + k) * INNER;
            float4 w0 = __ldg((const float4*)(wr + 4 * jcg));
            float4 w1 = __ldg((const float4*)(wr + 64 + 4 * jcg));
            float2 w2 = __ldg((const float2*)(wr + 128 + 2 * jcg));
            ull W00 = pk2(w0.x, w0.y), W01 = pk2(w0.z, w0.w);
            ull W10 = pk2(w1.x, w1.y), W11 = pk2(w1.z, w1.w);
            ull W2  = pk2(w2.x, w2.y);
            #pragma unroll
            for (int i = 0; i < 8; i++) {
                int r = 8 * ecg + i;
                float c = (k == 0) ? sRad[r] : sA[r * 16 + (k - 1)];
                ull fa = pk2(c, c);
                ffma2(acc[i][0], fa, W00); ffma2(acc[i][1], fa, W01);
                ffma2(acc[i][2], fa, W10); ffma2(acc[i][3], fa, W11);
                ffma2(acc[i][4], fa, W2);
            }
        }
        #pragma unroll
        for (int i = 0; i < 8; i++) {
            float* orow = sm1 + (8 * ecg + i) * 164;
            float lo, hi;
            int c = 4 * jcg;
            upk2(acc[i][0], lo, hi);
            orow[c]   = siluf(lo + __ldg(be1 + c));     orow[c+1] = siluf(hi + __ldg(be1 + c + 1));
            upk2(acc[i][1], lo, hi);
            orow[c+2] = siluf(lo + __ldg(be1 + c + 2)); orow[c+3] = siluf(hi + __ldg(be1 + c + 3));
            c = 64 + 4 * jcg;
            upk2(acc[i][2], lo, hi);
            orow[c]   = siluf(lo + __ldg(be1 + c));     orow[c+1] = siluf(hi + __ldg(be1 + c + 1));
            upk2(acc[i][3], lo, hi);
            orow[c+2] = siluf(lo + __ldg(be1 + c + 2)); orow[c+3] = siluf(hi + __ldg(be1 + c + 3));
            c = 128 + 2 * jcg;
            upk2(acc[i][4], lo, hi);
            orow[c]   = siluf(lo + __ldg(be1 + c));     orow[c+1] = siluf(hi + __ldg(be1 + c + 1));
        }
    }
    __syncthreads();

    // ---- GEMM2 (in-place): m = silu(m1 @ We2 + be2) ----
    {
        ull acc[8][5];
        #pragma unroll
        for (int i = 0; i < 8; i++)
            #pragma unroll
            for (int p = 0; p < 5; p++) acc[i][p] = 0;
        const float* base = sm1 + (8 * ecg) * 164;
        for (int k2 = 0; k2 < INNER; k2 += 2) {
            float2 av[8];
            #pragma unroll
            for (int i = 0; i < 8; i++) av[i] = *(const float2*)(base + i * 164 + k2);
            #pragma unroll
            for (int kk = 0; kk < 2; kk++) {
                const float* wr = We2 + (size_t)(k2 + kk) * INNER;
                float4 w0 = __ldg((const float4*)(wr + 4 * jcg));
                float4 w1 = __ldg((const float4*)(wr + 64 + 4 * jcg));
                float2 w2 = __ldg((const float2*)(wr + 128 + 2 * jcg));
                ull W00 = pk2(w0.x, w0.y), W01 = pk2(w0.z, w0.w);
                ull W10 = pk2(w1.x, w1.y), W11 = pk2(w1.z, w1.w);
                ull W2  = pk2(w2.x, w2.y);
                #pragma unroll
                for (int i = 0; i < 8; i++) {
                    float c = kk ? av[i].y : av[i].x;
                    ull fa = pk2(c, c);
                    ffma2(acc[i][0], fa, W00); ffma2(acc[i][1], fa, W01);
                    ffma2(acc[i][2], fa, W10); ffma2(acc[i][3], fa, W11);
                    ffma2(acc[i][4], fa, W2);
                }
            }
        }
        __syncthreads();   // all reads of m1 done before in-place overwrite
        #pragma unroll
        for (int i = 0; i < 8; i++) {
            float* orow = sm1 + (8 * ecg + i) * 164;
            float lo, hi;
            int c = 4 * jcg;
            upk2(acc[i][0], lo, hi);
            orow[c]   = siluf(lo + __ldg(be2 + c));     orow[c+1] = siluf(hi + __ldg(be2 + c + 1));
            upk2(acc[i][1], lo, hi);
            orow[c+2] = siluf(lo + __ldg(be2 + c + 2)); orow[c+3] = siluf(hi + __ldg(be2 + c + 3));
            c = 64 + 4 * jcg;
            upk2(acc[i][2], lo, hi);
            orow[c]   = siluf(lo + __ldg(be2 + c));     orow[c+1] = siluf(hi + __ldg(be2 + c + 1));
            upk2(acc[i][3], lo, hi);
            orow[c+2] = siluf(lo + __ldg(be2 + c + 2)); orow[c+3] = siluf(hi + __ldg(be2 + c + 3));
            c = 128 + 2 * jcg;
            upk2(acc[i][4], lo, hi);
            orow[c]   = siluf(lo + __ldg(be2 + c));     orow[c+1] = siluf(hi + __ldg(be2 + c + 1));
        }
    }
    __syncthreads();

    // ---- tail GEMM: logits (8 cols) + coord scalar (1 col), register-tiled ----
    {
        const int jc = tid & 7;          // 0..3: logit pairs; 4: Wc; 5..7: idle
        const int ecg2 = tid >> 3;       // 0..15, rows ecg2 + 16*i
        if (jc < 5) {
            ull acc4[4] = {0, 0, 0, 0};
            for (int k = 0; k < INNER; k++) {
                ull W;
                if (jc < 4) {
                    float2 wa = __ldg((const float2*)(Wa + k * 8 + 2 * jc));
                    W = pk2(wa.x, wa.y);
                } else {
                    W = pk2(__ldg(Wc + k), 0.0f);
                }
                #pragma unroll
                for (int i = 0; i < 4; i++) {
                    float c = sm1[(ecg2 + 16 * i) * 164 + k];
                    ffma2(acc4[i], pk2(c, c), W);
                }
            }
            #pragma unroll
            for (int i = 0; i < 4; i++) {
                int e = ecg2 + 16 * i;
                int ed = eg + e;
                if (ed < E) {
                    float lo, hi; upk2(acc4[i], lo, hi);
                    if (jc < 4) {
                        *(float2*)(g_logits + (size_t)ed * 8 + 2 * jc) = make_float2(lo, hi);
                    } else {
                        float s = lo / (sqrtf(sRad[e] + 1e-5f) + 1.0f);
                        g_msgx[(size_t)ed * 3 + 0] = sDx[e] * s;
                        g_msgx[(size_t)ed * 3 + 1] = sDy[e] * s;
                        g_msgx[(size_t)ed * 3 + 2] = sDz[e] * s;
                    }
                }
            }
        }
    }

    // ---- write m to global ----
    for (int idx = tid; idx < 64 * 40; idx += 128) {
        int r = idx / 40, c4 = idx % 40;
        int ed = eg + r;
        if (ed < E)
            *(float4*)(g_m + (size_t)ed * 160 + 4 * c4) = *(const float4*)(sm1 + r * 164 + 4 * c4);
    }
}

// ---------------- warp-per-node aggregation + batched Wv epilogue ----------------
__global__ void __launch_bounds__(256) k_agg(const float* __restrict__ coords,
                                             const float* __restrict__ Wv,
                                             float* __restrict__ out_coords, int N)
{
    __shared__ float sS[8][8][164];   // node, head, k
    const int tid = threadIdx.x;
    const int warp = tid >> 5, lane = tid & 31;
    const int nb = blockIdx.x * 8;
    const int n = nb + warp;

    if (n < N) {
        const int s0 = g_start[n];
        const int deg = g_start[n + 1] - s0;

        // --- softmax stats: lane layout (le = lane>>3 edge slot, lh = lane&7 head) ---
        const int le = lane >> 3, lh = lane & 7;
        float mx = -3.0e38f;
        for (int c = 0; c < deg; c += 4) {
            int i = c + le;
            if (i < deg) {
                int e = g_eid[s0 + i];
                mx = fmaxf(mx, __ldg(g_logits + (size_t)e * 8 + lh));
            }
        }
        mx = fmaxf(mx, __shfl_xor_sync(~0u, mx, 8));
        mx = fmaxf(mx, __shfl_xor_sync(~0u, mx, 16));
        float den = 0.f;
        for (int c = 0; c < deg; c += 4) {
            int i = c + le;
            if (i < deg) {
                int e = g_eid[s0 + i];
                den += __expf(__ldg(g_logits + (size_t)e * 8 + lh) - mx);
            }
        }
        den += __shfl_xor_sync(~0u, den, 8);
        den += __shfl_xor_sync(~0u, den, 16);

        // --- s[h][k] accumulation: lane layout (hh = lane>>2, ks = (lane&3)*40) ---
        const int hh = lane >> 2, ks = (lane & 3) * 40;
        float mxh = __shfl_sync(~0u, mx, hh);     // lanes 0..7 hold heads 0..7
        float denh = __shfl_sync(~0u, den, hh);
        float acc[40];
        #pragma unroll
        for (int d = 0; d < 40; d++) acc[d] = 0.f;

        for (int i = 0; i < deg; i++) {
            int e = g_eid[s0 + i];
            float w = __expf(__ldg(g_logits + (size_t)e * 8 + hh) - mxh) / denh;
            const float4* mrow = (const float4*)(g_m + (size_t)e * 160 + ks);
            #pragma unroll
            for (int q = 0; q < 10; q++) {
                float4 v = __ldg(mrow + q);
                acc[4*q]   += v.x * w; acc[4*q+1] += v.y * w;
                acc[4*q+2] += v.z * w; acc[4*q+3] += v.w * w;
            }
        }
        #pragma unroll
        for (int q = 0; q < 10; q++)
            *(float4*)(&sS[warp][hh][ks + 4 * q]) = make_float4(acc[4*q], acc[4*q+1], acc[4*q+2], acc[4*q+3]);

        // --- coordinate scatter-sum (lanes 0..2) ---
        if (lane < 3) {
            float cacc = 0.f;
            for (int i = 0; i < deg; i++)
                cacc += __ldg(g_msgx + (size_t)g_eid[s0 + i] * 3 + lane);
            out_coords[n * 3 + lane] = coords[n * 3 + lane] + cacc;
        }
    }
    __syncthreads();

    // --- batched Wv epilogue: h_agg[n][j] = sum_k sS[n][j>>4][k] * Wv[k][j] ---
    {
        const int j = tid & 127, grp = tid >> 7;     // grp 0..1, 4 nodes each
        const int head = j >> 4;
        #pragma unroll
        for (int r = 0; r < 4; r++) {
            int wn = grp * 4 + r;
            int n2 = nb + wn;
            if (n2 < N) {
                const float* sr = sS[wn][head];
                float hv = 0.f;
                #pragma unroll 8
                for (int k = 0; k < INNER; k++) hv += sr[k] * __ldg(Wv + k * 128 + j);
                g_hagg[(size_t)n2 * 128 + j] = hv;
            }
        }
    }
}

// ---------------- batched node GEMM helpers ----------------
template<int K, int NP, int C>
__device__ __forceinline__ void gemm_n(const float* __restrict__ sIn, int is,
                                       const float* __restrict__ W,
                                       ull (&acc)[4][NP][2]) {
    const int tid = threadIdx.x;
    const int ecg = tid >> 5, jcg = tid & 31;
    #pragma unroll
    for (int i = 0; i < 4; i++)
        #pragma unroll
        for (int p = 0; p < NP; p++) { acc[i][p][0] = 0; acc[i][p][1] = 0; }
    for (int k4 = 0; k4 < K; k4 += 4) {
        float4 av[4];
        #pragma unroll
        for (int i = 0; i < 4; i++) av[i] = *(const float4*)(sIn + (ecg + 8 * i) * is + k4);
        #pragma unroll
        for (int kk = 0; kk < 4; kk++) {
            ull fa[4];
            #pragma unroll
            for (int i = 0; i < 4; i++) { float c = getc(av[i], kk); fa[i] = pk2(c, c); }
            const float* wr = W + (k4 + kk) * C + 4 * jcg;
            #pragma unroll
            for (int p = 0; p < NP; p++) {
                if ((C % 128 == 0) || (128 * p + 4 * jcg < C)) {
                    float4 wv = __ldg((const float4*)(wr + 128 * p));
                    ull w0 = pk2(wv.x, wv.y), w1 = pk2(wv.z, wv.w);
                    #pragma unroll
                    for (int i = 0; i < 4; i++) { ffma2(acc[i][p][0], fa[i], w0); ffma2(acc[i][p][1], fa[i], w1); }
                }
            }
        }
    }
}

template<int NP, int C>
__device__ __forceinline__ void store_acc(ull (&acc)[4][NP][2], float* sOut, int os,
                                          const float* bias, bool dosilu) {
    const int tid = threadIdx.x, ecg = tid >> 5, jcg = tid & 31;
    #pragma unroll
    for (int i = 0; i < 4; i++) {
        int r = ecg + 8 * i;
        #pragma unroll
        for (int p = 0; p < NP; p++) {
            int c0 = 128 * p + 4 * jcg;
            if ((C % 128 == 0) || (c0 < C)) {
                float v0, v1, v2, v3;
                upk2(acc[i][p][0], v0, v1); upk2(acc[i][p][1], v2, v3);
                if (bias) {
                    v0 += __ldg(bias + c0); v1 += __ldg(bias + c0 + 1);
                    v2 += __ldg(bias + c0 + 2); v3 += __ldg(bias + c0 + 3);
                }
                if (dosilu) { v0 = siluf(v0); v1 = siluf(v1); v2 = siluf(v2); v3 = siluf(v3); }
                *(float4*)(sOut + r * os + c0) = make_float4(v0, v1, v2, v3);
            }
        }
    }
}

__device__ __forceinline__ void film_store(ull (&acc)[4][2][2], float* sScale, float* sShift,
                                           const float* bias) {
    const int tid = threadIdx.x, ecg = tid >> 5, jcg = tid & 31;
    #pragma unroll
    for (int i = 0; i < 4; i++) {
        int r = ecg + 8 * i;
        int c0 = 4 * jcg;
        float v0, v1, v2, v3;
        upk2(acc[i][0][0], v0, v1); upk2(acc[i][0][1], v2, v3);
        v0 += __ldg(bias + c0); v1 += __ldg(bias + c0 + 1);
        v2 += __ldg(bias + c0 + 2); v3 += __ldg(bias + c0 + 3);
        *(float4*)(sScale + r * 132 + c0) = make_float4(v0, v1, v2, v3);
        upk2(acc[i][1][0], v0, v1); upk2(acc[i][1][1], v2, v3);
        v0 += __ldg(bias + 128 + c0); v1 += __ldg(bias + 128 + c0 + 1);
        v2 += __ldg(bias + 128 + c0 + 2); v3 += __ldg(bias + 128 + c0 + 3);
        *(float4*)(sShift + r * 164 + c0) = make_float4(v0, v1, v2, v3);
    }
}

__device__ __forceinline__ void ln_stats(const float* sX, float* sMu, float* sRs) {
    int w = threadIdx.x >> 5, lane = threadIdx.x & 31;
    #pragma unroll
    for (int rr = 0; rr < 4; rr++) {
        int r = w * 4 + rr;
        float4 v = *(const float4*)(sX + r * 132 + 4 * lane);
        float s = v.x + v.y + v.z + v.w;
        float q = v.x * v.x + v.y * v.y + v.z * v.z + v.w * v.w;
        #pragma unroll
        for (int o = 16; o; o >>= 1) {
            s += __shfl_xor_sync(~0u, s, o);
            q += __shfl_xor_sync(~0u, q, o);
        }
        if (lane == 0) {
            float mu = s * (1.f / 128.f);
            float var = q * (1.f / 128.f) - mu * mu;
            sMu[r] = mu; sRs[r] = rsqrtf(var + 1e-5f);
        }
    }
}

// ---------------- batched node kernel (32 nodes/block) ----------------
__global__ void __launch_bounds__(256, 2) k_node(
    const float* __restrict__ h, const float* __restrict__ res, const float* __restrict__ y,
    const float* __restrict__ Wo,
    const float* __restrict__ Wn1, const float* __restrict__ bn1,
    const float* __restrict__ Wn2, const float* __restrict__ bn2,
    const float* __restrict__ Wf1, const float* __restrict__ bf1,
    const float* __restrict__ Wf2, const float* __restrict__ bf2,
    float* __restrict__ out_h2, float* __restrict__ out_res2, int N)
{
    extern __shared__ float sm_n[];
    float* sA  = sm_n;                 // [32][164]
    float* sB  = sA + 32 * 164;        // [32][132]
    float* sC  = sB + 32 * 132;        // [32][132]
    float* sY  = sC + 32 * 132;        // [32][68]
    float* sMu = sY + 32 * 68;         // [32]
    float* sRs = sMu + 32;             // [32]

    const int nb = blockIdx.x * NB;
    const int tid = threadIdx.x;

    for (int idx = tid; idx < 32 * 128; idx += 256) {
        int r = idx >> 7, c = idx & 127;
        int n = min(nb + r, N - 1);
        sB[r * 132 + c] = g_hagg[(size_t)n * 128 + c];
    }
    for (int idx = tid; idx < 32 * 64; idx += 256) {
        int r = idx >> 6, c = idx & 63;
        int n = min(nb + r, N - 1);
        sY[r * 68 + c] = y[(size_t)n * 64 + c];
    }
    __syncthreads();

    {
        ull acc[4][1][2];
        gemm_n<128, 1, 128>(sB, 132, Wo, acc);
        store_acc<1, 128>(acc, sC, 132, nullptr, false);
    }
    __syncthreads();

    float f2r[16];
    #pragma unroll
    for (int t = 0; t < 16; t++) {
        int idx = tid + 256 * t;
        int r = idx >> 7, c = idx & 127;
        int n = min(nb + r, N - 1);
        float f2v = sC[r * 132 + c];
        f2r[t] = f2v;
        sB[r * 132 + c] = h[(size_t)n * 128 + c] + f2v;
    }
    __syncthreads();
    ln_stats(sB, sMu, sRs);
    __syncthreads();

    {
        ull acc[4][2][2];
        gemm_n<64, 2, 256>(sY, 68, Wf1, acc);
        film_store(acc, sC, sA, bf1);
    }
    __syncthreads();

    #pragma unroll
    for (int t = 0; t < 16; t++) {
        int idx = tid + 256 * t;
        int r = idx >> 7, c = idx & 127;
        float x = sB[r * 132 + c];
        float xn = (x - sMu[r]) * sRs[r];
        sB[r * 132 + c] = xn * (1.f + sC[r * 132 + c]) + sA[r * 164 + c];
    }
    __syncthreads();

    {
        ull acc[4][2][2];
        gemm_n<128, 2, 160>(sB, 132, Wn1, acc);
        store_acc<2, 160>(acc, sA, 164, bn1, true);
    }
    __syncthreads();

    {
        ull acc[4][1][2];
        gemm_n<160, 1, 128>(sA, 164, Wn2, acc);
        store_acc<1, 128>(acc, sC, 132, bn2, false);
    }
    __syncthreads();

    #pragma unroll
    for (int t = 0; t < 16; t++) {
        int idx = tid + 256 * t;
        int r = idx >> 7, c = idx & 127;
        float f3 = sC[r * 132 + c];
        int n = nb + r;
        if (n < N) out_res2[(size_t)n * 128 + c] = res[(size_t)n * 128 + c] + f2r[t] + f3;
        sB[r * 132 + c] += f3;
    }
    __syncthreads();
    ln_stats(sB, sMu, sRs);
    __syncthreads();

    {
        ull acc[4][2][2];
        gemm_n<64, 2, 256>(sY, 68, Wf2, acc);
        film_store(acc, sC, sA, bf2);
    }
    __syncthreads();

    #pragma unroll
    for (int t = 0; t < 16; t++) {
        int idx = tid + 256 * t;
        int r = idx >> 7, c = idx & 127;
        int n = nb + r;
        if (n < N) {
            float xn = (sB[r * 132 + c] - sMu[r]) * sRs[r];
            out_h2[(size_t)n * 128 + c] = xn * (1.f + sC[r * 132 + c]) + sA[r * 164 + c];
        }
    }
}

// ---------------- launch ----------------
extern "C" void kernel_launch(void* const* d_in, const int* in_sizes, int n_in,
                              void* d_out, int out_size) {
    const float* h      = (const float*)d_in[0];
    const float* coords = (const float*)d_in[1];
    const float* a      = (const float*)d_in[2];
    const float* y      = (const float*)d_in[3];
    const float* res    = (const float*)d_in[4];
    const int*   src    = (const int*)d_in[5];
    const int*   dst    = (const int*)d_in[6];
    const float* We1 = (const float*)d_in[7];
    const float* be1 = (const float*)d_in[8];
    const float* We2 = (const float*)d_in[9];
    const float* be2 = (const float*)d_in[10];
    const float* Wc  = (const float*)d_in[11];
    const float* Wv  = (const float*)d_in[12];
    const float* Wa  = (const float*)d_in[13];
    const float* Wo  = (const float*)d_in[14];
    const float* Wn1 = (const float*)d_in[15];
    const float* bn1 = (const float*)d_in[16];
    const float* Wn2 = (const float*)d_in[17];
    const float* bn2 = (const float*)d_in[18];
    const float* Wf1 = (const float*)d_in[19];
    const float* bf1 = (const float*)d_in[20];
    const float* Wf2 = (const float*)d_in[21];
    const float* bf2 = (const float*)d_in[22];

    const int N = in_sizes[0] / HID;
    const int E = in_sizes[5];

    float* out = (float*)d_out;
    float* out_h2 = out;
    float* out_coords = out + (size_t)N * HID;
    float* out_res2 = out + (size_t)N * HID + (size_t)N * 3;

    const int SMEM_E = (64 * 164 + 64 * 16 + 64 * 6) * (int)sizeof(float);
    const int SMEM_N = (32 * 164 + 32 * 132 * 2 + 32 * 68 + 64) * (int)sizeof(float);
    cudaFuncSetAttribute(k_edge, cudaFuncAttributeMaxDynamicSharedMemorySize, SMEM_E);
    cudaFuncSetAttribute(k_node, cudaFuncAttributeMaxDynamicSharedMemorySize, SMEM_N);

    k_zero<<<(N + 255) / 256, 256>>>(N);
    k_deg<<<(E + 255) / 256, 256>>>(dst, E);
    k_pre<<<(N + 31) / 32, 256>>>(h, We1, N);
    // k_edge 4th: the ncu window captures launch #4
    k_edge<<<(E + EB - 1) / EB, 128, SMEM_E>>>(coords, a, src, dst,
                                               We1, be1, We2, be2, Wc, Wa, E);
    k_scan<<<1, 1024>>>(N);
    k_fill<<<(E + 255) / 256, 256>>>(dst, E);
    k_agg<<<(N + 7) / 8, 256>>>(coords, Wv, out_coords, N);
    k_node<<<(N + NB - 1) / NB, 256, SMEM_N>>>(h, res, y, Wo, Wn1, bn1, Wn2, bn2,
                                               Wf1, bf1, Wf2, bf2, out_h2, out_res2, N);
}

// round 7
// speedup vs baseline: 1.1046x; 1.1046x over previous
#include <cuda_runtime.h>
#include <math.h>

#define NMAX 25000
#define EMAX 400000
#define HID 128
#define INNER 160
#define EB 64      // edges per block
#define NB 32      // nodes per block (k_node)

// ---------------- scratch ----------------
__device__ float g_m[(size_t)EMAX * 160];      // per-edge message m
__device__ float g_logits[(size_t)EMAX * 8];
__device__ float g_msgx[(size_t)EMAX * 3];
__device__ float g_hagg[(size_t)NMAX * 128];
__device__ float g_P[(size_t)NMAX * 320];      // precomputed h@We1 (src half | dst half)
__device__ int g_deg[NMAX];
__device__ int g_cursor[NMAX];
__device__ int g_start[NMAX + 1];
__device__ int g_eid[EMAX];

// ---------------- helpers ----------------
typedef unsigned long long ull;
__device__ __forceinline__ ull pk2(float a, float b) {
    ull r;
    asm("mov.b64 %0, {%1, %2};" : "=l"(r) : "r"(__float_as_uint(a)), "r"(__float_as_uint(b)));
    return r;
}
__device__ __forceinline__ void upk2(ull v, float &a, float &b) {
    unsigned int lo, hi;
    asm("mov.b64 {%0, %1}, %2;" : "=r"(lo), "=r"(hi) : "l"(v));
    a = __uint_as_float(lo); b = __uint_as_float(hi);
}
__device__ __forceinline__ void ffma2(ull &d, ull a, ull b) {
    asm("fma.rn.f32x2 %0, %1, %2, %3;" : "=l"(d) : "l"(a), "l"(b), "l"(d));
}
__device__ __forceinline__ float siluf(float x) { return x / (1.0f + __expf(-x)); }
__device__ __forceinline__ float getc(const float4& v, int kk) {
    return kk == 0 ? v.x : kk == 1 ? v.y : kk == 2 ? v.z : v.w;
}

// ---------------- CSR build ----------------
__global__ void k_zero(int n) {
    int i = blockIdx.x * blockDim.x + threadIdx.x;
    if (i < n) { g_deg[i] = 0; g_cursor[i] = 0; }
}
__global__ void k_deg(const int* __restrict__ dst, int E) {
    int e = blockIdx.x * blockDim.x + threadIdx.x;
    if (e < E) atomicAdd(&g_deg[dst[e]], 1);
}
__global__ void k_scan(int n) {
    __shared__ int sh[1024];
    int carry = 0;
    for (int base = 0; base < n; base += 1024) {
        int i = base + threadIdx.x;
        int x = (i < n) ? g_deg[i] : 0;
        sh[threadIdx.x] = x;
        __syncthreads();
        for (int off = 1; off < 1024; off <<= 1) {
            int v = (threadIdx.x >= off) ? sh[threadIdx.x - off] : 0;
            __syncthreads();
            sh[threadIdx.x] += v;
            __syncthreads();
        }
        if (i < n) g_start[i] = carry + sh[threadIdx.x] - x;
        carry += sh[1023];
        __syncthreads();
    }
    if (threadIdx.x == 0) g_start[n] = carry;
}
__global__ void k_fill(const int* __restrict__ dst, int E) {
    int e = blockIdx.x * blockDim.x + threadIdx.x;
    if (e < E) {
        int d = dst[e];
        int p = atomicAdd(&g_cursor[d], 1);
        g_eid[g_start[d] + p] = e;
    }
}

// ---------------- precompute P[n] = [h@We1[0:128] | h@We1[128:256]] ----------------
__global__ void __launch_bounds__(256) k_pre(const float* __restrict__ h,
                                             const float* __restrict__ We1, int N)
{
    __shared__ float sH[32][132];
    const int nb = blockIdx.x * 32;
    const int tid = threadIdx.x;
    for (int idx = tid; idx < 32 * 128; idx += 256) {
        int r = idx >> 7, c = idx & 127;
        int n = min(nb + r, N - 1);
        sH[r][c] = h[(size_t)n * 128 + c];
    }
    __syncthreads();

    const int ecg = tid >> 5, jcg = tid & 31;
    ull accA[4][3], accB[4][3];
    #pragma unroll
    for (int i = 0; i < 4; i++)
        #pragma unroll
        for (int p = 0; p < 3; p++) { accA[i][p] = 0; accB[i][p] = 0; }

    for (int k = 0; k < 128; k++) {
        ull fa[4];
        #pragma unroll
        for (int i = 0; i < 4; i++) { float c = sH[ecg + 8 * i][k]; fa[i] = pk2(c, c); }
        const float* w1 = We1 + (size_t)k * INNER;
        const float* w2 = We1 + (size_t)(128 + k) * INNER;
        float4 wa = __ldg((const float4*)(w1 + 4 * jcg));
        float4 wb = __ldg((const float4*)(w2 + 4 * jcg));
        ull A0 = pk2(wa.x, wa.y), A1 = pk2(wa.z, wa.w);
        ull B0 = pk2(wb.x, wb.y), B1 = pk2(wb.z, wb.w);
        ull A2 = 0, B2 = 0;
        if (jcg < 16) {
            float2 ta = __ldg((const float2*)(w1 + 128 + 2 * jcg));
            float2 tb = __ldg((const float2*)(w2 + 128 + 2 * jcg));
            A2 = pk2(ta.x, ta.y); B2 = pk2(tb.x, tb.y);
        }
        #pragma unroll
        for (int i = 0; i < 4; i++) {
            ffma2(accA[i][0], fa[i], A0); ffma2(accA[i][1], fa[i], A1);
            ffma2(accB[i][0], fa[i], B0); ffma2(accB[i][1], fa[i], B1);
            if (jcg < 16) { ffma2(accA[i][2], fa[i], A2); ffma2(accB[i][2], fa[i], B2); }
        }
    }
    #pragma unroll
    for (int i = 0; i < 4; i++) {
        int n = nb + ecg + 8 * i;
        if (n < N) {
            float* out = g_P + (size_t)n * 320;
            float x0, x1, x2, x3;
            upk2(accA[i][0], x0, x1); upk2(accA[i][1], x2, x3);
            *(float4*)(out + 4 * jcg) = make_float4(x0, x1, x2, x3);
            upk2(accB[i][0], x0, x1); upk2(accB[i][1], x2, x3);
            *(float4*)(out + 160 + 4 * jcg) = make_float4(x0, x1, x2, x3);
            if (jcg < 16) {
                upk2(accA[i][2], x0, x1);
                *(float2*)(out + 128 + 2 * jcg) = make_float2(x0, x1);
                upk2(accB[i][2], x0, x1);
                *(float2*)(out + 288 + 2 * jcg) = make_float2(x0, x1);
            }
        }
    }
}

// ---------------- fused edge kernel (R4 winner: 256 threads, 4 rows x 10 cols) ----------------
__global__ void __launch_bounds__(256, 3) k_edge(
    const float* __restrict__ coords, const float* __restrict__ a,
    const int* __restrict__ src, const int* __restrict__ dst,
    const float* __restrict__ We1, const float* __restrict__ be1,
    const float* __restrict__ We2, const float* __restrict__ be2,
    const float* __restrict__ Wc, const float* __restrict__ Wa,
    int E)
{
    extern __shared__ float sm_e[];
    float* sm1  = sm_e;               // [64][164]
    float* sA   = sm1 + 64 * 164;     // [64][16]
    float* sRad = sA + 64 * 16;       // [64]
    float* sDx  = sRad + 64;          // [64]
    float* sDy  = sDx + 64;
    float* sDz  = sDy + 64;
    int*   sSrc = (int*)(sDz + 64);   // [64]
    int*   sDst = sSrc + 64;          // [64]

    const int tid = threadIdx.x;
    const int eg = blockIdx.x * EB;
    const int warp = tid >> 5, lane = tid & 31;

    // ---- gather edge extras ----
    for (int e = warp; e < EB; e += 8) {
        int ed = eg + e; if (ed > E - 1) ed = E - 1;
        if (lane < 16) sA[e * 16 + lane] = __ldg(a + (size_t)ed * 16 + lane);
        if (lane == 0) {
            int si = src[ed], di = dst[ed];
            sSrc[e] = si; sDst[e] = di;
            float dx = coords[si * 3 + 0] - coords[di * 3 + 0];
            float dy = coords[si * 3 + 1] - coords[di * 3 + 1];
            float dz = coords[si * 3 + 2] - coords[di * 3 + 2];
            sRad[e] = dx * dx + dy * dy + dz * dz;
            sDx[e] = dx; sDy[e] = dy; sDz[e] = dz;
        }
    }
    __syncthreads();

    const int ecg = tid >> 4;   // rows ecg + 16*i
    const int jcg = tid & 15;   // cols 4jcg..+3, 64+4jcg..+3, 128+2jcg,+1

    // ---- GEMM1-lite: m1 = silu(P1[src] + P2[dst] + [rad,a]@We1[256:273] + be1) ----
    {
        ull acc[4][5];
        #pragma unroll
        for (int i = 0; i < 4; i++) {
            int r = ecg + 16 * i;
            const float* Ps = g_P + (size_t)sSrc[r] * 320;
            const float* Pd = g_P + (size_t)sDst[r] * 320 + 160;
            float4 a0 = __ldg((const float4*)(Ps + 4 * jcg));
            float4 b0 = __ldg((const float4*)(Pd + 4 * jcg));
            acc[i][0] = pk2(a0.x + b0.x, a0.y + b0.y);
            acc[i][1] = pk2(a0.z + b0.z, a0.w + b0.w);
            float4 a1 = __ldg((const float4*)(Ps + 64 + 4 * jcg));
            float4 b1 = __ldg((const float4*)(Pd + 64 + 4 * jcg));
            acc[i][2] = pk2(a1.x + b1.x, a1.y + b1.y);
            acc[i][3] = pk2(a1.z + b1.z, a1.w + b1.w);
            float2 a2 = __ldg((const float2*)(Ps + 128 + 2 * jcg));
            float2 b2 = __ldg((const float2*)(Pd + 128 + 2 * jcg));
            acc[i][4] = pk2(a2.x + b2.x, a2.y + b2.y);
        }
        // k = 0..16: radial + edge attrs (We1 rows 256..272)
        #pragma unroll 4
        for (int k = 0; k < 17; k++) {
            const float* wr = We1 + (size_t)(256 + k) * INNER;
            float4 w0 = __ldg((const float4*)(wr + 4 * jcg));
            float4 w1 = __ldg((const float4*)(wr + 64 + 4 * jcg));
            float2 w2 = __ldg((const float2*)(wr + 128 + 2 * jcg));
            ull W00 = pk2(w0.x, w0.y), W01 = pk2(w0.z, w0.w);
            ull W10 = pk2(w1.x, w1.y), W11 = pk2(w1.z, w1.w);
            ull W2  = pk2(w2.x, w2.y);
            #pragma unroll
            for (int i = 0; i < 4; i++) {
                int r = ecg + 16 * i;
                float c = (k == 0) ? sRad[r] : sA[r * 16 + (k - 1)];
                ull fa = pk2(c, c);
                ffma2(acc[i][0], fa, W00); ffma2(acc[i][1], fa, W01);
                ffma2(acc[i][2], fa, W10); ffma2(acc[i][3], fa, W11);
                ffma2(acc[i][4], fa, W2);
            }
        }
        #pragma unroll
        for (int i = 0; i < 4; i++) {
            float* orow = sm1 + (ecg + 16 * i) * 164;
            float lo, hi;
            int c = 4 * jcg;
            upk2(acc[i][0], lo, hi);
            orow[c]   = siluf(lo + __ldg(be1 + c));     orow[c+1] = siluf(hi + __ldg(be1 + c + 1));
            upk2(acc[i][1], lo, hi);
            orow[c+2] = siluf(lo + __ldg(be1 + c + 2)); orow[c+3] = siluf(hi + __ldg(be1 + c + 3));
            c = 64 + 4 * jcg;
            upk2(acc[i][2], lo, hi);
            orow[c]   = siluf(lo + __ldg(be1 + c));     orow[c+1] = siluf(hi + __ldg(be1 + c + 1));
            upk2(acc[i][3], lo, hi);
            orow[c+2] = siluf(lo + __ldg(be1 + c + 2)); orow[c+3] = siluf(hi + __ldg(be1 + c + 3));
            c = 128 + 2 * jcg;
            upk2(acc[i][4], lo, hi);
            orow[c]   = siluf(lo + __ldg(be1 + c));     orow[c+1] = siluf(hi + __ldg(be1 + c + 1));
        }
    }
    __syncthreads();

    // ---- GEMM2 (in-place): m = silu(m1 @ We2 + be2) ----
    {
        ull acc[4][5];
        #pragma unroll
        for (int i = 0; i < 4; i++) { acc[i][0]=0; acc[i][1]=0; acc[i][2]=0; acc[i][3]=0; acc[i][4]=0; }
        const float* f0 = sm1 + (ecg +  0) * 164;
        const float* f1 = sm1 + (ecg + 16) * 164;
        const float* f2p = sm1 + (ecg + 32) * 164;
        const float* f3p = sm1 + (ecg + 48) * 164;
        #pragma unroll 2
        for (int k2 = 0; k2 < INNER; k2 += 2) {
            float2 a0 = *(const float2*)(f0 + k2);
            float2 a1 = *(const float2*)(f1 + k2);
            float2 a2 = *(const float2*)(f2p + k2);
            float2 a3 = *(const float2*)(f3p + k2);
            #pragma unroll
            for (int kk = 0; kk < 2; kk++) {
                ull fa[4];
                float c0 = kk ? a0.y : a0.x, c1 = kk ? a1.y : a1.x;
                float c2 = kk ? a2.y : a2.x, c3 = kk ? a3.y : a3.x;
                fa[0] = pk2(c0, c0); fa[1] = pk2(c1, c1);
                fa[2] = pk2(c2, c2); fa[3] = pk2(c3, c3);
                const float* wr = We2 + (size_t)(k2 + kk) * INNER;
                float4 w0 = __ldg((const float4*)(wr + 4 * jcg));
                float4 w1 = __ldg((const float4*)(wr + 64 + 4 * jcg));
                float2 w2 = __ldg((const float2*)(wr + 128 + 2 * jcg));
                ull W00 = pk2(w0.x, w0.y), W01 = pk2(w0.z, w0.w);
                ull W10 = pk2(w1.x, w1.y), W11 = pk2(w1.z, w1.w);
                ull W2  = pk2(w2.x, w2.y);
                #pragma unroll
                for (int i = 0; i < 4; i++) {
                    ffma2(acc[i][0], fa[i], W00); ffma2(acc[i][1], fa[i], W01);
                    ffma2(acc[i][2], fa[i], W10); ffma2(acc[i][3], fa[i], W11);
                    ffma2(acc[i][4], fa[i], W2);
                }
            }
        }
        __syncthreads();   // all reads of m1 done before in-place overwrite
        #pragma unroll
        for (int i = 0; i < 4; i++) {
            float* orow = sm1 + (ecg + 16 * i) * 164;
            float lo, hi;
            int c = 4 * jcg;
            upk2(acc[i][0], lo, hi);
            orow[c]   = siluf(lo + __ldg(be2 + c));     orow[c+1] = siluf(hi + __ldg(be2 + c + 1));
            upk2(acc[i][1], lo, hi);
            orow[c+2] = siluf(lo + __ldg(be2 + c + 2)); orow[c+3] = siluf(hi + __ldg(be2 + c + 3));
            c = 64 + 4 * jcg;
            upk2(acc[i][2], lo, hi);
            orow[c]   = siluf(lo + __ldg(be2 + c));     orow[c+1] = siluf(hi + __ldg(be2 + c + 1));
            upk2(acc[i][3], lo, hi);
            orow[c+2] = siluf(lo + __ldg(be2 + c + 2)); orow[c+3] = siluf(hi + __ldg(be2 + c + 3));
            c = 128 + 2 * jcg;
            upk2(acc[i][4], lo, hi);
            orow[c]   = siluf(lo + __ldg(be2 + c));     orow[c+1] = siluf(hi + __ldg(be2 + c + 1));
        }
    }
    __syncthreads();

    // ---- logits = m @ Wa ----
    #pragma unroll
    for (int pass = 0; pass < 2; pass++) {
        int e = (tid >> 3) + 32 * pass;
        int hh = tid & 7;
        const float* mr = sm1 + e * 164;
        float accl = 0.f;
        #pragma unroll 8
        for (int k = 0; k < INNER; k++) accl += mr[k] * __ldg(Wa + k * 8 + hh);
        int ed = eg + e;
        if (ed < E) g_logits[(size_t)ed * 8 + hh] = accl;
    }

    // ---- coordinate messages ----
    if (tid < EB) {
        int e = tid;
        const float* mr = sm1 + e * 164;
        float c = 0.f;
        #pragma unroll 8
        for (int k = 0; k < INNER; k++) c += mr[k] * __ldg(Wc + k);
        float s = c / (sqrtf(sRad[e] + 1e-5f) + 1.0f);
        int ed = eg + e;
        if (ed < E) {
            g_msgx[(size_t)ed * 3 + 0] = sDx[e] * s;
            g_msgx[(size_t)ed * 3 + 1] = sDy[e] * s;
            g_msgx[(size_t)ed * 3 + 2] = sDz[e] * s;
        }
    }

    // ---- write m to global ----
    for (int idx = tid; idx < 64 * 40; idx += 256) {
        int r = idx / 40, c4 = idx % 40;
        int ed = eg + r;
        if (ed < E)
            *(float4*)(g_m + (size_t)ed * 160 + 4 * c4) = *(const float4*)(sm1 + r * 164 + 4 * c4);
    }
}

// ---------------- warp-per-node aggregation: single-pass m reads ----------------
__global__ void __launch_bounds__(256) k_agg(const float* __restrict__ coords,
                                             const float* __restrict__ Wv,
                                             float* __restrict__ out_coords, int N)
{
    __shared__ float sS[8][8][164];   // node, head, k
    __shared__ float sWw[8][4][8];    // node, edge-slot, head
    __shared__ int sEd[8][4];
    const int tid = threadIdx.x;
    const int warp = tid >> 5, lane = tid & 31;
    const int nb = blockIdx.x * 8;
    const int n = nb + warp;
    const int le = lane >> 3, lh = lane & 7;

    if (n < N) {
        const int s0 = g_start[n];
        const int deg = g_start[n + 1] - s0;

        // --- softmax stats (per head lh, strided over edges by le) ---
        float mx = -3.0e38f;
        for (int c = le; c < deg; c += 4) {
            int e = g_eid[s0 + c];
            mx = fmaxf(mx, __ldg(g_logits + (size_t)e * 8 + lh));
        }
        mx = fmaxf(mx, __shfl_xor_sync(~0u, mx, 8));
        mx = fmaxf(mx, __shfl_xor_sync(~0u, mx, 16));
        float den = 0.f;
        for (int c = le; c < deg; c += 4) {
            int e = g_eid[s0 + c];
            den += __expf(__ldg(g_logits + (size_t)e * 8 + lh) - mx);
        }
        den += __shfl_xor_sync(~0u, den, 8);
        den += __shfl_xor_sync(~0u, den, 16);
        float rden = 1.f / den;

        // --- accumulate s[h][k]: lane owns k = lane + 32q; each m row read once ---
        float acc[8][5];
        #pragma unroll
        for (int hh = 0; hh < 8; hh++)
            #pragma unroll
            for (int q = 0; q < 5; q++) acc[hh][q] = 0.f;

        for (int c = 0; c < deg; c += 4) {
            int len = min(4, deg - c);
            if (le < len) {
                int e = g_eid[s0 + c + le];
                if (lh == 0) sEd[warp][le] = e;
                sWw[warp][le][lh] = __expf(__ldg(g_logits + (size_t)e * 8 + lh) - mx) * rden;
            }
            __syncwarp();
            for (int ii = 0; ii < len; ii++) {
                int e = sEd[warp][ii];
                float4 wlo = *(const float4*)&sWw[warp][ii][0];
                float4 whi = *(const float4*)&sWw[warp][ii][4];
                float v[5];
                #pragma unroll
                for (int q = 0; q < 5; q++)
                    v[q] = __ldg(g_m + (size_t)e * 160 + lane + 32 * q);
                #pragma unroll
                for (int q = 0; q < 5; q++) {
                    acc[0][q] += v[q] * wlo.x; acc[1][q] += v[q] * wlo.y;
                    acc[2][q] += v[q] * wlo.z; acc[3][q] += v[q] * wlo.w;
                    acc[4][q] += v[q] * whi.x; acc[5][q] += v[q] * whi.y;
                    acc[6][q] += v[q] * whi.z; acc[7][q] += v[q] * whi.w;
                }
            }
            __syncwarp();
        }
        #pragma unroll
        for (int hh = 0; hh < 8; hh++)
            #pragma unroll
            for (int q = 0; q < 5; q++)
                sS[warp][hh][lane + 32 * q] = acc[hh][q];

        // --- coordinate scatter-sum (lanes 0..2) ---
        if (lane < 3) {
            float cacc = 0.f;
            for (int i = 0; i < deg; i++)
                cacc += __ldg(g_msgx + (size_t)g_eid[s0 + i] * 3 + lane);
            out_coords[n * 3 + lane] = coords[n * 3 + lane] + cacc;
        }
    }
    __syncthreads();

    // --- batched Wv epilogue: h_agg[n][j] = sum_k sS[n][j>>4][k] * Wv[k][j] ---
    {
        const int j = tid & 127, grp = tid >> 7;     // grp 0..1, 4 nodes each
        const int head = j >> 4;
        #pragma unroll
        for (int r = 0; r < 4; r++) {
            int wn = grp * 4 + r;
            int n2 = nb + wn;
            if (n2 < N) {
                const float* sr = sS[wn][head];
                float hv = 0.f;
                #pragma unroll 8
                for (int k = 0; k < INNER; k++) hv += sr[k] * __ldg(Wv + k * 128 + j);
                g_hagg[(size_t)n2 * 128 + j] = hv;
            }
        }
    }
}

// ---------------- batched node GEMM helpers ----------------
template<int K, int NP, int C>
__device__ __forceinline__ void gemm_n(const float* __restrict__ sIn, int is,
                                       const float* __restrict__ W,
                                       ull (&acc)[4][NP][2]) {
    const int tid = threadIdx.x;
    const int ecg = tid >> 5, jcg = tid & 31;
    #pragma unroll
    for (int i = 0; i < 4; i++)
        #pragma unroll
        for (int p = 0; p < NP; p++) { acc[i][p][0] = 0; acc[i][p][1] = 0; }
    for (int k4 = 0; k4 < K; k4 += 4) {
        float4 av[4];
        #pragma unroll
        for (int i = 0; i < 4; i++) av[i] = *(const float4*)(sIn + (ecg + 8 * i) * is + k4);
        #pragma unroll
        for (int kk = 0; kk < 4; kk++) {
            ull fa[4];
            #pragma unroll
            for (int i = 0; i < 4; i++) { float c = getc(av[i], kk); fa[i] = pk2(c, c); }
            const float* wr = W + (k4 + kk) * C + 4 * jcg;
            #pragma unroll
            for (int p = 0; p < NP; p++) {
                if ((C % 128 == 0) || (128 * p + 4 * jcg < C)) {
                    float4 wv = __ldg((const float4*)(wr + 128 * p));
                    ull w0 = pk2(wv.x, wv.y), w1 = pk2(wv.z, wv.w);
                    #pragma unroll
                    for (int i = 0; i < 4; i++) { ffma2(acc[i][p][0], fa[i], w0); ffma2(acc[i][p][1], fa[i], w1); }
                }
            }
        }
    }
}

template<int NP, int C>
__device__ __forceinline__ void store_acc(ull (&acc)[4][NP][2], float* sOut, int os,
                                          const float* bias, bool dosilu) {
    const int tid = threadIdx.x, ecg = tid >> 5, jcg = tid & 31;
    #pragma unroll
    for (int i = 0; i < 4; i++) {
        int r = ecg + 8 * i;
        #pragma unroll
        for (int p = 0; p < NP; p++) {
            int c0 = 128 * p + 4 * jcg;
            if ((C % 128 == 0) || (c0 < C)) {
                float v0, v1, v2, v3;
                upk2(acc[i][p][0], v0, v1); upk2(acc[i][p][1], v2, v3);
                if (bias) {
                    v0 += __ldg(bias + c0); v1 += __ldg(bias + c0 + 1);
                    v2 += __ldg(bias + c0 + 2); v3 += __ldg(bias + c0 + 3);
                }
                if (dosilu) { v0 = siluf(v0); v1 = siluf(v1); v2 = siluf(v2); v3 = siluf(v3); }
                *(float4*)(sOut + r * os + c0) = make_float4(v0, v1, v2, v3);
            }
        }
    }
}

__device__ __forceinline__ void film_store(ull (&acc)[4][2][2], float* sScale, float* sShift,
                                           const float* bias) {
    const int tid = threadIdx.x, ecg = tid >> 5, jcg = tid & 31;
    #pragma unroll
    for (int i = 0; i < 4; i++) {
        int r = ecg + 8 * i;
        int c0 = 4 * jcg;
        float v0, v1, v2, v3;
        upk2(acc[i][0][0], v0, v1); upk2(acc[i][0][1], v2, v3);
        v0 += __ldg(bias + c0); v1 += __ldg(bias + c0 + 1);
        v2 += __ldg(bias + c0 + 2); v3 += __ldg(bias + c0 + 3);
        *(float4*)(sScale + r * 132 + c0) = make_float4(v0, v1, v2, v3);
        upk2(acc[i][1][0], v0, v1); upk2(acc[i][1][1], v2, v3);
        v0 += __ldg(bias + 128 + c0); v1 += __ldg(bias + 128 + c0 + 1);
        v2 += __ldg(bias + 128 + c0 + 2); v3 += __ldg(bias + 128 + c0 + 3);
        *(float4*)(sShift + r * 164 + c0) = make_float4(v0, v1, v2, v3);
    }
}

__device__ __forceinline__ void ln_stats(const float* sX, float* sMu, float* sRs) {
    int w = threadIdx.x >> 5, lane = threadIdx.x & 31;
    #pragma unroll
    for (int rr = 0; rr < 4; rr++) {
        int r = w * 4 + rr;
        float4 v = *(const float4*)(sX + r * 132 + 4 * lane);
        float s = v.x + v.y + v.z + v.w;
        float q = v.x * v.x + v.y * v.y + v.z * v.z + v.w * v.w;
        #pragma unroll
        for (int o = 16; o; o >>= 1) {
            s += __shfl_xor_sync(~0u, s, o);
            q += __shfl_xor_sync(~0u, q, o);
        }
        if (lane == 0) {
            float mu = s * (1.f / 128.f);
            float var = q * (1.f / 128.f) - mu * mu;
            sMu[r] = mu; sRs[r] = rsqrtf(var + 1e-5f);
        }
    }
}

// ---------------- batched node kernel (32 nodes/block) ----------------
__global__ void __launch_bounds__(256, 2) k_node(
    const float* __restrict__ h, const float* __restrict__ res, const float* __restrict__ y,
    const float* __restrict__ Wo,
    const float* __restrict__ Wn1, const float* __restrict__ bn1,
    const float* __restrict__ Wn2, const float* __restrict__ bn2,
    const float* __restrict__ Wf1, const float* __restrict__ bf1,
    const float* __restrict__ Wf2, const float* __restrict__ bf2,
    float* __restrict__ out_h2, float* __restrict__ out_res2, int N)
{
    extern __shared__ float sm_n[];
    float* sA  = sm_n;                 // [32][164]
    float* sB  = sA + 32 * 164;        // [32][132]
    float* sC  = sB + 32 * 132;        // [32][132]
    float* sY  = sC + 32 * 132;        // [32][68]
    float* sMu = sY + 32 * 68;         // [32]
    float* sRs = sMu + 32;             // [32]

    const int nb = blockIdx.x * NB;
    const int tid = threadIdx.x;

    for (int idx = tid; idx < 32 * 128; idx += 256) {
        int r = idx >> 7, c = idx & 127;
        int n = min(nb + r, N - 1);
        sB[r * 132 + c] = g_hagg[(size_t)n * 128 + c];
    }
    for (int idx = tid; idx < 32 * 64; idx += 256) {
        int r = idx >> 6, c = idx & 63;
        int n = min(nb + r, N - 1);
        sY[r * 68 + c] = y[(size_t)n * 64 + c];
    }
    __syncthreads();

    {
        ull acc[4][1][2];
        gemm_n<128, 1, 128>(sB, 132, Wo, acc);
        store_acc<1, 128>(acc, sC, 132, nullptr, false);
    }
    __syncthreads();

    float f2r[16];
    #pragma unroll
    for (int t = 0; t < 16; t++) {
        int idx = tid + 256 * t;
        int r = idx >> 7, c = idx & 127;
        int n = min(nb + r, N - 1);
        float f2v = sC[r * 132 + c];
        f2r[t] = f2v;
        sB[r * 132 + c] = h[(size_t)n * 128 + c] + f2v;
    }
    __syncthreads();
    ln_stats(sB, sMu, sRs);
    __syncthreads();

    {
        ull acc[4][2][2];
        gemm_n<64, 2, 256>(sY, 68, Wf1, acc);
        film_store(acc, sC, sA, bf1);
    }
    __syncthreads();

    #pragma unroll
    for (int t = 0; t < 16; t++) {
        int idx = tid + 256 * t;
        int r = idx >> 7, c = idx & 127;
        float x = sB[r * 132 + c];
        float xn = (x - sMu[r]) * sRs[r];
        sB[r * 132 + c] = xn * (1.f + sC[r * 132 + c]) + sA[r * 164 + c];
    }
    __syncthreads();

    {
        ull acc[4][2][2];
        gemm_n<128, 2, 160>(sB, 132, Wn1, acc);
        store_acc<2, 160>(acc, sA, 164, bn1, true);
    }
    __syncthreads();

    {
        ull acc[4][1][2];
        gemm_n<160, 1, 128>(sA, 164, Wn2, acc);
        store_acc<1, 128>(acc, sC, 132, bn2, false);
    }
    __syncthreads();

    #pragma unroll
    for (int t = 0; t < 16; t++) {
        int idx = tid + 256 * t;
        int r = idx >> 7, c = idx & 127;
        float f3 = sC[r * 132 + c];
        int n = nb + r;
        if (n < N) out_res2[(size_t)n * 128 + c] = res[(size_t)n * 128 + c] + f2r[t] + f3;
        sB[r * 132 + c] += f3;
    }
    __syncthreads();
    ln_stats(sB, sMu, sRs);
    __syncthreads();

    {
        ull acc[4][2][2];
        gemm_n<64, 2, 256>(sY, 68, Wf2, acc);
        film_store(acc, sC, sA, bf2);
    }
    __syncthreads();

    #pragma unroll
    for (int t = 0; t < 16; t++) {
        int idx = tid + 256 * t;
        int r = idx >> 7, c = idx & 127;
        int n = nb + r;
        if (n < N) {
            float xn = (sB[r * 132 + c] - sMu[r]) * sRs[r];
            out_h2[(size_t)n * 128 + c] = xn * (1.f + sC[r * 132 + c]) + sA[r * 164 + c];
        }
    }
}

// ---------------- launch ----------------
extern "C" void kernel_launch(void* const* d_in, const int* in_sizes, int n_in,
                              void* d_out, int out_size) {
    const float* h      = (const float*)d_in[0];
    const float* coords = (const float*)d_in[1];
    const float* a      = (const float*)d_in[2];
    const float* y      = (const float*)d_in[3];
    const float* res    = (const float*)d_in[4];
    const int*   src    = (const int*)d_in[5];
    const int*   dst    = (const int*)d_in[6];
    const float* We1 = (const float*)d_in[7];
    const float* be1 = (const float*)d_in[8];
    const float* We2 = (const float*)d_in[9];
    const float* be2 = (const float*)d_in[10];
    const float* Wc  = (const float*)d_in[11];
    const float* Wv  = (const float*)d_in[12];
    const float* Wa  = (const float*)d_in[13];
    const float* Wo  = (const float*)d_in[14];
    const float* Wn1 = (const float*)d_in[15];
    const float* bn1 = (const float*)d_in[16];
    const float* Wn2 = (const float*)d_in[17];
    const float* bn2 = (const float*)d_in[18];
    const float* Wf1 = (const float*)d_in[19];
    const float* bf1 = (const float*)d_in[20];
    const float* Wf2 = (const float*)d_in[21];
    const float* bf2 = (const float*)d_in[22];

    const int N = in_sizes[0] / HID;
    const int E = in_sizes[5];

    float* out = (float*)d_out;
    float* out_h2 = out;
    float* out_coords = out + (size_t)N * HID;
    float* out_res2 = out + (size_t)N * HID + (size_t)N * 3;

    const int SMEM_E = (64 * 164 + 64 * 16 + 64 * 6) * (int)sizeof(float);
    const int SMEM_N = (32 * 164 + 32 * 132 * 2 + 32 * 68 + 64) * (int)sizeof(float);
    cudaFuncSetAttribute(k_edge, cudaFuncAttributeMaxDynamicSharedMemorySize, SMEM_E);
    cudaFuncSetAttribute(k_node, cudaFuncAttributeMaxDynamicSharedMemorySize, SMEM_N);

    k_zero<<<(N + 255) / 256, 256>>>(N);
    k_deg<<<(E + 255) / 256, 256>>>(dst, E);
    k_pre<<<(N + 31) / 32, 256>>>(h, We1, N);
    // k_edge 4th: the ncu window captures launch #4
    k_edge<<<(E + EB - 1) / EB, 256, SMEM_E>>>(coords, a, src, dst,
                                               We1, be1, We2, be2, Wc, Wa, E);
    k_scan<<<1, 1024>>>(N);
    k_fill<<<(E + 255) / 256, 256>>>(dst, E);
    k_agg<<<(N + 7) / 8, 256>>>(coords, Wv, out_coords, N);
    k_node<<<(N + NB - 1) / NB, 256, SMEM_N>>>(h, res, y, Wo, Wn1, bn1, Wn2, bn2,
                                               Wf1, bf1, Wf2, bf2, out_h2, out_res2, N);
}

// round 8
// speedup vs baseline: 1.1314x; 1.0242x over previous
#include <cuda_runtime.h>
#include <math.h>

#define NMAX 25000
#define EMAX 400000
#define HID 128
#define INNER 160
#define EB 64      // edges per block
#define NB 32      // nodes per block (k_node)

// ---------------- scratch ----------------
__device__ float g_m[(size_t)EMAX * 160];      // per-edge message m
__device__ float g_logits[(size_t)EMAX * 8];
__device__ float g_msgx[(size_t)EMAX * 3];
__device__ float g_hagg[(size_t)NMAX * 128];
__device__ float g_P[(size_t)NMAX * 320];      // precomputed h@We1 (src half | dst half)
__device__ int g_deg[NMAX];
__device__ int g_cursor[NMAX];
__device__ int g_start[NMAX + 1];
__device__ int g_eid[EMAX];

// ---------------- helpers ----------------
typedef unsigned long long ull;
__device__ __forceinline__ ull pk2(float a, float b) {
    ull r;
    asm("mov.b64 %0, {%1, %2};" : "=l"(r) : "r"(__float_as_uint(a)), "r"(__float_as_uint(b)));
    return r;
}
__device__ __forceinline__ void upk2(ull v, float &a, float &b) {
    unsigned int lo, hi;
    asm("mov.b64 {%0, %1}, %2;" : "=r"(lo), "=r"(hi) : "l"(v));
    a = __uint_as_float(lo); b = __uint_as_float(hi);
}
__device__ __forceinline__ void ffma2(ull &d, ull a, ull b) {
    asm("fma.rn.f32x2 %0, %1, %2, %3;" : "=l"(d) : "l"(a), "l"(b), "l"(d));
}
__device__ __forceinline__ float siluf(float x) { return x / (1.0f + __expf(-x)); }
__device__ __forceinline__ float getc(const float4& v, int kk) {
    return kk == 0 ? v.x : kk == 1 ? v.y : kk == 2 ? v.z : v.w;
}

// ---------------- CSR build ----------------
__global__ void k_zero(int n) {
    int i = blockIdx.x * blockDim.x + threadIdx.x;
    if (i < n) { g_deg[i] = 0; g_cursor[i] = 0; }
}
__global__ void k_deg(const int* __restrict__ dst, int E) {
    int e = blockIdx.x * blockDim.x + threadIdx.x;
    if (e < E) atomicAdd(&g_deg[dst[e]], 1);
}
__global__ void k_scan(int n) {
    __shared__ int sh[1024];
    int carry = 0;
    for (int base = 0; base < n; base += 1024) {
        int i = base + threadIdx.x;
        int x = (i < n) ? g_deg[i] : 0;
        sh[threadIdx.x] = x;
        __syncthreads();
        for (int off = 1; off < 1024; off <<= 1) {
            int v = (threadIdx.x >= off) ? sh[threadIdx.x - off] : 0;
            __syncthreads();
            sh[threadIdx.x] += v;
            __syncthreads();
        }
        if (i < n) g_start[i] = carry + sh[threadIdx.x] - x;
        carry += sh[1023];
        __syncthreads();
    }
    if (threadIdx.x == 0) g_start[n] = carry;
}
__global__ void k_fill(const int* __restrict__ dst, int E) {
    int e = blockIdx.x * blockDim.x + threadIdx.x;
    if (e < E) {
        int d = dst[e];
        int p = atomicAdd(&g_cursor[d], 1);
        g_eid[g_start[d] + p] = e;
    }
}

// ---------------- precompute P[n] = [h@We1[0:128] | h@We1[128:256]] ----------------
__global__ void __launch_bounds__(256) k_pre(const float* __restrict__ h,
                                             const float* __restrict__ We1, int N)
{
    __shared__ float sH[32][132];
    const int nb = blockIdx.x * 32;
    const int tid = threadIdx.x;
    for (int idx = tid; idx < 32 * 128; idx += 256) {
        int r = idx >> 7, c = idx & 127;
        int n = min(nb + r, N - 1);
        sH[r][c] = h[(size_t)n * 128 + c];
    }
    __syncthreads();

    const int ecg = tid >> 5, jcg = tid & 31;
    ull accA[4][3], accB[4][3];
    #pragma unroll
    for (int i = 0; i < 4; i++)
        #pragma unroll
        for (int p = 0; p < 3; p++) { accA[i][p] = 0; accB[i][p] = 0; }

    for (int k = 0; k < 128; k++) {
        ull fa[4];
        #pragma unroll
        for (int i = 0; i < 4; i++) { float c = sH[ecg + 8 * i][k]; fa[i] = pk2(c, c); }
        const float* w1 = We1 + (size_t)k * INNER;
        const float* w2 = We1 + (size_t)(128 + k) * INNER;
        float4 wa = __ldg((const float4*)(w1 + 4 * jcg));
        float4 wb = __ldg((const float4*)(w2 + 4 * jcg));
        ull A0 = pk2(wa.x, wa.y), A1 = pk2(wa.z, wa.w);
        ull B0 = pk2(wb.x, wb.y), B1 = pk2(wb.z, wb.w);
        ull A2 = 0, B2 = 0;
        if (jcg < 16) {
            float2 ta = __ldg((const float2*)(w1 + 128 + 2 * jcg));
            float2 tb = __ldg((const float2*)(w2 + 128 + 2 * jcg));
            A2 = pk2(ta.x, ta.y); B2 = pk2(tb.x, tb.y);
        }
        #pragma unroll
        for (int i = 0; i < 4; i++) {
            ffma2(accA[i][0], fa[i], A0); ffma2(accA[i][1], fa[i], A1);
            ffma2(accB[i][0], fa[i], B0); ffma2(accB[i][1], fa[i], B1);
            if (jcg < 16) { ffma2(accA[i][2], fa[i], A2); ffma2(accB[i][2], fa[i], B2); }
        }
    }
    #pragma unroll
    for (int i = 0; i < 4; i++) {
        int n = nb + ecg + 8 * i;
        if (n < N) {
            float* out = g_P + (size_t)n * 320;
            float x0, x1, x2, x3;
            upk2(accA[i][0], x0, x1); upk2(accA[i][1], x2, x3);
            *(float4*)(out + 4 * jcg) = make_float4(x0, x1, x2, x3);
            upk2(accB[i][0], x0, x1); upk2(accB[i][1], x2, x3);
            *(float4*)(out + 160 + 4 * jcg) = make_float4(x0, x1, x2, x3);
            if (jcg < 16) {
                upk2(accA[i][2], x0, x1);
                *(float2*)(out + 128 + 2 * jcg) = make_float2(x0, x1);
                upk2(accB[i][2], x0, x1);
                *(float2*)(out + 288 + 2 * jcg) = make_float2(x0, x1);
            }
        }
    }
}

// chunk loader: 16 rows x 160 cols of W into smem buffer
__device__ __forceinline__ void load_w_chunk(float* dstbuf, const float* __restrict__ W,
                                             int k0, int tid) {
    #pragma unroll
    for (int i = 0; i < 3; i++) {
        int idx = tid + 256 * i;
        if (i < 2 || idx < 640) {
            int r = idx / 40, c4 = idx % 40;
            *(float4*)(dstbuf + r * 160 + 4 * c4) =
                __ldg((const float4*)(W + (size_t)(k0 + r) * 160 + 4 * c4));
        }
    }
}

// ---------------- fused edge kernel (smem-staged weights) ----------------
__global__ void __launch_bounds__(256, 3) k_edge(
    const float* __restrict__ coords, const float* __restrict__ a,
    const int* __restrict__ src, const int* __restrict__ dst,
    const float* __restrict__ We1, const float* __restrict__ be1,
    const float* __restrict__ We2, const float* __restrict__ be2,
    const float* __restrict__ Wc, const float* __restrict__ Wa,
    int E)
{
    extern __shared__ float sm_e[];
    float* sm1  = sm_e;               // [64][164]
    float* sWA  = sm1 + 64 * 164;     // weight buffer A: 17x160 (2720)
    float* sWB  = sWA + 2720;         // weight buffer B: 16x160 (2560, padded to 2720)
    float* sA   = sWB + 2720;         // [64][16]
    float* sRad = sA + 64 * 16;       // [64]
    float* sDx  = sRad + 64;          // [64]
    float* sDy  = sDx + 64;
    float* sDz  = sDy + 64;
    int*   sSrc = (int*)(sDz + 64);   // [64]
    int*   sDst = sSrc + 64;          // [64]

    const int tid = threadIdx.x;
    const int eg = blockIdx.x * EB;
    const int warp = tid >> 5, lane = tid & 31;

    // ---- stage 0: gather edge extras + load We1 tail into A + We2 chunk0 into B ----
    for (int e = warp; e < EB; e += 8) {
        int ed = eg + e; if (ed > E - 1) ed = E - 1;
        if (lane < 16) sA[e * 16 + lane] = __ldg(a + (size_t)ed * 16 + lane);
        if (lane == 0) {
            int si = src[ed], di = dst[ed];
            sSrc[e] = si; sDst[e] = di;
            float dx = coords[si * 3 + 0] - coords[di * 3 + 0];
            float dy = coords[si * 3 + 1] - coords[di * 3 + 1];
            float dz = coords[si * 3 + 2] - coords[di * 3 + 2];
            sRad[e] = dx * dx + dy * dy + dz * dz;
            sDx[e] = dx; sDy[e] = dy; sDz[e] = dz;
        }
    }
    // We1 rows 256..272 (17 x 160 = 680 float4)
    #pragma unroll
    for (int i = 0; i < 3; i++) {
        int idx = tid + 256 * i;
        if (i < 2 || idx < 680) {
            int r = idx / 40, c4 = idx % 40;
            *(float4*)(sWA + r * 160 + 4 * c4) =
                __ldg((const float4*)(We1 + (size_t)(256 + r) * 160 + 4 * c4));
        }
    }
    load_w_chunk(sWB, We2, 0, tid);
    __syncthreads();

    const int ecg = tid >> 4;   // rows ecg + 16*i
    const int jcg = tid & 15;   // cols 4jcg..+3, 64+4jcg..+3, 128+2jcg,+1

    // ---- GEMM1-lite: m1 = silu(P1[src] + P2[dst] + [rad,a]@We1[256:273] + be1) ----
    {
        ull acc[4][5];
        #pragma unroll
        for (int i = 0; i < 4; i++) {
            int r = ecg + 16 * i;
            const float* Ps = g_P + (size_t)sSrc[r] * 320;
            const float* Pd = g_P + (size_t)sDst[r] * 320 + 160;
            float4 a0 = __ldg((const float4*)(Ps + 4 * jcg));
            float4 b0 = __ldg((const float4*)(Pd + 4 * jcg));
            acc[i][0] = pk2(a0.x + b0.x, a0.y + b0.y);
            acc[i][1] = pk2(a0.z + b0.z, a0.w + b0.w);
            float4 a1 = __ldg((const float4*)(Ps + 64 + 4 * jcg));
            float4 b1 = __ldg((const float4*)(Pd + 64 + 4 * jcg));
            acc[i][2] = pk2(a1.x + b1.x, a1.y + b1.y);
            acc[i][3] = pk2(a1.z + b1.z, a1.w + b1.w);
            float2 a2 = __ldg((const float2*)(Ps + 128 + 2 * jcg));
            float2 b2 = __ldg((const float2*)(Pd + 128 + 2 * jcg));
            acc[i][4] = pk2(a2.x + b2.x, a2.y + b2.y);
        }
        // k = 0..16: radial + edge attrs, weights from smem buffer A
        #pragma unroll 4
        for (int k = 0; k < 17; k++) {
            const float* wr = sWA + k * 160;
            float4 w0 = *(const float4*)(wr + 4 * jcg);
            float4 w1 = *(const float4*)(wr + 64 + 4 * jcg);
            float2 w2 = *(const float2*)(wr + 128 + 2 * jcg);
            ull W00 = pk2(w0.x, w0.y), W01 = pk2(w0.z, w0.w);
            ull W10 = pk2(w1.x, w1.y), W11 = pk2(w1.z, w1.w);
            ull W2  = pk2(w2.x, w2.y);
            #pragma unroll
            for (int i = 0; i < 4; i++) {
                int r = ecg + 16 * i;
                float c = (k == 0) ? sRad[r] : sA[r * 16 + (k - 1)];
                ull fa = pk2(c, c);
                ffma2(acc[i][0], fa, W00); ffma2(acc[i][1], fa, W01);
                ffma2(acc[i][2], fa, W10); ffma2(acc[i][3], fa, W11);
                ffma2(acc[i][4], fa, W2);
            }
        }
        #pragma unroll
        for (int i = 0; i < 4; i++) {
            float* orow = sm1 + (ecg + 16 * i) * 164;
            float lo, hi;
            int c = 4 * jcg;
            upk2(acc[i][0], lo, hi);
            orow[c]   = siluf(lo + __ldg(be1 + c));     orow[c+1] = siluf(hi + __ldg(be1 + c + 1));
            upk2(acc[i][1], lo, hi);
            orow[c+2] = siluf(lo + __ldg(be1 + c + 2)); orow[c+3] = siluf(hi + __ldg(be1 + c + 3));
            c = 64 + 4 * jcg;
            upk2(acc[i][2], lo, hi);
            orow[c]   = siluf(lo + __ldg(be1 + c));     orow[c+1] = siluf(hi + __ldg(be1 + c + 1));
            upk2(acc[i][3], lo, hi);
            orow[c+2] = siluf(lo + __ldg(be1 + c + 2)); orow[c+3] = siluf(hi + __ldg(be1 + c + 3));
            c = 128 + 2 * jcg;
            upk2(acc[i][4], lo, hi);
            orow[c]   = siluf(lo + __ldg(be1 + c));     orow[c+1] = siluf(hi + __ldg(be1 + c + 1));
        }
    }
    __syncthreads();

    // ---- GEMM2 (in-place): m = silu(m1 @ We2 + be2), weights double-buffered in smem ----
    {
        ull acc[4][5];
        #pragma unroll
        for (int i = 0; i < 4; i++) { acc[i][0]=0; acc[i][1]=0; acc[i][2]=0; acc[i][3]=0; acc[i][4]=0; }
        const float* f0 = sm1 + (ecg +  0) * 164;
        const float* f1 = sm1 + (ecg + 16) * 164;
        const float* f2p = sm1 + (ecg + 32) * 164;
        const float* f3p = sm1 + (ecg + 48) * 164;

        for (int ch = 0; ch < 10; ch++) {
            const float* wbuf = (ch & 1) ? sWA : sWB;
            if (ch < 9) load_w_chunk((ch & 1) ? sWB : sWA, We2, 16 * (ch + 1), tid);
            const int kb = 16 * ch;
            #pragma unroll 2
            for (int k2 = 0; k2 < 16; k2 += 2) {
                float2 a0 = *(const float2*)(f0 + kb + k2);
                float2 a1 = *(const float2*)(f1 + kb + k2);
                float2 a2 = *(const float2*)(f2p + kb + k2);
                float2 a3 = *(const float2*)(f3p + kb + k2);
                #pragma unroll
                for (int kk = 0; kk < 2; kk++) {
                    ull fa[4];
                    float c0 = kk ? a0.y : a0.x, c1 = kk ? a1.y : a1.x;
                    float c2 = kk ? a2.y : a2.x, c3 = kk ? a3.y : a3.x;
                    fa[0] = pk2(c0, c0); fa[1] = pk2(c1, c1);
                    fa[2] = pk2(c2, c2); fa[3] = pk2(c3, c3);
                    const float* wr = wbuf + (k2 + kk) * 160;
                    float4 w0 = *(const float4*)(wr + 4 * jcg);
                    float4 w1 = *(const float4*)(wr + 64 + 4 * jcg);
                    float2 w2 = *(const float2*)(wr + 128 + 2 * jcg);
                    ull W00 = pk2(w0.x, w0.y), W01 = pk2(w0.z, w0.w);
                    ull W10 = pk2(w1.x, w1.y), W11 = pk2(w1.z, w1.w);
                    ull W2  = pk2(w2.x, w2.y);
                    #pragma unroll
                    for (int i = 0; i < 4; i++) {
                        ffma2(acc[i][0], fa[i], W00); ffma2(acc[i][1], fa[i], W01);
                        ffma2(acc[i][2], fa[i], W10); ffma2(acc[i][3], fa[i], W11);
                        ffma2(acc[i][4], fa[i], W2);
                    }
                }
            }
            __syncthreads();   // compute of ch done by all; load of ch+1 visible
        }
        // in-place overwrite is safe: last sync guarantees all activation reads done
        #pragma unroll
        for (int i = 0; i < 4; i++) {
            float* orow = sm1 + (ecg + 16 * i) * 164;
            float lo, hi;
            int c = 4 * jcg;
            upk2(acc[i][0], lo, hi);
            orow[c]   = siluf(lo + __ldg(be2 + c));     orow[c+1] = siluf(hi + __ldg(be2 + c + 1));
            upk2(acc[i][1], lo, hi);
            orow[c+2] = siluf(lo + __ldg(be2 + c + 2)); orow[c+3] = siluf(hi + __ldg(be2 + c + 3));
            c = 64 + 4 * jcg;
            upk2(acc[i][2], lo, hi);
            orow[c]   = siluf(lo + __ldg(be2 + c));     orow[c+1] = siluf(hi + __ldg(be2 + c + 1));
            upk2(acc[i][3], lo, hi);
            orow[c+2] = siluf(lo + __ldg(be2 + c + 2)); orow[c+3] = siluf(hi + __ldg(be2 + c + 3));
            c = 128 + 2 * jcg;
            upk2(acc[i][4], lo, hi);
            orow[c]   = siluf(lo + __ldg(be2 + c));     orow[c+1] = siluf(hi + __ldg(be2 + c + 1));
        }
    }
    __syncthreads();

    // ---- logits = m @ Wa ----
    #pragma unroll
    for (int pass = 0; pass < 2; pass++) {
        int e = (tid >> 3) + 32 * pass;
        int hh = tid & 7;
        const float* mr = sm1 + e * 164;
        float accl = 0.f;
        #pragma unroll 8
        for (int k = 0; k < INNER; k++) accl += mr[k] * __ldg(Wa + k * 8 + hh);
        int ed = eg + e;
        if (ed < E) g_logits[(size_t)ed * 8 + hh] = accl;
    }

    // ---- coordinate messages ----
    if (tid < EB) {
        int e = tid;
        const float* mr = sm1 + e * 164;
        float c = 0.f;
        #pragma unroll 8
        for (int k = 0; k < INNER; k++) c += mr[k] * __ldg(Wc + k);
        float s = c / (sqrtf(sRad[e] + 1e-5f) + 1.0f);
        int ed = eg + e;
        if (ed < E) {
            g_msgx[(size_t)ed * 3 + 0] = sDx[e] * s;
            g_msgx[(size_t)ed * 3 + 1] = sDy[e] * s;
            g_msgx[(size_t)ed * 3 + 2] = sDz[e] * s;
        }
    }

    // ---- write m to global ----
    for (int idx = tid; idx < 64 * 40; idx += 256) {
        int r = idx / 40, c4 = idx % 40;
        int ed = eg + r;
        if (ed < E)
            *(float4*)(g_m + (size_t)ed * 160 + 4 * c4) = *(const float4*)(sm1 + r * 164 + 4 * c4);
    }
}

// ---------------- warp-per-node aggregation: single-pass m reads ----------------
__global__ void __launch_bounds__(256) k_agg(const float* __restrict__ coords,
                                             const float* __restrict__ Wv,
                                             float* __restrict__ out_coords, int N)
{
    __shared__ float sS[8][8][164];   // node, head, k
    __shared__ float sWw[8][4][8];    // node, edge-slot, head
    __shared__ int sEd[8][4];
    const int tid = threadIdx.x;
    const int warp = tid >> 5, lane = tid & 31;
    const int nb = blockIdx.x * 8;
    const int n = nb + warp;
    const int le = lane >> 3, lh = lane & 7;

    if (n < N) {
        const int s0 = g_start[n];
        const int deg = g_start[n + 1] - s0;

        // --- softmax stats (per head lh, strided over edges by le) ---
        float mx = -3.0e38f;
        for (int c = le; c < deg; c += 4) {
            int e = g_eid[s0 + c];
            mx = fmaxf(mx, __ldg(g_logits + (size_t)e * 8 + lh));
        }
        mx = fmaxf(mx, __shfl_xor_sync(~0u, mx, 8));
        mx = fmaxf(mx, __shfl_xor_sync(~0u, mx, 16));
        float den = 0.f;
        for (int c = le; c < deg; c += 4) {
            int e = g_eid[s0 + c];
            den += __expf(__ldg(g_logits + (size_t)e * 8 + lh) - mx);
        }
        den += __shfl_xor_sync(~0u, den, 8);
        den += __shfl_xor_sync(~0u, den, 16);
        float rden = 1.f / den;

        // --- accumulate s[h][k]: lane owns k = lane + 32q; each m row read once ---
        float acc[8][5];
        #pragma unroll
        for (int hh = 0; hh < 8; hh++)
            #pragma unroll
            for (int q = 0; q < 5; q++) acc[hh][q] = 0.f;

        for (int c = 0; c < deg; c += 4) {
            int len = min(4, deg - c);
            if (le < len) {
                int e = g_eid[s0 + c + le];
                if (lh == 0) sEd[warp][le] = e;
                sWw[warp][le][lh] = __expf(__ldg(g_logits + (size_t)e * 8 + lh) - mx) * rden;
            }
            __syncwarp();
            for (int ii = 0; ii < len; ii++) {
                int e = sEd[warp][ii];
                float4 wlo = *(const float4*)&sWw[warp][ii][0];
                float4 whi = *(const float4*)&sWw[warp][ii][4];
                float v[5];
                #pragma unroll
                for (int q = 0; q < 5; q++)
                    v[q] = __ldg(g_m + (size_t)e * 160 + lane + 32 * q);
                #pragma unroll
                for (int q = 0; q < 5; q++) {
                    acc[0][q] += v[q] * wlo.x; acc[1][q] += v[q] * wlo.y;
                    acc[2][q] += v[q] * wlo.z; acc[3][q] += v[q] * wlo.w;
                    acc[4][q] += v[q] * whi.x; acc[5][q] += v[q] * whi.y;
                    acc[6][q] += v[q] * whi.z; acc[7][q] += v[q] * whi.w;
                }
            }
            __syncwarp();
        }
        #pragma unroll
        for (int hh = 0; hh < 8; hh++)
            #pragma unroll
            for (int q = 0; q < 5; q++)
                sS[warp][hh][lane + 32 * q] = acc[hh][q];

        // --- coordinate scatter-sum (lanes 0..2) ---
        if (lane < 3) {
            float cacc = 0.f;
            for (int i = 0; i < deg; i++)
                cacc += __ldg(g_msgx + (size_t)g_eid[s0 + i] * 3 + lane);
            out_coords[n * 3 + lane] = coords[n * 3 + lane] + cacc;
        }
    }
    __syncthreads();

    // --- batched Wv epilogue: h_agg[n][j] = sum_k sS[n][j>>4][k] * Wv[k][j] ---
    {
        const int j = tid & 127, grp = tid >> 7;     // grp 0..1, 4 nodes each
        const int head = j >> 4;
        #pragma unroll
        for (int r = 0; r < 4; r++) {
            int wn = grp * 4 + r;
            int n2 = nb + wn;
            if (n2 < N) {
                const float* sr = sS[wn][head];
                float hv = 0.f;
                #pragma unroll 8
                for (int k = 0; k < INNER; k++) hv += sr[k] * __ldg(Wv + k * 128 + j);
                g_hagg[(size_t)n2 * 128 + j] = hv;
            }
        }
    }
}

// ---------------- batched node GEMM helpers ----------------
template<int K, int NP, int C>
__device__ __forceinline__ void gemm_n(const float* __restrict__ sIn, int is,
                                       const float* __restrict__ W,
                                       ull (&acc)[4][NP][2]) {
    const int tid = threadIdx.x;
    const int ecg = tid >> 5, jcg = tid & 31;
    #pragma unroll
    for (int i = 0; i < 4; i++)
        #pragma unroll
        for (int p = 0; p < NP; p++) { acc[i][p][0] = 0; acc[i][p][1] = 0; }
    for (int k4 = 0; k4 < K; k4 += 4) {
        float4 av[4];
        #pragma unroll
        for (int i = 0; i < 4; i++) av[i] = *(const float4*)(sIn + (ecg + 8 * i) * is + k4);
        #pragma unroll
        for (int kk = 0; kk < 4; kk++) {
            ull fa[4];
            #pragma unroll
            for (int i = 0; i < 4; i++) { float c = getc(av[i], kk); fa[i] = pk2(c, c); }
            const float* wr = W + (k4 + kk) * C + 4 * jcg;
            #pragma unroll
            for (int p = 0; p < NP; p++) {
                if ((C % 128 == 0) || (128 * p + 4 * jcg < C)) {
                    float4 wv = __ldg((const float4*)(wr + 128 * p));
                    ull w0 = pk2(wv.x, wv.y), w1 = pk2(wv.z, wv.w);
                    #pragma unroll
                    for (int i = 0; i < 4; i++) { ffma2(acc[i][p][0], fa[i], w0); ffma2(acc[i][p][1], fa[i], w1); }
                }
            }
        }
    }
}

template<int NP, int C>
__device__ __forceinline__ void store_acc(ull (&acc)[4][NP][2], float* sOut, int os,
                                          const float* bias, bool dosilu) {
    const int tid = threadIdx.x, ecg = tid >> 5, jcg = tid & 31;
    #pragma unroll
    for (int i = 0; i < 4; i++) {
        int r = ecg + 8 * i;
        #pragma unroll
        for (int p = 0; p < NP; p++) {
            int c0 = 128 * p + 4 * jcg;
            if ((C % 128 == 0) || (c0 < C)) {
                float v0, v1, v2, v3;
                upk2(acc[i][p][0], v0, v1); upk2(acc[i][p][1], v2, v3);
                if (bias) {
                    v0 += __ldg(bias + c0); v1 += __ldg(bias + c0 + 1);
                    v2 += __ldg(bias + c0 + 2); v3 += __ldg(bias + c0 + 3);
                }
                if (dosilu) { v0 = siluf(v0); v1 = siluf(v1); v2 = siluf(v2); v3 = siluf(v3); }
                *(float4*)(sOut + r * os + c0) = make_float4(v0, v1, v2, v3);
            }
        }
    }
}

__device__ __forceinline__ void film_store(ull (&acc)[4][2][2], float* sScale, float* sShift,
                                           const float* bias) {
    const int tid = threadIdx.x, ecg = tid >> 5, jcg = tid & 31;
    #pragma unroll
    for (int i = 0; i < 4; i++) {
        int r = ecg + 8 * i;
        int c0 = 4 * jcg;
        float v0, v1, v2, v3;
        upk2(acc[i][0][0], v0, v1); upk2(acc[i][0][1], v2, v3);
        v0 += __ldg(bias + c0); v1 += __ldg(bias + c0 + 1);
        v2 += __ldg(bias + c0 + 2); v3 += __ldg(bias + c0 + 3);
        *(float4*)(sScale + r * 132 + c0) = make_float4(v0, v1, v2, v3);
        upk2(acc[i][1][0], v0, v1); upk2(acc[i][1][1], v2, v3);
        v0 += __ldg(bias + 128 + c0); v1 += __ldg(bias + 128 + c0 + 1);
        v2 += __ldg(bias + 128 + c0 + 2); v3 += __ldg(bias + 128 + c0 + 3);
        *(float4*)(sShift + r * 164 + c0) = make_float4(v0, v1, v2, v3);
    }
}

__device__ __forceinline__ void ln_stats(const float* sX, float* sMu, float* sRs) {
    int w = threadIdx.x >> 5, lane = threadIdx.x & 31;
    #pragma unroll
    for (int rr = 0; rr < 4; rr++) {
        int r = w * 4 + rr;
        float4 v = *(const float4*)(sX + r * 132 + 4 * lane);
        float s = v.x + v.y + v.z + v.w;
        float q = v.x * v.x + v.y * v.y + v.z * v.z + v.w * v.w;
        #pragma unroll
        for (int o = 16; o; o >>= 1) {
            s += __shfl_xor_sync(~0u, s, o);
            q += __shfl_xor_sync(~0u, q, o);
        }
        if (lane == 0) {
            float mu = s * (1.f / 128.f);
            float var = q * (1.f / 128.f) - mu * mu;
            sMu[r] = mu; sRs[r] = rsqrtf(var + 1e-5f);
        }
    }
}

// ---------------- batched node kernel (32 nodes/block) ----------------
__global__ void __launch_bounds__(256, 2) k_node(
    const float* __restrict__ h, const float* __restrict__ res, const float* __restrict__ y,
    const float* __restrict__ Wo,
    const float* __restrict__ Wn1, const float* __restrict__ bn1,
    const float* __restrict__ Wn2, const float* __restrict__ bn2,
    const float* __restrict__ Wf1, const float* __restrict__ bf1,
    const float* __restrict__ Wf2, const float* __restrict__ bf2,
    float* __restrict__ out_h2, float* __restrict__ out_res2, int N)
{
    extern __shared__ float sm_n[];
    float* sA  = sm_n;                 // [32][164]
    float* sB  = sA + 32 * 164;        // [32][132]
    float* sC  = sB + 32 * 132;        // [32][132]
    float* sY  = sC + 32 * 132;        // [32][68]
    float* sMu = sY + 32 * 68;         // [32]
    float* sRs = sMu + 32;             // [32]

    const int nb = blockIdx.x * NB;
    const int tid = threadIdx.x;

    for (int idx = tid; idx < 32 * 128; idx += 256) {
        int r = idx >> 7, c = idx & 127;
        int n = min(nb + r, N - 1);
        sB[r * 132 + c] = g_hagg[(size_t)n * 128 + c];
    }
    for (int idx = tid; idx < 32 * 64; idx += 256) {
        int r = idx >> 6, c = idx & 63;
        int n = min(nb + r, N - 1);
        sY[r * 68 + c] = y[(size_t)n * 64 + c];
    }
    __syncthreads();

    {
        ull acc[4][1][2];
        gemm_n<128, 1, 128>(sB, 132, Wo, acc);
        store_acc<1, 128>(acc, sC, 132, nullptr, false);
    }
    __syncthreads();

    float f2r[16];
    #pragma unroll
    for (int t = 0; t < 16; t++) {
        int idx = tid + 256 * t;
        int r = idx >> 7, c = idx & 127;
        int n = min(nb + r, N - 1);
        float f2v = sC[r * 132 + c];
        f2r[t] = f2v;
        sB[r * 132 + c] = h[(size_t)n * 128 + c] + f2v;
    }
    __syncthreads();
    ln_stats(sB, sMu, sRs);
    __syncthreads();

    {
        ull acc[4][2][2];
        gemm_n<64, 2, 256>(sY, 68, Wf1, acc);
        film_store(acc, sC, sA, bf1);
    }
    __syncthreads();

    #pragma unroll
    for (int t = 0; t < 16; t++) {
        int idx = tid + 256 * t;
        int r = idx >> 7, c = idx & 127;
        float x = sB[r * 132 + c];
        float xn = (x - sMu[r]) * sRs[r];
        sB[r * 132 + c] = xn * (1.f + sC[r * 132 + c]) + sA[r * 164 + c];
    }
    __syncthreads();

    {
        ull acc[4][2][2];
        gemm_n<128, 2, 160>(sB, 132, Wn1, acc);
        store_acc<2, 160>(acc, sA, 164, bn1, true);
    }
    __syncthreads();

    {
        ull acc[4][1][2];
        gemm_n<160, 1, 128>(sA, 164, Wn2, acc);
        store_acc<1, 128>(acc, sC, 132, bn2, false);
    }
    __syncthreads();

    #pragma unroll
    for (int t = 0; t < 16; t++) {
        int idx = tid + 256 * t;
        int r = idx >> 7, c = idx & 127;
        float f3 = sC[r * 132 + c];
        int n = nb + r;
        if (n < N) out_res2[(size_t)n * 128 + c] = res[(size_t)n * 128 + c] + f2r[t] + f3;
        sB[r * 132 + c] += f3;
    }
    __syncthreads();
    ln_stats(sB, sMu, sRs);
    __syncthreads();

    {
        ull acc[4][2][2];
        gemm_n<64, 2, 256>(sY, 68, Wf2, acc);
        film_store(acc, sC, sA, bf2);
    }
    __syncthreads();

    #pragma unroll
    for (int t = 0; t < 16; t++) {
        int idx = tid + 256 * t;
        int r = idx >> 7, c = idx & 127;
        int n = nb + r;
        if (n < N) {
            float xn = (sB[r * 132 + c] - sMu[r]) * sRs[r];
            out_h2[(size_t)n * 128 + c] = xn * (1.f + sC[r * 132 + c]) + sA[r * 164 + c];
        }
    }
}

// ---------------- launch ----------------
extern "C" void kernel_launch(void* const* d_in, const int* in_sizes, int n_in,
                              void* d_out, int out_size) {
    const float* h      = (const float*)d_in[0];
    const float* coords = (const float*)d_in[1];
    const float* a      = (const float*)d_in[2];
    const float* y      = (const float*)d_in[3];
    const float* res    = (const float*)d_in[4];
    const int*   src    = (const int*)d_in[5];
    const int*   dst    = (const int*)d_in[6];
    const float* We1 = (const float*)d_in[7];
    const float* be1 = (const float*)d_in[8];
    const float* We2 = (const float*)d_in[9];
    const float* be2 = (const float*)d_in[10];
    const float* Wc  = (const float*)d_in[11];
    const float* Wv  = (const float*)d_in[12];
    const float* Wa  = (const float*)d_in[13];
    const float* Wo  = (const float*)d_in[14];
    const float* Wn1 = (const float*)d_in[15];
    const float* bn1 = (const float*)d_in[16];
    const float* Wn2 = (const float*)d_in[17];
    const float* bn2 = (const float*)d_in[18];
    const float* Wf1 = (const float*)d_in[19];
    const float* bf1 = (const float*)d_in[20];
    const float* Wf2 = (const float*)d_in[21];
    const float* bf2 = (const float*)d_in[22];

    const int N = in_sizes[0] / HID;
    const int E = in_sizes[5];

    float* out = (float*)d_out;
    float* out_h2 = out;
    float* out_coords = out + (size_t)N * HID;
    float* out_res2 = out + (size_t)N * HID + (size_t)N * 3;

    const int SMEM_E = (64 * 164 + 2 * 2720 + 64 * 16 + 64 * 6) * (int)sizeof(float);
    const int SMEM_N = (32 * 164 + 32 * 132 * 2 + 32 * 68 + 64) * (int)sizeof(float);
    cudaFuncSetAttribute(k_edge, cudaFuncAttributeMaxDynamicSharedMemorySize, SMEM_E);
    cudaFuncSetAttribute(k_node, cudaFuncAttributeMaxDynamicSharedMemorySize, SMEM_N);

    k_zero<<<(N + 255) / 256, 256>>>(N);
    k_deg<<<(E + 255) / 256, 256>>>(dst, E);
    k_pre<<<(N + 31) / 32, 256>>>(h, We1, N);
    // k_edge 4th: the ncu window captures launch #4
    k_edge<<<(E + EB - 1) / EB, 256, SMEM_E>>>(coords, a, src, dst,
                                               We1, be1, We2, be2, Wc, Wa, E);
    k_scan<<<1, 1024>>>(N);
    k_fill<<<(E + 255) / 256, 256>>>(dst, E);
    k_agg<<<(N + 7) / 8, 256>>>(coords, Wv, out_coords, N);
    k_node<<<(N + NB - 1) / NB, 256, SMEM_N>>>(h, res, y, Wo, Wn1, bn1, Wn2, bn2,
                                               Wf1, bf1, Wf2, bf2, out_h2, out_res2, N);
}

// round 9
// speedup vs baseline: 1.1530x; 1.0191x over previous
#include <cuda_runtime.h>
#include <math.h>

#define NMAX 25000
#define EMAX 400000
#define HID 128
#define INNER 160
#define EB 64      // edges per block
#define NB 32      // nodes per block (k_node)

// ---------------- scratch ----------------
__device__ float g_m[(size_t)EMAX * 160];      // per-edge message m
__device__ float g_logits[(size_t)EMAX * 8];   // logits, later overwritten with softmax weights
__device__ float g_msgx[(size_t)EMAX * 3];
__device__ float g_hagg[(size_t)NMAX * 128];
__device__ float g_P[(size_t)NMAX * 320];      // precomputed h@We1 (src half | dst half)
__device__ int g_deg[NMAX];
__device__ int g_cursor[NMAX];
__device__ int g_start[NMAX + 1];
__device__ int g_eid[EMAX];

// ---------------- helpers ----------------
typedef unsigned long long ull;
__device__ __forceinline__ ull pk2(float a, float b) {
    ull r;
    asm("mov.b64 %0, {%1, %2};" : "=l"(r) : "r"(__float_as_uint(a)), "r"(__float_as_uint(b)));
    return r;
}
__device__ __forceinline__ void upk2(ull v, float &a, float &b) {
    unsigned int lo, hi;
    asm("mov.b64 {%0, %1}, %2;" : "=r"(lo), "=r"(hi) : "l"(v));
    a = __uint_as_float(lo); b = __uint_as_float(hi);
}
__device__ __forceinline__ void ffma2(ull &d, ull a, ull b) {
    asm("fma.rn.f32x2 %0, %1, %2, %3;" : "=l"(d) : "l"(a), "l"(b), "l"(d));
}
__device__ __forceinline__ float siluf(float x) { return x / (1.0f + __expf(-x)); }
__device__ __forceinline__ float getc(const float4& v, int kk) {
    return kk == 0 ? v.x : kk == 1 ? v.y : kk == 2 ? v.z : v.w;
}

// ---------------- CSR build ----------------
__global__ void k_zero(int n) {
    int i = blockIdx.x * blockDim.x + threadIdx.x;
    if (i < n) { g_deg[i] = 0; g_cursor[i] = 0; }
}
__global__ void k_deg(const int* __restrict__ dst, int E) {
    int e = blockIdx.x * blockDim.x + threadIdx.x;
    if (e < E) atomicAdd(&g_deg[dst[e]], 1);
}
__global__ void k_scan(int n) {
    __shared__ int sh[1024];
    int carry = 0;
    for (int base = 0; base < n; base += 1024) {
        int i = base + threadIdx.x;
        int x = (i < n) ? g_deg[i] : 0;
        sh[threadIdx.x] = x;
        __syncthreads();
        for (int off = 1; off < 1024; off <<= 1) {
            int v = (threadIdx.x >= off) ? sh[threadIdx.x - off] : 0;
            __syncthreads();
            sh[threadIdx.x] += v;
            __syncthreads();
        }
        if (i < n) g_start[i] = carry + sh[threadIdx.x] - x;
        carry += sh[1023];
        __syncthreads();
    }
    if (threadIdx.x == 0) g_start[n] = carry;
}
__global__ void k_fill(const int* __restrict__ dst, int E) {
    int e = blockIdx.x * blockDim.x + threadIdx.x;
    if (e < E) {
        int d = dst[e];
        int p = atomicAdd(&g_cursor[d], 1);
        g_eid[g_start[d] + p] = e;
    }
}

// ---------------- precompute P[n] = [h@We1[0:128] | h@We1[128:256]] ----------------
__global__ void __launch_bounds__(256) k_pre(const float* __restrict__ h,
                                             const float* __restrict__ We1, int N)
{
    __shared__ float sH[32][132];
    const int nb = blockIdx.x * 32;
    const int tid = threadIdx.x;
    for (int idx = tid; idx < 32 * 128; idx += 256) {
        int r = idx >> 7, c = idx & 127;
        int n = min(nb + r, N - 1);
        sH[r][c] = h[(size_t)n * 128 + c];
    }
    __syncthreads();

    const int ecg = tid >> 5, jcg = tid & 31;
    ull accA[4][3], accB[4][3];
    #pragma unroll
    for (int i = 0; i < 4; i++)
        #pragma unroll
        for (int p = 0; p < 3; p++) { accA[i][p] = 0; accB[i][p] = 0; }

    for (int k = 0; k < 128; k++) {
        ull fa[4];
        #pragma unroll
        for (int i = 0; i < 4; i++) { float c = sH[ecg + 8 * i][k]; fa[i] = pk2(c, c); }
        const float* w1 = We1 + (size_t)k * INNER;
        const float* w2 = We1 + (size_t)(128 + k) * INNER;
        ulonglong2 WA = __ldg((const ulonglong2*)(w1 + 4 * jcg));
        ulonglong2 WB = __ldg((const ulonglong2*)(w2 + 4 * jcg));
        ull A2 = 0, B2 = 0;
        if (jcg < 16) {
            A2 = __ldg((const ull*)(w1 + 128 + 2 * jcg));
            B2 = __ldg((const ull*)(w2 + 128 + 2 * jcg));
        }
        #pragma unroll
        for (int i = 0; i < 4; i++) {
            ffma2(accA[i][0], fa[i], WA.x); ffma2(accA[i][1], fa[i], WA.y);
            ffma2(accB[i][0], fa[i], WB.x); ffma2(accB[i][1], fa[i], WB.y);
            if (jcg < 16) { ffma2(accA[i][2], fa[i], A2); ffma2(accB[i][2], fa[i], B2); }
        }
    }
    #pragma unroll
    for (int i = 0; i < 4; i++) {
        int n = nb + ecg + 8 * i;
        if (n < N) {
            float* out = g_P + (size_t)n * 320;
            float x0, x1, x2, x3;
            upk2(accA[i][0], x0, x1); upk2(accA[i][1], x2, x3);
            *(float4*)(out + 4 * jcg) = make_float4(x0, x1, x2, x3);
            upk2(accB[i][0], x0, x1); upk2(accB[i][1], x2, x3);
            *(float4*)(out + 160 + 4 * jcg) = make_float4(x0, x1, x2, x3);
            if (jcg < 16) {
                upk2(accA[i][2], x0, x1);
                *(float2*)(out + 128 + 2 * jcg) = make_float2(x0, x1);
                upk2(accB[i][2], x0, x1);
                *(float2*)(out + 288 + 2 * jcg) = make_float2(x0, x1);
            }
        }
    }
}

// chunk loader: 16 rows x 160 cols of W into smem buffer
__device__ __forceinline__ void load_w_chunk(float* dstbuf, const float* __restrict__ W,
                                             int k0, int tid) {
    #pragma unroll
    for (int i = 0; i < 3; i++) {
        int idx = tid + 256 * i;
        if (i < 2 || idx < 640) {
            int r = idx / 40, c4 = idx % 40;
            *(float4*)(dstbuf + r * 160 + 4 * c4) =
                __ldg((const float4*)(W + (size_t)(k0 + r) * 160 + 4 * c4));
        }
    }
}

// ---------------- fused edge kernel (smem-staged weights, packed ull loads) ----------------
__global__ void __launch_bounds__(256, 3) k_edge(
    const float* __restrict__ coords, const float* __restrict__ a,
    const int* __restrict__ src, const int* __restrict__ dst,
    const float* __restrict__ We1, const float* __restrict__ be1,
    const float* __restrict__ We2, const float* __restrict__ be2,
    const float* __restrict__ Wc, const float* __restrict__ Wa,
    int E)
{
    extern __shared__ float sm_e[];
    float* sm1  = sm_e;               // [64][164]
    float* sWA  = sm1 + 64 * 164;     // weight buffer A: 17x160 (2720)
    float* sWB  = sWA + 2720;         // weight buffer B: 16x160
    float* sA   = sWB + 2720;         // [64][16]
    float* sRad = sA + 64 * 16;       // [64]
    float* sDx  = sRad + 64;          // [64]
    float* sDy  = sDx + 64;
    float* sDz  = sDy + 64;
    int*   sSrc = (int*)(sDz + 64);   // [64]
    int*   sDst = sSrc + 64;          // [64]

    const int tid = threadIdx.x;
    const int eg = blockIdx.x * EB;
    const int warp = tid >> 5, lane = tid & 31;

    // ---- stage 0: gather edge extras + load We1 tail into A + We2 chunk0 into B ----
    for (int e = warp; e < EB; e += 8) {
        int ed = eg + e; if (ed > E - 1) ed = E - 1;
        if (lane < 16) sA[e * 16 + lane] = __ldg(a + (size_t)ed * 16 + lane);
        if (lane == 0) {
            int si = src[ed], di = dst[ed];
            sSrc[e] = si; sDst[e] = di;
            float dx = coords[si * 3 + 0] - coords[di * 3 + 0];
            float dy = coords[si * 3 + 1] - coords[di * 3 + 1];
            float dz = coords[si * 3 + 2] - coords[di * 3 + 2];
            sRad[e] = dx * dx + dy * dy + dz * dz;
            sDx[e] = dx; sDy[e] = dy; sDz[e] = dz;
        }
    }
    // We1 rows 256..272 (17 x 160 = 680 float4)
    #pragma unroll
    for (int i = 0; i < 3; i++) {
        int idx = tid + 256 * i;
        if (i < 2 || idx < 680) {
            int r = idx / 40, c4 = idx % 40;
            *(float4*)(sWA + r * 160 + 4 * c4) =
                __ldg((const float4*)(We1 + (size_t)(256 + r) * 160 + 4 * c4));
        }
    }
    load_w_chunk(sWB, We2, 0, tid);
    __syncthreads();

    const int ecg = tid >> 4;   // rows ecg + 16*i
    const int jcg = tid & 15;   // cols 4jcg..+3, 64+4jcg..+3, 128+2jcg,+1

    // ---- GEMM1-lite: m1 = silu(P1[src] + P2[dst] + [rad,a]@We1[256:273] + be1) ----
    {
        ull acc[4][5];
        #pragma unroll
        for (int i = 0; i < 4; i++) {
            int r = ecg + 16 * i;
            const float* Ps = g_P + (size_t)sSrc[r] * 320;
            const float* Pd = g_P + (size_t)sDst[r] * 320 + 160;
            float4 a0 = __ldg((const float4*)(Ps + 4 * jcg));
            float4 b0 = __ldg((const float4*)(Pd + 4 * jcg));
            acc[i][0] = pk2(a0.x + b0.x, a0.y + b0.y);
            acc[i][1] = pk2(a0.z + b0.z, a0.w + b0.w);
            float4 a1 = __ldg((const float4*)(Ps + 64 + 4 * jcg));
            float4 b1 = __ldg((const float4*)(Pd + 64 + 4 * jcg));
            acc[i][2] = pk2(a1.x + b1.x, a1.y + b1.y);
            acc[i][3] = pk2(a1.z + b1.z, a1.w + b1.w);
            float2 a2 = __ldg((const float2*)(Ps + 128 + 2 * jcg));
            float2 b2 = __ldg((const float2*)(Pd + 128 + 2 * jcg));
            acc[i][4] = pk2(a2.x + b2.x, a2.y + b2.y);
        }
        // k = 0..16: radial + edge attrs, weights from smem buffer A (packed loads)
        #pragma unroll 4
        for (int k = 0; k < 17; k++) {
            const float* wr = sWA + k * 160;
            ulonglong2 W0 = *(const ulonglong2*)(wr + 4 * jcg);
            ulonglong2 W1 = *(const ulonglong2*)(wr + 64 + 4 * jcg);
            ull W2 = *(const ull*)(wr + 128 + 2 * jcg);
            #pragma unroll
            for (int i = 0; i < 4; i++) {
                int r = ecg + 16 * i;
                float c = (k == 0) ? sRad[r] : sA[r * 16 + (k - 1)];
                ull fa = pk2(c, c);
                ffma2(acc[i][0], fa, W0.x); ffma2(acc[i][1], fa, W0.y);
                ffma2(acc[i][2], fa, W1.x); ffma2(acc[i][3], fa, W1.y);
                ffma2(acc[i][4], fa, W2);
            }
        }
        #pragma unroll
        for (int i = 0; i < 4; i++) {
            float* orow = sm1 + (ecg + 16 * i) * 164;
            float lo, hi;
            int c = 4 * jcg;
            upk2(acc[i][0], lo, hi);
            orow[c]   = siluf(lo + __ldg(be1 + c));     orow[c+1] = siluf(hi + __ldg(be1 + c + 1));
            upk2(acc[i][1], lo, hi);
            orow[c+2] = siluf(lo + __ldg(be1 + c + 2)); orow[c+3] = siluf(hi + __ldg(be1 + c + 3));
            c = 64 + 4 * jcg;
            upk2(acc[i][2], lo, hi);
            orow[c]   = siluf(lo + __ldg(be1 + c));     orow[c+1] = siluf(hi + __ldg(be1 + c + 1));
            upk2(acc[i][3], lo, hi);
            orow[c+2] = siluf(lo + __ldg(be1 + c + 2)); orow[c+3] = siluf(hi + __ldg(be1 + c + 3));
            c = 128 + 2 * jcg;
            upk2(acc[i][4], lo, hi);
            orow[c]   = siluf(lo + __ldg(be1 + c));     orow[c+1] = siluf(hi + __ldg(be1 + c + 1));
        }
    }
    __syncthreads();

    // ---- GEMM2 (in-place): m = silu(m1 @ We2 + be2), double-buffered smem weights ----
    {
        ull acc[4][5];
        #pragma unroll
        for (int i = 0; i < 4; i++) { acc[i][0]=0; acc[i][1]=0; acc[i][2]=0; acc[i][3]=0; acc[i][4]=0; }
        const float* f0 = sm1 + (ecg +  0) * 164;
        const float* f1 = sm1 + (ecg + 16) * 164;
        const float* f2p = sm1 + (ecg + 32) * 164;
        const float* f3p = sm1 + (ecg + 48) * 164;

        for (int ch = 0; ch < 10; ch++) {
            const float* wbuf = (ch & 1) ? sWA : sWB;
            if (ch < 9) load_w_chunk((ch & 1) ? sWB : sWA, We2, 16 * (ch + 1), tid);
            const int kb = 16 * ch;
            #pragma unroll 2
            for (int k2 = 0; k2 < 16; k2 += 2) {
                float2 a0 = *(const float2*)(f0 + kb + k2);
                float2 a1 = *(const float2*)(f1 + kb + k2);
                float2 a2 = *(const float2*)(f2p + kb + k2);
                float2 a3 = *(const float2*)(f3p + kb + k2);
                #pragma unroll
                for (int kk = 0; kk < 2; kk++) {
                    ull fa[4];
                    float c0 = kk ? a0.y : a0.x, c1 = kk ? a1.y : a1.x;
                    float c2 = kk ? a2.y : a2.x, c3 = kk ? a3.y : a3.x;
                    fa[0] = pk2(c0, c0); fa[1] = pk2(c1, c1);
                    fa[2] = pk2(c2, c2); fa[3] = pk2(c3, c3);
                    const float* wr = wbuf + (k2 + kk) * 160;
                    ulonglong2 W0 = *(const ulonglong2*)(wr + 4 * jcg);
                    ulonglong2 W1 = *(const ulonglong2*)(wr + 64 + 4 * jcg);
                    ull W2 = *(const ull*)(wr + 128 + 2 * jcg);
                    #pragma unroll
                    for (int i = 0; i < 4; i++) {
                        ffma2(acc[i][0], fa[i], W0.x); ffma2(acc[i][1], fa[i], W0.y);
                        ffma2(acc[i][2], fa[i], W1.x); ffma2(acc[i][3], fa[i], W1.y);
                        ffma2(acc[i][4], fa[i], W2);
                    }
                }
            }
            __syncthreads();   // compute of ch done by all; load of ch+1 visible
        }
        // in-place overwrite safe: last sync drained all activation reads
        #pragma unroll
        for (int i = 0; i < 4; i++) {
            float* orow = sm1 + (ecg + 16 * i) * 164;
            float lo, hi;
            int c = 4 * jcg;
            upk2(acc[i][0], lo, hi);
            orow[c]   = siluf(lo + __ldg(be2 + c));     orow[c+1] = siluf(hi + __ldg(be2 + c + 1));
            upk2(acc[i][1], lo, hi);
            orow[c+2] = siluf(lo + __ldg(be2 + c + 2)); orow[c+3] = siluf(hi + __ldg(be2 + c + 3));
            c = 64 + 4 * jcg;
            upk2(acc[i][2], lo, hi);
            orow[c]   = siluf(lo + __ldg(be2 + c));     orow[c+1] = siluf(hi + __ldg(be2 + c + 1));
            upk2(acc[i][3], lo, hi);
            orow[c+2] = siluf(lo + __ldg(be2 + c + 2)); orow[c+3] = siluf(hi + __ldg(be2 + c + 3));
            c = 128 + 2 * jcg;
            upk2(acc[i][4], lo, hi);
            orow[c]   = siluf(lo + __ldg(be2 + c));     orow[c+1] = siluf(hi + __ldg(be2 + c + 1));
        }
    }
    __syncthreads();

    // ---- logits = m @ Wa ----
    #pragma unroll
    for (int pass = 0; pass < 2; pass++) {
        int e = (tid >> 3) + 32 * pass;
        int hh = tid & 7;
        const float* mr = sm1 + e * 164;
        float accl = 0.f;
        #pragma unroll 8
        for (int k = 0; k < INNER; k++) accl += mr[k] * __ldg(Wa + k * 8 + hh);
        int ed = eg + e;
        if (ed < E) g_logits[(size_t)ed * 8 + hh] = accl;
    }

    // ---- coordinate messages ----
    if (tid < EB) {
        int e = tid;
        const float* mr = sm1 + e * 164;
        float c = 0.f;
        #pragma unroll 8
        for (int k = 0; k < INNER; k++) c += mr[k] * __ldg(Wc + k);
        float s = c / (sqrtf(sRad[e] + 1e-5f) + 1.0f);
        int ed = eg + e;
        if (ed < E) {
            g_msgx[(size_t)ed * 3 + 0] = sDx[e] * s;
            g_msgx[(size_t)ed * 3 + 1] = sDy[e] * s;
            g_msgx[(size_t)ed * 3 + 2] = sDz[e] * s;
        }
    }

    // ---- write m to global ----
    for (int idx = tid; idx < 64 * 40; idx += 256) {
        int r = idx / 40, c4 = idx % 40;
        int ed = eg + r;
        if (ed < E)
            *(float4*)(g_m + (size_t)ed * 160 + 4 * c4) = *(const float4*)(sm1 + r * 164 + 4 * c4);
    }
}

// ---------------- warp-per-node aggregation: in-place weights, streaming loop ----------------
__global__ void __launch_bounds__(256) k_agg(const float* __restrict__ coords,
                                             const float* __restrict__ Wv,
                                             float* __restrict__ out_coords, int N)
{
    __shared__ float sS[8][8][164];   // node, head, k
    const int tid = threadIdx.x;
    const int warp = tid >> 5, lane = tid & 31;
    const int nb = blockIdx.x * 8;
    const int n = nb + warp;
    const int le = lane >> 3, lh = lane & 7;

    if (n < N) {
        const int s0 = g_start[n];
        const int deg = g_start[n + 1] - s0;

        // --- phase 1: softmax stats, then overwrite g_logits with normalized weights ---
        float mx = -3.0e38f;
        for (int c = le; c < deg; c += 4) {
            int e = g_eid[s0 + c];
            mx = fmaxf(mx, __ldg(g_logits + (size_t)e * 8 + lh));
        }
        mx = fmaxf(mx, __shfl_xor_sync(~0u, mx, 8));
        mx = fmaxf(mx, __shfl_xor_sync(~0u, mx, 16));
        float den = 0.f;
        for (int c = le; c < deg; c += 4) {
            int e = g_eid[s0 + c];
            den += __expf(__ldg(g_logits + (size_t)e * 8 + lh) - mx);
        }
        den += __shfl_xor_sync(~0u, den, 8);
        den += __shfl_xor_sync(~0u, den, 16);
        float rden = 1.f / den;
        for (int c = le; c < deg; c += 4) {
            int e = g_eid[s0 + c];
            float w = __expf(__ldg(g_logits + (size_t)e * 8 + lh) - mx) * rden;
            g_logits[(size_t)e * 8 + lh] = w;     // this edge belongs only to this warp
        }
        __syncwarp();

        // --- phase 2: streaming accumulation, no barriers ---
        float acc[8][5];
        #pragma unroll
        for (int hh = 0; hh < 8; hh++)
            #pragma unroll
            for (int q = 0; q < 5; q++) acc[hh][q] = 0.f;

        for (int i = 0; i < deg; i++) {
            int e = g_eid[s0 + i];
            float4 wlo = __ldg((const float4*)(g_logits + (size_t)e * 8));
            float4 whi = __ldg((const float4*)(g_logits + (size_t)e * 8 + 4));
            float v[5];
            #pragma unroll
            for (int q = 0; q < 5; q++)
                v[q] = __ldg(g_m + (size_t)e * 160 + lane + 32 * q);
            #pragma unroll
            for (int q = 0; q < 5; q++) {
                acc[0][q] += v[q] * wlo.x; acc[1][q] += v[q] * wlo.y;
                acc[2][q] += v[q] * wlo.z; acc[3][q] += v[q] * wlo.w;
                acc[4][q] += v[q] * whi.x; acc[5][q] += v[q] * whi.y;
                acc[6][q] += v[q] * whi.z; acc[7][q] += v[q] * whi.w;
            }
        }
        #pragma unroll
        for (int hh = 0; hh < 8; hh++)
            #pragma unroll
            for (int q = 0; q < 5; q++)
                sS[warp][hh][lane + 32 * q] = acc[hh][q];

        // --- coordinate scatter-sum (lanes 0..2) ---
        if (lane < 3) {
            float cacc = 0.f;
            for (int i = 0; i < deg; i++)
                cacc += __ldg(g_msgx + (size_t)g_eid[s0 + i] * 3 + lane);
            out_coords[n * 3 + lane] = coords[n * 3 + lane] + cacc;
        }
    }
    __syncthreads();

    // --- batched Wv epilogue: h_agg[n][j] = sum_k sS[n][j>>4][k] * Wv[k][j] ---
    {
        const int j = tid & 127, grp = tid >> 7;     // grp 0..1, 4 nodes each
        const int head = j >> 4;
        #pragma unroll
        for (int r = 0; r < 4; r++) {
            int wn = grp * 4 + r;
            int n2 = nb + wn;
            if (n2 < N) {
                const float* sr = sS[wn][head];
                float hv = 0.f;
                #pragma unroll 8
                for (int k = 0; k < INNER; k++) hv += sr[k] * __ldg(Wv + k * 128 + j);
                g_hagg[(size_t)n2 * 128 + j] = hv;
            }
        }
    }
}

// ---------------- batched node GEMM helpers ----------------
template<int K, int NP, int C>
__device__ __forceinline__ void gemm_n(const float* __restrict__ sIn, int is,
                                       const float* __restrict__ W,
                                       ull (&acc)[4][NP][2]) {
    const int tid = threadIdx.x;
    const int ecg = tid >> 5, jcg = tid & 31;
    #pragma unroll
    for (int i = 0; i < 4; i++)
        #pragma unroll
        for (int p = 0; p < NP; p++) { acc[i][p][0] = 0; acc[i][p][1] = 0; }
    for (int k4 = 0; k4 < K; k4 += 4) {
        float4 av[4];
        #pragma unroll
        for (int i = 0; i < 4; i++) av[i] = *(const float4*)(sIn + (ecg + 8 * i) * is + k4);
        #pragma unroll
        for (int kk = 0; kk < 4; kk++) {
            ull fa[4];
            #pragma unroll
            for (int i = 0; i < 4; i++) { float c = getc(av[i], kk); fa[i] = pk2(c, c); }
            const float* wr = W + (k4 + kk) * C + 4 * jcg;
            #pragma unroll
            for (int p = 0; p < NP; p++) {
                if ((C % 128 == 0) || (128 * p + 4 * jcg < C)) {
                    ulonglong2 wv = __ldg((const ulonglong2*)(wr + 128 * p));
                    #pragma unroll
                    for (int i = 0; i < 4; i++) { ffma2(acc[i][p][0], fa[i], wv.x); ffma2(acc[i][p][1], fa[i], wv.y); }
                }
            }
        }
    }
}

template<int NP, int C>
__device__ __forceinline__ void store_acc(ull (&acc)[4][NP][2], float* sOut, int os,
                                          const float* bias, bool dosilu) {
    const int tid = threadIdx.x, ecg = tid >> 5, jcg = tid & 31;
    #pragma unroll
    for (int i = 0; i < 4; i++) {
        int r = ecg + 8 * i;
        #pragma unroll
        for (int p = 0; p < NP; p++) {
            int c0 = 128 * p + 4 * jcg;
            if ((C % 128 == 0) || (c0 < C)) {
                float v0, v1, v2, v3;
                upk2(acc[i][p][0], v0, v1); upk2(acc[i][p][1], v2, v3);
                if (bias) {
                    v0 += __ldg(bias + c0); v1 += __ldg(bias + c0 + 1);
                    v2 += __ldg(bias + c0 + 2); v3 += __ldg(bias + c0 + 3);
                }
                if (dosilu) { v0 = siluf(v0); v1 = siluf(v1); v2 = siluf(v2); v3 = siluf(v3); }
                *(float4*)(sOut + r * os + c0) = make_float4(v0, v1, v2, v3);
            }
        }
    }
}

__device__ __forceinline__ void film_store(ull (&acc)[4][2][2], float* sScale, float* sShift,
                                           const float* bias) {
    const int tid = threadIdx.x, ecg = tid >> 5, jcg = tid & 31;
    #pragma unroll
    for (int i = 0; i < 4; i++) {
        int r = ecg + 8 * i;
        int c0 = 4 * jcg;
        float v0, v1, v2, v3;
        upk2(acc[i][0][0], v0, v1); upk2(acc[i][0][1], v2, v3);
        v0 += __ldg(bias + c0); v1 += __ldg(bias + c0 + 1);
        v2 += __ldg(bias + c0 + 2); v3 += __ldg(bias + c0 + 3);
        *(float4*)(sScale + r * 132 + c0) = make_float4(v0, v1, v2, v3);
        upk2(acc[i][1][0], v0, v1); upk2(acc[i][1][1], v2, v3);
        v0 += __ldg(bias + 128 + c0); v1 += __ldg(bias + 128 + c0 + 1);
        v2 += __ldg(bias + 128 + c0 + 2); v3 += __ldg(bias + 128 + c0 + 3);
        *(float4*)(sShift + r * 164 + c0) = make_float4(v0, v1, v2, v3);
    }
}

__device__ __forceinline__ void ln_stats(const float* sX, float* sMu, float* sRs) {
    int w = threadIdx.x >> 5, lane = threadIdx.x & 31;
    #pragma unroll
    for (int rr = 0; rr < 4; rr++) {
        int r = w * 4 + rr;
        float4 v = *(const float4*)(sX + r * 132 + 4 * lane);
        float s = v.x + v.y + v.z + v.w;
        float q = v.x * v.x + v.y * v.y + v.z * v.z + v.w * v.w;
        #pragma unroll
        for (int o = 16; o; o >>= 1) {
            s += __shfl_xor_sync(~0u, s, o);
            q += __shfl_xor_sync(~0u, q, o);
        }
        if (lane == 0) {
            float mu = s * (1.f / 128.f);
            float var = q * (1.f / 128.f) - mu * mu;
            sMu[r] = mu; sRs[r] = rsqrtf(var + 1e-5f);
        }
    }
}

// ---------------- batched node kernel (32 nodes/block) ----------------
__global__ void __launch_bounds__(256, 2) k_node(
    const float* __restrict__ h, const float* __restrict__ res, const float* __restrict__ y,
    const float* __restrict__ Wo,
    const float* __restrict__ Wn1, const float* __restrict__ bn1,
    const float* __restrict__ Wn2, const float* __restrict__ bn2,
    const float* __restrict__ Wf1, const float* __restrict__ bf1,
    const float* __restrict__ Wf2, const float* __restrict__ bf2,
    float* __restrict__ out_h2, float* __restrict__ out_res2, int N)
{
    extern __shared__ float sm_n[];
    float* sA  = sm_n;                 // [32][164]
    float* sB  = sA + 32 * 164;        // [32][132]
    float* sC  = sB + 32 * 132;        // [32][132]
    float* sY  = sC + 32 * 132;        // [32][68]
    float* sMu = sY + 32 * 68;         // [32]
    float* sRs = sMu + 32;             // [32]

    const int nb = blockIdx.x * NB;
    const int tid = threadIdx.x;

    for (int idx = tid; idx < 32 * 128; idx += 256) {
        int r = idx >> 7, c = idx & 127;
        int n = min(nb + r, N - 1);
        sB[r * 132 + c] = g_hagg[(size_t)n * 128 + c];
    }
    for (int idx = tid; idx < 32 * 64; idx += 256) {
        int r = idx >> 6, c = idx & 63;
        int n = min(nb + r, N - 1);
        sY[r * 68 + c] = y[(size_t)n * 64 + c];
    }
    __syncthreads();

    {
        ull acc[4][1][2];
        gemm_n<128, 1, 128>(sB, 132, Wo, acc);
        store_acc<1, 128>(acc, sC, 132, nullptr, false);
    }
    __syncthreads();

    float f2r[16];
    #pragma unroll
    for (int t = 0; t < 16; t++) {
        int idx = tid + 256 * t;
        int r = idx >> 7, c = idx & 127;
        int n = min(nb + r, N - 1);
        float f2v = sC[r * 132 + c];
        f2r[t] = f2v;
        sB[r * 132 + c] = h[(size_t)n * 128 + c] + f2v;
    }
    __syncthreads();
    ln_stats(sB, sMu, sRs);
    __syncthreads();

    {
        ull acc[4][2][2];
        gemm_n<64, 2, 256>(sY, 68, Wf1, acc);
        film_store(acc, sC, sA, bf1);
    }
    __syncthreads();

    #pragma unroll
    for (int t = 0; t < 16; t++) {
        int idx = tid + 256 * t;
        int r = idx >> 7, c = idx & 127;
        float x = sB[r * 132 + c];
        float xn = (x - sMu[r]) * sRs[r];
        sB[r * 132 + c] = xn * (1.f + sC[r * 132 + c]) + sA[r * 164 + c];
    }
    __syncthreads();

    {
        ull acc[4][2][2];
        gemm_n<128, 2, 160>(sB, 132, Wn1, acc);
        store_acc<2, 160>(acc, sA, 164, bn1, true);
    }
    __syncthreads();

    {
        ull acc[4][1][2];
        gemm_n<160, 1, 128>(sA, 164, Wn2, acc);
        store_acc<1, 128>(acc, sC, 132, bn2, false);
    }
    __syncthreads();

    #pragma unroll
    for (int t = 0; t < 16; t++) {
        int idx = tid + 256 * t;
        int r = idx >> 7, c = idx & 127;
        float f3 = sC[r * 132 + c];
        int n = nb + r;
        if (n < N) out_res2[(size_t)n * 128 + c] = res[(size_t)n * 128 + c] + f2r[t] + f3;
        sB[r * 132 + c] += f3;
    }
    __syncthreads();
    ln_stats(sB, sMu, sRs);
    __syncthreads();

    {
        ull acc[4][2][2];
        gemm_n<64, 2, 256>(sY, 68, Wf2, acc);
        film_store(acc, sC, sA, bf2);
    }
    __syncthreads();

    #pragma unroll
    for (int t = 0; t < 16; t++) {
        int idx = tid + 256 * t;
        int r = idx >> 7, c = idx & 127;
        int n = nb + r;
        if (n < N) {
            float xn = (sB[r * 132 + c] - sMu[r]) * sRs[r];
            out_h2[(size_t)n * 128 + c] = xn * (1.f + sC[r * 132 + c]) + sA[r * 164 + c];
        }
    }
}

// ---------------- launch ----------------
extern "C" void kernel_launch(void* const* d_in, const int* in_sizes, int n_in,
                              void* d_out, int out_size) {
    const float* h      = (const float*)d_in[0];
    const float* coords = (const float*)d_in[1];
    const float* a      = (const float*)d_in[2];
    const float* y      = (const float*)d_in[3];
    const float* res    = (const float*)d_in[4];
    const int*   src    = (const int*)d_in[5];
    const int*   dst    = (const int*)d_in[6];
    const float* We1 = (const float*)d_in[7];
    const float* be1 = (const float*)d_in[8];
    const float* We2 = (const float*)d_in[9];
    const float* be2 = (const float*)d_in[10];
    const float* Wc  = (const float*)d_in[11];
    const float* Wv  = (const float*)d_in[12];
    const float* Wa  = (const float*)d_in[13];
    const float* Wo  = (const float*)d_in[14];
    const float* Wn1 = (const float*)d_in[15];
    const float* bn1 = (const float*)d_in[16];
    const float* Wn2 = (const float*)d_in[17];
    const float* bn2 = (const float*)d_in[18];
    const float* Wf1 = (const float*)d_in[19];
    const float* bf1 = (const float*)d_in[20];
    const float* Wf2 = (const float*)d_in[21];
    const float* bf2 = (const float*)d_in[22];

    const int N = in_sizes[0] / HID;
    const int E = in_sizes[5];

    float* out = (float*)d_out;
    float* out_h2 = out;
    float* out_coords = out + (size_t)N * HID;
    float* out_res2 = out + (size_t)N * HID + (size_t)N * 3;

    const int SMEM_E = (64 * 164 + 2 * 2720 + 64 * 16 + 64 * 6) * (int)sizeof(float);
    const int SMEM_N = (32 * 164 + 32 * 132 * 2 + 32 * 68 + 64) * (int)sizeof(float);
    cudaFuncSetAttribute(k_edge, cudaFuncAttributeMaxDynamicSharedMemorySize, SMEM_E);
    cudaFuncSetAttribute(k_node, cudaFuncAttributeMaxDynamicSharedMemorySize, SMEM_N);

    k_zero<<<(N + 255) / 256, 256>>>(N);
    k_deg<<<(E + 255) / 256, 256>>>(dst, E);
    k_pre<<<(N + 31) / 32, 256>>>(h, We1, N);
    // k_edge 4th: the ncu window captures launch #4
    k_edge<<<(E + EB - 1) / EB, 256, SMEM_E>>>(coords, a, src, dst,
                                               We1, be1, We2, be2, Wc, Wa, E);
    k_scan<<<1, 1024>>>(N);
    k_fill<<<(E + 255) / 256, 256>>>(dst, E);
    k_agg<<<(N + 7) / 8, 256>>>(coords, Wv, out_coords, N);
    k_node<<<(N + NB - 1) / NB, 256, SMEM_N>>>(h, res, y, Wo, Wn1, bn1, Wn2, bn2,
                                               Wf1, bf1, Wf2, bf2, out_h2, out_res2, N);
}

// round 11
// speedup vs baseline: 1.3463x; 1.1677x over previous
#include <cuda_runtime.h>
#include <math.h>

#define NMAX 25000
#define EMAX 400000
#define HID 128
#define INNER 160
#define EB 64      // edges per block
#define NB 32      // nodes per block (k_node)

// ---------------- scratch ----------------
__device__ float g_m[(size_t)EMAX * 160];      // per-edge message m
__device__ float g_logits[(size_t)EMAX * 8];   // logits, later overwritten with softmax weights
__device__ float g_msgx[(size_t)EMAX * 3];
__device__ float g_hagg[(size_t)NMAX * 128];
__device__ float g_P[(size_t)NMAX * 320];      // precomputed h@We1 (src half | dst half)
__device__ int g_deg[NMAX];
__device__ int g_cursor[NMAX];
__device__ int g_start[NMAX + 1];
__device__ int g_eid[EMAX];

// ---------------- helpers ----------------
typedef unsigned long long ull;
__device__ __forceinline__ ull pk2(float a, float b) {
    ull r;
    asm("mov.b64 %0, {%1, %2};" : "=l"(r) : "r"(__float_as_uint(a)), "r"(__float_as_uint(b)));
    return r;
}
__device__ __forceinline__ void upk2(ull v, float &a, float &b) {
    unsigned int lo, hi;
    asm("mov.b64 {%0, %1}, %2;" : "=r"(lo), "=r"(hi) : "l"(v));
    a = __uint_as_float(lo); b = __uint_as_float(hi);
}
__device__ __forceinline__ void ffma2(ull &d, ull a, ull b) {
    asm("fma.rn.f32x2 %0, %1, %2, %3;" : "=l"(d) : "l"(a), "l"(b), "l"(d));
}
__device__ __forceinline__ float siluf(float x) { return x / (1.0f + __expf(-x)); }
__device__ __forceinline__ float getc(const float4& v, int kk) {
    return kk == 0 ? v.x : kk == 1 ? v.y : kk == 2 ? v.z : v.w;
}
// round fp32 -> tf32 (rna), keep as fp32 bit pattern
__device__ __forceinline__ float tf32f(float x) {
    unsigned r;
    asm("cvt.rna.tf32.f32 %0, %1;" : "=r"(r) : "f"(x));
    return __uint_as_float(r);
}
__device__ __forceinline__ void mma_tf32(float* c, unsigned a0, unsigned a1,
                                         unsigned a2, unsigned a3,
                                         unsigned b0, unsigned b1) {
    asm volatile(
        "mma.sync.aligned.m16n8k8.row.col.f32.tf32.tf32.f32 "
        "{%0,%1,%2,%3}, {%4,%5,%6,%7}, {%8,%9}, {%0,%1,%2,%3};"
        : "+f"(c[0]), "+f"(c[1]), "+f"(c[2]), "+f"(c[3])
        : "r"(a0), "r"(a1), "r"(a2), "r"(a3), "r"(b0), "r"(b1));
}

// ---------------- CSR build ----------------
__global__ void k_zero(int n) {
    int i = blockIdx.x * blockDim.x + threadIdx.x;
    if (i < n) { g_deg[i] = 0; g_cursor[i] = 0; }
}
__global__ void k_deg(const int* __restrict__ dst, int E) {
    int e = blockIdx.x * blockDim.x + threadIdx.x;
    if (e < E) atomicAdd(&g_deg[dst[e]], 1);
}
__global__ void k_scan(int n) {
    __shared__ int sh[1024];
    int carry = 0;
    for (int base = 0; base < n; base += 1024) {
        int i = base + threadIdx.x;
        int x = (i < n) ? g_deg[i] : 0;
        sh[threadIdx.x] = x;
        __syncthreads();
        for (int off = 1; off < 1024; off <<= 1) {
            int v = (threadIdx.x >= off) ? sh[threadIdx.x - off] : 0;
            __syncthreads();
            sh[threadIdx.x] += v;
            __syncthreads();
        }
        if (i < n) g_start[i] = carry + sh[threadIdx.x] - x;
        carry += sh[1023];
        __syncthreads();
    }
    if (threadIdx.x == 0) g_start[n] = carry;
}
__global__ void k_fill(const int* __restrict__ dst, int E) {
    int e = blockIdx.x * blockDim.x + threadIdx.x;
    if (e < E) {
        int d = dst[e];
        int p = atomicAdd(&g_cursor[d], 1);
        g_eid[g_start[d] + p] = e;
    }
}

// ---------------- precompute P[n] = [h@We1[0:128] | h@We1[128:256]] ----------------
__global__ void __launch_bounds__(256) k_pre(const float* __restrict__ h,
                                             const float* __restrict__ We1, int N)
{
    __shared__ float sH[32][132];
    const int nb = blockIdx.x * 32;
    const int tid = threadIdx.x;
    for (int idx = tid; idx < 32 * 128; idx += 256) {
        int r = idx >> 7, c = idx & 127;
        int n = min(nb + r, N - 1);
        sH[r][c] = h[(size_t)n * 128 + c];
    }
    __syncthreads();

    const int ecg = tid >> 5, jcg = tid & 31;
    ull accA[4][3], accB[4][3];
    #pragma unroll
    for (int i = 0; i < 4; i++)
        #pragma unroll
        for (int p = 0; p < 3; p++) { accA[i][p] = 0; accB[i][p] = 0; }

    for (int k = 0; k < 128; k++) {
        ull fa[4];
        #pragma unroll
        for (int i = 0; i < 4; i++) { float c = sH[ecg + 8 * i][k]; fa[i] = pk2(c, c); }
        const float* w1 = We1 + (size_t)k * INNER;
        const float* w2 = We1 + (size_t)(128 + k) * INNER;
        ulonglong2 WA = __ldg((const ulonglong2*)(w1 + 4 * jcg));
        ulonglong2 WB = __ldg((const ulonglong2*)(w2 + 4 * jcg));
        ull A2 = 0, B2 = 0;
        if (jcg < 16) {
            A2 = __ldg((const ull*)(w1 + 128 + 2 * jcg));
            B2 = __ldg((const ull*)(w2 + 128 + 2 * jcg));
        }
        #pragma unroll
        for (int i = 0; i < 4; i++) {
            ffma2(accA[i][0], fa[i], WA.x); ffma2(accA[i][1], fa[i], WA.y);
            ffma2(accB[i][0], fa[i], WB.x); ffma2(accB[i][1], fa[i], WB.y);
            if (jcg < 16) { ffma2(accA[i][2], fa[i], A2); ffma2(accB[i][2], fa[i], B2); }
        }
    }
    #pragma unroll
    for (int i = 0; i < 4; i++) {
        int n = nb + ecg + 8 * i;
        if (n < N) {
            float* out = g_P + (size_t)n * 320;
            float x0, x1, x2, x3;
            upk2(accA[i][0], x0, x1); upk2(accA[i][1], x2, x3);
            *(float4*)(out + 4 * jcg) = make_float4(x0, x1, x2, x3);
            upk2(accB[i][0], x0, x1); upk2(accB[i][1], x2, x3);
            *(float4*)(out + 160 + 4 * jcg) = make_float4(x0, x1, x2, x3);
            if (jcg < 16) {
                upk2(accA[i][2], x0, x1);
                *(float2*)(out + 128 + 2 * jcg) = make_float2(x0, x1);
                upk2(accB[i][2], x0, x1);
                *(float2*)(out + 288 + 2 * jcg) = make_float2(x0, x1);
            }
        }
    }
}

// chunk loader: 16 rows x 160 cols of W -> tf32-rounded, stride-168 smem buffer
__device__ __forceinline__ void load_w_chunk_tf32(float* dstbuf, const float* __restrict__ W,
                                                  int k0, int tid) {
    #pragma unroll
    for (int i = 0; i < 3; i++) {
        int idx = tid + 256 * i;
        if (i < 2 || idx < 640) {
            int r = idx / 40, c4 = idx % 40;
            float4 v = __ldg((const float4*)(W + (size_t)(k0 + r) * 160 + 4 * c4));
            v.x = tf32f(v.x); v.y = tf32f(v.y); v.z = tf32f(v.z); v.w = tf32f(v.w);
            *(float4*)(dstbuf + r * 168 + 4 * c4) = v;
        }
    }
}

// ---------------- fused edge kernel (GEMM2 on tf32 tensor cores) ----------------
__global__ void __launch_bounds__(256, 3) k_edge(
    const float* __restrict__ coords, const float* __restrict__ a,
    const int* __restrict__ src, const int* __restrict__ dst,
    const float* __restrict__ We1, const float* __restrict__ be1,
    const float* __restrict__ We2, const float* __restrict__ be2,
    const float* __restrict__ Wc, const float* __restrict__ Wa,
    int E)
{
    extern __shared__ float sm_e[];
    float* sm1  = sm_e;               // [64][164]
    float* sWA  = sm1 + 64 * 164;     // weight buffer A (2720 floats)
    float* sWB  = sWA + 2720;         // weight buffer B (2720 floats; GEMM2 uses stride 168)
    float* sA   = sWB + 2720;         // [64][16]
    float* sRad = sA + 64 * 16;       // [64]
    float* sDx  = sRad + 64;          // [64]
    float* sDy  = sDx + 64;
    float* sDz  = sDy + 64;
    int*   sSrc = (int*)(sDz + 64);   // [64]
    int*   sDst = sSrc + 64;          // [64]

    const int tid = threadIdx.x;
    const int eg = blockIdx.x * EB;
    const int warp = tid >> 5, lane = tid & 31;

    // ---- stage 0: gather edge extras + We1 tail into A (stride 160) + We2 chunk0 into B ----
    for (int e = warp; e < EB; e += 8) {
        int ed = eg + e; if (ed > E - 1) ed = E - 1;
        if (lane < 16) sA[e * 16 + lane] = __ldg(a + (size_t)ed * 16 + lane);
        if (lane == 0) {
            int si = src[ed], di = dst[ed];
            sSrc[e] = si; sDst[e] = di;
            float dx = coords[si * 3 + 0] - coords[di * 3 + 0];
            float dy = coords[si * 3 + 1] - coords[di * 3 + 1];
            float dz = coords[si * 3 + 2] - coords[di * 3 + 2];
            sRad[e] = dx * dx + dy * dy + dz * dz;
            sDx[e] = dx; sDy[e] = dy; sDz[e] = dz;
        }
    }
    // We1 rows 256..272 (17 x 160)
    #pragma unroll
    for (int i = 0; i < 3; i++) {
        int idx = tid + 256 * i;
        if (i < 2 || idx < 680) {
            int r = idx / 40, c4 = idx % 40;
            *(float4*)(sWA + r * 160 + 4 * c4) =
                __ldg((const float4*)(We1 + (size_t)(256 + r) * 160 + 4 * c4));
        }
    }
    load_w_chunk_tf32(sWB, We2, 0, tid);
    __syncthreads();

    const int ecg = tid >> 4;   // rows ecg + 16*i
    const int jcg = tid & 15;   // cols 4jcg..+3, 64+4jcg..+3, 128+2jcg,+1

    // ---- GEMM1-lite: m1 = silu(P1[src] + P2[dst] + [rad,a]@We1[256:273] + be1) ----
    // m1 is stored TF32-ROUNDED (only consumer is the tf32 GEMM2)
    {
        ull acc[4][5];
        #pragma unroll
        for (int i = 0; i < 4; i++) {
            int r = ecg + 16 * i;
            const float* Ps = g_P + (size_t)sSrc[r] * 320;
            const float* Pd = g_P + (size_t)sDst[r] * 320 + 160;
            float4 a0 = __ldg((const float4*)(Ps + 4 * jcg));
            float4 b0 = __ldg((const float4*)(Pd + 4 * jcg));
            acc[i][0] = pk2(a0.x + b0.x, a0.y + b0.y);
            acc[i][1] = pk2(a0.z + b0.z, a0.w + b0.w);
            float4 a1 = __ldg((const float4*)(Ps + 64 + 4 * jcg));
            float4 b1 = __ldg((const float4*)(Pd + 64 + 4 * jcg));
            acc[i][2] = pk2(a1.x + b1.x, a1.y + b1.y);
            acc[i][3] = pk2(a1.z + b1.z, a1.w + b1.w);
            float2 a2 = __ldg((const float2*)(Ps + 128 + 2 * jcg));
            float2 b2 = __ldg((const float2*)(Pd + 128 + 2 * jcg));
            acc[i][4] = pk2(a2.x + b2.x, a2.y + b2.y);
        }
        #pragma unroll 4
        for (int k = 0; k < 17; k++) {
            const float* wr = sWA + k * 160;
            ulonglong2 W0 = *(const ulonglong2*)(wr + 4 * jcg);
            ulonglong2 W1 = *(const ulonglong2*)(wr + 64 + 4 * jcg);
            ull W2 = *(const ull*)(wr + 128 + 2 * jcg);
            #pragma unroll
            for (int i = 0; i < 4; i++) {
                int r = ecg + 16 * i;
                float c = (k == 0) ? sRad[r] : sA[r * 16 + (k - 1)];
                ull fa = pk2(c, c);
                ffma2(acc[i][0], fa, W0.x); ffma2(acc[i][1], fa, W0.y);
                ffma2(acc[i][2], fa, W1.x); ffma2(acc[i][3], fa, W1.y);
                ffma2(acc[i][4], fa, W2);
            }
        }
        #pragma unroll
        for (int i = 0; i < 4; i++) {
            float* orow = sm1 + (ecg + 16 * i) * 164;
            float lo, hi;
            int c = 4 * jcg;
            upk2(acc[i][0], lo, hi);
            orow[c]   = tf32f(siluf(lo + __ldg(be1 + c)));
            orow[c+1] = tf32f(siluf(hi + __ldg(be1 + c + 1)));
            upk2(acc[i][1], lo, hi);
            orow[c+2] = tf32f(siluf(lo + __ldg(be1 + c + 2)));
            orow[c+3] = tf32f(siluf(hi + __ldg(be1 + c + 3)));
            c = 64 + 4 * jcg;
            upk2(acc[i][2], lo, hi);
            orow[c]   = tf32f(siluf(lo + __ldg(be1 + c)));
            orow[c+1] = tf32f(siluf(hi + __ldg(be1 + c + 1)));
            upk2(acc[i][3], lo, hi);
            orow[c+2] = tf32f(siluf(lo + __ldg(be1 + c + 2)));
            orow[c+3] = tf32f(siluf(hi + __ldg(be1 + c + 3)));
            c = 128 + 2 * jcg;
            upk2(acc[i][4], lo, hi);
            orow[c]   = tf32f(siluf(lo + __ldg(be1 + c)));
            orow[c+1] = tf32f(siluf(hi + __ldg(be1 + c + 1)));
        }
    }
    __syncthreads();

    // ---- GEMM2 via tf32 mma.sync: m = silu(m1 @ We2 + be2), in-place into sm1 ----
    {
        const int gid = lane >> 2, tig = lane & 3;
        const int mr  = (warp & 3) * 16;       // M-tile rows mr..mr+15
        const int nb0 = (warp >> 2) * 80;      // N half: 80 cols, 10 subtiles of 8
        float c[10][4];
        #pragma unroll
        for (int ns = 0; ns < 10; ns++)
            #pragma unroll
            for (int q = 0; q < 4; q++) c[ns][q] = 0.f;

        for (int ch = 0; ch < 10; ch++) {
            const float* wbuf = (ch & 1) ? sWA : sWB;     // stride 168
            if (ch < 9) load_w_chunk_tf32((ch & 1) ? sWB : sWA, We2, 16 * (ch + 1), tid);
            #pragma unroll
            for (int ks = 0; ks < 2; ks++) {
                const float* ar = sm1 + (mr + gid) * 164 + ch * 16 + ks * 8;
                unsigned a0 = __float_as_uint(ar[tig]);
                unsigned a1 = __float_as_uint(ar[8 * 164 + tig]);
                unsigned a2 = __float_as_uint(ar[tig + 4]);
                unsigned a3 = __float_as_uint(ar[8 * 164 + tig + 4]);
                const float* br  = wbuf + (ks * 8 + tig) * 168 + nb0 + gid;
                const float* br2 = wbuf + (ks * 8 + tig + 4) * 168 + nb0 + gid;
                #pragma unroll
                for (int ns = 0; ns < 10; ns++) {
                    unsigned b0 = __float_as_uint(br[ns * 8]);
                    unsigned b1 = __float_as_uint(br2[ns * 8]);
                    mma_tf32(c[ns], a0, a1, a2, a3, b0, b1);
                }
            }
            __syncthreads();   // compute of ch done by all; prefetch of ch+1 visible
        }
        // epilogue: bias + silu, in-place store (all m1 reads drained by last sync)
        #pragma unroll
        for (int ns = 0; ns < 10; ns++) {
            int col = nb0 + ns * 8 + tig * 2;
            float b0v = __ldg(be2 + col), b1v = __ldg(be2 + col + 1);
            float* r0 = sm1 + (mr + gid) * 164 + col;
            float* r1 = sm1 + (mr + gid + 8) * 164 + col;
            r0[0] = siluf(c[ns][0] + b0v); r0[1] = siluf(c[ns][1] + b1v);
            r1[0] = siluf(c[ns][2] + b0v); r1[1] = siluf(c[ns][3] + b1v);
        }
    }
    __syncthreads();

    // ---- logits = m @ Wa ----
    #pragma unroll
    for (int pass = 0; pass < 2; pass++) {
        int e = (tid >> 3) + 32 * pass;
        int hh = tid & 7;
        const float* mr = sm1 + e * 164;
        float accl = 0.f;
        #pragma unroll 8
        for (int k = 0; k < INNER; k++) accl += mr[k] * __ldg(Wa + k * 8 + hh);
        int ed = eg + e;
        if (ed < E) g_logits[(size_t)ed * 8 + hh] = accl;
    }

    // ---- coordinate messages ----
    if (tid < EB) {
        int e = tid;
        const float* mr = sm1 + e * 164;
        float c = 0.f;
        #pragma unroll 8
        for (int k = 0; k < INNER; k++) c += mr[k] * __ldg(Wc + k);
        float s = c / (sqrtf(sRad[e] + 1e-5f) + 1.0f);
        int ed = eg + e;
        if (ed < E) {
            g_msgx[(size_t)ed * 3 + 0] = sDx[e] * s;
            g_msgx[(size_t)ed * 3 + 1] = sDy[e] * s;
            g_msgx[(size_t)ed * 3 + 2] = sDz[e] * s;
        }
    }

    // ---- write m to global ----
    for (int idx = tid; idx < 64 * 40; idx += 256) {
        int r = idx / 40, c4 = idx % 40;
        int ed = eg + r;
        if (ed < E)
            *(float4*)(g_m + (size_t)ed * 160 + 4 * c4) = *(const float4*)(sm1 + r * 164 + 4 * c4);
    }
}

// ---------------- warp-per-node aggregation: in-place weights, streaming loop ----------------
__global__ void __launch_bounds__(256) k_agg(const float* __restrict__ coords,
                                             const float* __restrict__ Wv,
                                             float* __restrict__ out_coords, int N)
{
    __shared__ float sS[8][8][164];   // node, head, k
    const int tid = threadIdx.x;
    const int warp = tid >> 5, lane = tid & 31;
    const int nb = blockIdx.x * 8;
    const int n = nb + warp;
    const int le = lane >> 3, lh = lane & 7;

    if (n < N) {
        const int s0 = g_start[n];
        const int deg = g_start[n + 1] - s0;

        // --- phase 1: softmax stats, then overwrite g_logits with normalized weights ---
        float mx = -3.0e38f;
        for (int c = le; c < deg; c += 4) {
            int e = g_eid[s0 + c];
            mx = fmaxf(mx, __ldg(g_logits + (size_t)e * 8 + lh));
        }
        mx = fmaxf(mx, __shfl_xor_sync(~0u, mx, 8));
        mx = fmaxf(mx, __shfl_xor_sync(~0u, mx, 16));
        float den = 0.f;
        for (int c = le; c < deg; c += 4) {
            int e = g_eid[s0 + c];
            den += __expf(__ldg(g_logits + (size_t)e * 8 + lh) - mx);
        }
        den += __shfl_xor_sync(~0u, den, 8);
        den += __shfl_xor_sync(~0u, den, 16);
        float rden = 1.f / den;
        for (int c = le; c < deg; c += 4) {
            int e = g_eid[s0 + c];
            float w = __expf(__ldg(g_logits + (size_t)e * 8 + lh) - mx) * rden;
            g_logits[(size_t)e * 8 + lh] = w;     // this edge belongs only to this warp
        }
        __syncwarp();

        // --- phase 2: streaming accumulation, no barriers ---
        float acc[8][5];
        #pragma unroll
        for (int hh = 0; hh < 8; hh++)
            #pragma unroll
            for (int q = 0; q < 5; q++) acc[hh][q] = 0.f;

        for (int i = 0; i < deg; i++) {
            int e = g_eid[s0 + i];
            float4 wlo = __ldg((const float4*)(g_logits + (size_t)e * 8));
            float4 whi = __ldg((const float4*)(g_logits + (size_t)e * 8 + 4));
            float v[5];
            #pragma unroll
            for (int q = 0; q < 5; q++)
                v[q] = __ldg(g_m + (size_t)e * 160 + lane + 32 * q);
            #pragma unroll
            for (int q = 0; q < 5; q++) {
                acc[0][q] += v[q] * wlo.x; acc[1][q] += v[q] * wlo.y;
                acc[2][q] += v[q] * wlo.z; acc[3][q] += v[q] * wlo.w;
                acc[4][q] += v[q] * whi.x; acc[5][q] += v[q] * whi.y;
                acc[6][q] += v[q] * whi.z; acc[7][q] += v[q] * whi.w;
            }
        }
        #pragma unroll
        for (int hh = 0; hh < 8; hh++)
            #pragma unroll
            for (int q = 0; q < 5; q++)
                sS[warp][hh][lane + 32 * q] = acc[hh][q];

        // --- coordinate scatter-sum (lanes 0..2) ---
        if (lane < 3) {
            float cacc = 0.f;
            for (int i = 0; i < deg; i++)
                cacc += __ldg(g_msgx + (size_t)g_eid[s0 + i] * 3 + lane);
            out_coords[n * 3 + lane] = coords[n * 3 + lane] + cacc;
        }
    }
    __syncthreads();

    // --- batched Wv epilogue: h_agg[n][j] = sum_k sS[n][j>>4][k] * Wv[k][j] ---
    {
        const int j = tid & 127, grp = tid >> 7;     // grp 0..1, 4 nodes each
        const int head = j >> 4;
        #pragma unroll
        for (int r = 0; r < 4; r++) {
            int wn = grp * 4 + r;
            int n2 = nb + wn;
            if (n2 < N) {
                const float* sr = sS[wn][head];
                float hv = 0.f;
                #pragma unroll 8
                for (int k = 0; k < INNER; k++) hv += sr[k] * __ldg(Wv + k * 128 + j);
                g_hagg[(size_t)n2 * 128 + j] = hv;
            }
        }
    }
}

// ---------------- batched node GEMM helpers ----------------
template<int K, int NP, int C>
__device__ __forceinline__ void gemm_n(const float* __restrict__ sIn, int is,
                                       const float* __restrict__ W,
                                       ull (&acc)[4][NP][2]) {
    const int tid = threadIdx.x;
    const int ecg = tid >> 5, jcg = tid & 31;
    #pragma unroll
    for (int i = 0; i < 4; i++)
        #pragma unroll
        for (int p = 0; p < NP; p++) { acc[i][p][0] = 0; acc[i][p][1] = 0; }
    for (int k4 = 0; k4 < K; k4 += 4) {
        float4 av[4];
        #pragma unroll
        for (int i = 0; i < 4; i++) av[i] = *(const float4*)(sIn + (ecg + 8 * i) * is + k4);
        #pragma unroll
        for (int kk = 0; kk < 4; kk++) {
            ull fa[4];
            #pragma unroll
            for (int i = 0; i < 4; i++) { float c = getc(av[i], kk); fa[i] = pk2(c, c); }
            const float* wr = W + (k4 + kk) * C + 4 * jcg;
            #pragma unroll
            for (int p = 0; p < NP; p++) {
                if ((C % 128 == 0) || (128 * p + 4 * jcg < C)) {
                    ulonglong2 wv = __ldg((const ulonglong2*)(wr + 128 * p));
                    #pragma unroll
                    for (int i = 0; i < 4; i++) { ffma2(acc[i][p][0], fa[i], wv.x); ffma2(acc[i][p][1], fa[i], wv.y); }
                }
            }
        }
    }
}

template<int NP, int C>
__device__ __forceinline__ void store_acc(ull (&acc)[4][NP][2], float* sOut, int os,
                                          const float* bias, bool dosilu) {
    const int tid = threadIdx.x, ecg = tid >> 5, jcg = tid & 31;
    #pragma unroll
    for (int i = 0; i < 4; i++) {
        int r = ecg + 8 * i;
        #pragma unroll
        for (int p = 0; p < NP; p++) {
            int c0 = 128 * p + 4 * jcg;
            if ((C % 128 == 0) || (c0 < C)) {
                float v0, v1, v2, v3;
                upk2(acc[i][p][0], v0, v1); upk2(acc[i][p][1], v2, v3);
                if (bias) {
                    v0 += __ldg(bias + c0); v1 += __ldg(bias + c0 + 1);
                    v2 += __ldg(bias + c0 + 2); v3 += __ldg(bias + c0 + 3);
                }
                if (dosilu) { v0 = siluf(v0); v1 = siluf(v1); v2 = siluf(v2); v3 = siluf(v3); }
                *(float4*)(sOut + r * os + c0) = make_float4(v0, v1, v2, v3);
            }
        }
    }
}

__device__ __forceinline__ void film_store(ull (&acc)[4][2][2], float* sScale, float* sShift,
                                           const float* bias) {
    const int tid = threadIdx.x, ecg = tid >> 5, jcg = tid & 31;
    #pragma unroll
    for (int i = 0; i < 4; i++) {
        int r = ecg + 8 * i;
        int c0 = 4 * jcg;
        float v0, v1, v2, v3;
        upk2(acc[i][0][0], v0, v1); upk2(acc[i][0][1], v2, v3);
        v0 += __ldg(bias + c0); v1 += __ldg(bias + c0 + 1);
        v2 += __ldg(bias + c0 + 2); v3 += __ldg(bias + c0 + 3);
        *(float4*)(sScale + r * 132 + c0) = make_float4(v0, v1, v2, v3);
        upk2(acc[i][1][0], v0, v1); upk2(acc[i][1][1], v2, v3);
        v0 += __ldg(bias + 128 + c0); v1 += __ldg(bias + 128 + c0 + 1);
        v2 += __ldg(bias + 128 + c0 + 2); v3 += __ldg(bias + 128 + c0 + 3);
        *(float4*)(sShift + r * 164 + c0) = make_float4(v0, v1, v2, v3);
    }
}

__device__ __forceinline__ void ln_stats(const float* sX, float* sMu, float* sRs) {
    int w = threadIdx.x >> 5, lane = threadIdx.x & 31;
    #pragma unroll
    for (int rr = 0; rr < 4; rr++) {
        int r = w * 4 + rr;
        float4 v = *(const float4*)(sX + r * 132 + 4 * lane);
        float s = v.x + v.y + v.z + v.w;
        float q = v.x * v.x + v.y * v.y + v.z * v.z + v.w * v.w;
        #pragma unroll
        for (int o = 16; o; o >>= 1) {
            s += __shfl_xor_sync(~0u, s, o);
            q += __shfl_xor_sync(~0u, q, o);
        }
        if (lane == 0) {
            float mu = s * (1.f / 128.f);
            float var = q * (1.f / 128.f) - mu * mu;
            sMu[r] = mu; sRs[r] = rsqrtf(var + 1e-5f);
        }
    }
}

// ---------------- batched node kernel (32 nodes/block) ----------------
__global__ void __launch_bounds__(256, 2) k_node(
    const float* __restrict__ h, const float* __restrict__ res, const float* __restrict__ y,
    const float* __restrict__ Wo,
    const float* __restrict__ Wn1, const float* __restrict__ bn1,
    const float* __restrict__ Wn2, const float* __restrict__ bn2,
    const float* __restrict__ Wf1, const float* __restrict__ bf1,
    const float* __restrict__ Wf2, const float* __restrict__ bf2,
    float* __restrict__ out_h2, float* __restrict__ out_res2, int N)
{
    extern __shared__ float sm_n[];
    float* sA  = sm_n;                 // [32][164]
    float* sB  = sA + 32 * 164;        // [32][132]
    float* sC  = sB + 32 * 132;        // [32][132]
    float* sY  = sC + 32 * 132;        // [32][68]
    float* sMu = sY + 32 * 68;         // [32]
    float* sRs = sMu + 32;             // [32]

    const int nb = blockIdx.x * NB;
    const int tid = threadIdx.x;

    for (int idx = tid; idx < 32 * 128; idx += 256) {
        int r = idx >> 7, c = idx & 127;
        int n = min(nb + r, N - 1);
        sB[r * 132 + c] = g_hagg[(size_t)n * 128 + c];
    }
    for (int idx = tid; idx < 32 * 64; idx += 256) {
        int r = idx >> 6, c = idx & 63;
        int n = min(nb + r, N - 1);
        sY[r * 68 + c] = y[(size_t)n * 64 + c];
    }
    __syncthreads();

    {
        ull acc[4][1][2];
        gemm_n<128, 1, 128>(sB, 132, Wo, acc);
        store_acc<1, 128>(acc, sC, 132, nullptr, false);
    }
    __syncthreads();

    float f2r[16];
    #pragma unroll
    for (int t = 0; t < 16; t++) {
        int idx = tid + 256 * t;
        int r = idx >> 7, c = idx & 127;
        int n = min(nb + r, N - 1);
        float f2v = sC[r * 132 + c];
        f2r[t] = f2v;
        sB[r * 132 + c] = h[(size_t)n * 128 + c] + f2v;
    }
    __syncthreads();
    ln_stats(sB, sMu, sRs);
    __syncthreads();

    {
        ull acc[4][2][2];
        gemm_n<64, 2, 256>(sY, 68, Wf1, acc);
        film_store(acc, sC, sA, bf1);
    }
    __syncthreads();

    #pragma unroll
    for (int t = 0; t < 16; t++) {
        int idx = tid + 256 * t;
        int r = idx >> 7, c = idx & 127;
        float x = sB[r * 132 + c];
        float xn = (x - sMu[r]) * sRs[r];
        sB[r * 132 + c] = xn * (1.f + sC[r * 132 + c]) + sA[r * 164 + c];
    }
    __syncthreads();

    {
        ull acc[4][2][2];
        gemm_n<128, 2, 160>(sB, 132, Wn1, acc);
        store_acc<2, 160>(acc, sA, 164, bn1, true);
    }
    __syncthreads();

    {
        ull acc[4][1][2];
        gemm_n<160, 1, 128>(sA, 164, Wn2, acc);
        store_acc<1, 128>(acc, sC, 132, bn2, false);
    }
    __syncthreads();

    #pragma unroll
    for (int t = 0; t < 16; t++) {
        int idx = tid + 256 * t;
        int r = idx >> 7, c = idx & 127;
        float f3 = sC[r * 132 + c];
        int n = nb + r;
        if (n < N) out_res2[(size_t)n * 128 + c] = res[(size_t)n * 128 + c] + f2r[t] + f3;
        sB[r * 132 + c] += f3;
    }
    __syncthreads();
    ln_stats(sB, sMu, sRs);
    __syncthreads();

    {
        ull acc[4][2][2];
        gemm_n<64, 2, 256>(sY, 68, Wf2, acc);
        film_store(acc, sC, sA, bf2);
    }
    __syncthreads();

    #pragma unroll
    for (int t = 0; t < 16; t++) {
        int idx = tid + 256 * t;
        int r = idx >> 7, c = idx & 127;
        int n = nb + r;
        if (n < N) {
            float xn = (sB[r * 132 + c] - sMu[r]) * sRs[r];
            out_h2[(size_t)n * 128 + c] = xn * (1.f + sC[r * 132 + c]) + sA[r * 164 + c];
        }
    }
}

// ---------------- launch ----------------
extern "C" void kernel_launch(void* const* d_in, const int* in_sizes, int n_in,
                              void* d_out, int out_size) {
    const float* h      = (const float*)d_in[0];
    const float* coords = (const float*)d_in[1];
    const float* a      = (const float*)d_in[2];
    const float* y      = (const float*)d_in[3];
    const float* res    = (const float*)d_in[4];
    const int*   src    = (const int*)d_in[5];
    const int*   dst    = (const int*)d_in[6];
    const float* We1 = (const float*)d_in[7];
    const float* be1 = (const float*)d_in[8];
    const float* We2 = (const float*)d_in[9];
    const float* be2 = (const float*)d_in[10];
    const float* Wc  = (const float*)d_in[11];
    const float* Wv  = (const float*)d_in[12];
    const float* Wa  = (const float*)d_in[13];
    const float* Wo  = (const float*)d_in[14];
    const float* Wn1 = (const float*)d_in[15];
    const float* bn1 = (const float*)d_in[16];
    const float* Wn2 = (const float*)d_in[17];
    const float* bn2 = (const float*)d_in[18];
    const float* Wf1 = (const float*)d_in[19];
    const float* bf1 = (const float*)d_in[20];
    const float* Wf2 = (const float*)d_in[21];
    const float* bf2 = (const float*)d_in[22];

    const int N = in_sizes[0] / HID;
    const int E = in_sizes[5];

    float* out = (float*)d_out;
    float* out_h2 = out;
    float* out_coords = out + (size_t)N * HID;
    float* out_res2 = out + (size_t)N * HID + (size_t)N * 3;

    const int SMEM_E = (64 * 164 + 2 * 2720 + 64 * 16 + 64 * 6) * (int)sizeof(float);
    const int SMEM_N = (32 * 164 + 32 * 132 * 2 + 32 * 68 + 64) * (int)sizeof(float);
    cudaFuncSetAttribute(k_edge, cudaFuncAttributeMaxDynamicSharedMemorySize, SMEM_E);
    cudaFuncSetAttribute(k_node, cudaFuncAttributeMaxDynamicSharedMemorySize, SMEM_N);

    k_zero<<<(N + 255) / 256, 256>>>(N);
    k_deg<<<(E + 255) / 256, 256>>>(dst, E);
    k_pre<<<(N + 31) / 32, 256>>>(h, We1, N);
    // k_edge 4th: the ncu window captures launch #4
    k_edge<<<(E + EB - 1) / EB, 256, SMEM_E>>>(coords, a, src, dst,
                                               We1, be1, We2, be2, Wc, Wa, E);
    k_scan<<<1, 1024>>>(N);
    k_fill<<<(E + 255) / 256, 256>>>(dst, E);
    k_agg<<<(N + 7) / 8, 256>>>(coords, Wv, out_coords, N);
    k_node<<<(N + NB - 1) / NB, 256, SMEM_N>>>(h, res, y, Wo, Wn1, bn1, Wn2, bn2,
                                               Wf1, bf1, Wf2, bf2, out_h2, out_res2, N);
}

// round 12
// speedup vs baseline: 1.4744x; 1.0951x over previous
#include <cuda_runtime.h>
#include <math.h>

#define NMAX 25000
#define EMAX 400000
#define HID 128
#define INNER 160
#define EB 64      // edges per block
#define NB 32      // nodes per block (k_node)

// ---------------- scratch ----------------
__device__ float g_m[(size_t)EMAX * 160];      // per-edge message m
__device__ float g_logits[(size_t)EMAX * 8];   // logits, later overwritten with softmax weights
__device__ float g_msgx[(size_t)EMAX * 3];
__device__ float g_hagg[(size_t)NMAX * 128];
__device__ float g_P[(size_t)NMAX * 320];      // precomputed h@We1 (src half | dst half)
__device__ int g_deg[NMAX];
__device__ int g_cursor[NMAX];
__device__ int g_start[NMAX + 1];
__device__ int g_eid[EMAX];

// ---------------- helpers ----------------
typedef unsigned long long ull;
__device__ __forceinline__ ull pk2(float a, float b) {
    ull r;
    asm("mov.b64 %0, {%1, %2};" : "=l"(r) : "r"(__float_as_uint(a)), "r"(__float_as_uint(b)));
    return r;
}
__device__ __forceinline__ void upk2(ull v, float &a, float &b) {
    unsigned int lo, hi;
    asm("mov.b64 {%0, %1}, %2;" : "=r"(lo), "=r"(hi) : "l"(v));
    a = __uint_as_float(lo); b = __uint_as_float(hi);
}
__device__ __forceinline__ void ffma2(ull &d, ull a, ull b) {
    asm("fma.rn.f32x2 %0, %1, %2, %3;" : "=l"(d) : "l"(a), "l"(b), "l"(d));
}
__device__ __forceinline__ float siluf(float x) { return x / (1.0f + __expf(-x)); }
__device__ __forceinline__ float getc(const float4& v, int kk) {
    return kk == 0 ? v.x : kk == 1 ? v.y : kk == 2 ? v.z : v.w;
}
// round fp32 -> tf32 (rna), keep as fp32 bit pattern
__device__ __forceinline__ float tf32f(float x) {
    unsigned r;
    asm("cvt.rna.tf32.f32 %0, %1;" : "=r"(r) : "f"(x));
    return __uint_as_float(r);
}
__device__ __forceinline__ void mma_tf32(float* c, unsigned a0, unsigned a1,
                                         unsigned a2, unsigned a3,
                                         unsigned b0, unsigned b1) {
    asm volatile(
        "mma.sync.aligned.m16n8k8.row.col.f32.tf32.tf32.f32 "
        "{%0,%1,%2,%3}, {%4,%5,%6,%7}, {%8,%9}, {%0,%1,%2,%3};"
        : "+f"(c[0]), "+f"(c[1]), "+f"(c[2]), "+f"(c[3])
        : "r"(a0), "r"(a1), "r"(a2), "r"(a3), "r"(b0), "r"(b1));
}

// ---------------- CSR build ----------------
__global__ void k_zero(int n) {
    int i = blockIdx.x * blockDim.x + threadIdx.x;
    if (i < n) { g_deg[i] = 0; g_cursor[i] = 0; }
}
__global__ void k_deg(const int* __restrict__ dst, int E) {
    int e = blockIdx.x * blockDim.x + threadIdx.x;
    if (e < E) atomicAdd(&g_deg[dst[e]], 1);
}
__global__ void k_scan(int n) {
    __shared__ int sh[1024];
    int carry = 0;
    for (int base = 0; base < n; base += 1024) {
        int i = base + threadIdx.x;
        int x = (i < n) ? g_deg[i] : 0;
        sh[threadIdx.x] = x;
        __syncthreads();
        for (int off = 1; off < 1024; off <<= 1) {
            int v = (threadIdx.x >= off) ? sh[threadIdx.x - off] : 0;
            __syncthreads();
            sh[threadIdx.x] += v;
            __syncthreads();
        }
        if (i < n) g_start[i] = carry + sh[threadIdx.x] - x;
        carry += sh[1023];
        __syncthreads();
    }
    if (threadIdx.x == 0) g_start[n] = carry;
}
__global__ void k_fill(const int* __restrict__ dst, int E) {
    int e = blockIdx.x * blockDim.x + threadIdx.x;
    if (e < E) {
        int d = dst[e];
        int p = atomicAdd(&g_cursor[d], 1);
        g_eid[g_start[d] + p] = e;
    }
}

// ---------------- precompute P[n] = [h@We1[0:128] | h@We1[128:256]] ----------------
__global__ void __launch_bounds__(256) k_pre(const float* __restrict__ h,
                                             const float* __restrict__ We1, int N)
{
    __shared__ float sH[32][132];
    const int nb = blockIdx.x * 32;
    const int tid = threadIdx.x;
    for (int idx = tid; idx < 32 * 128; idx += 256) {
        int r = idx >> 7, c = idx & 127;
        int n = min(nb + r, N - 1);
        sH[r][c] = h[(size_t)n * 128 + c];
    }
    __syncthreads();

    const int ecg = tid >> 5, jcg = tid & 31;
    ull accA[4][3], accB[4][3];
    #pragma unroll
    for (int i = 0; i < 4; i++)
        #pragma unroll
        for (int p = 0; p < 3; p++) { accA[i][p] = 0; accB[i][p] = 0; }

    for (int k = 0; k < 128; k++) {
        ull fa[4];
        #pragma unroll
        for (int i = 0; i < 4; i++) { float c = sH[ecg + 8 * i][k]; fa[i] = pk2(c, c); }
        const float* w1 = We1 + (size_t)k * INNER;
        const float* w2 = We1 + (size_t)(128 + k) * INNER;
        ulonglong2 WA = __ldg((const ulonglong2*)(w1 + 4 * jcg));
        ulonglong2 WB = __ldg((const ulonglong2*)(w2 + 4 * jcg));
        ull A2 = 0, B2 = 0;
        if (jcg < 16) {
            A2 = __ldg((const ull*)(w1 + 128 + 2 * jcg));
            B2 = __ldg((const ull*)(w2 + 128 + 2 * jcg));
        }
        #pragma unroll
        for (int i = 0; i < 4; i++) {
            ffma2(accA[i][0], fa[i], WA.x); ffma2(accA[i][1], fa[i], WA.y);
            ffma2(accB[i][0], fa[i], WB.x); ffma2(accB[i][1], fa[i], WB.y);
            if (jcg < 16) { ffma2(accA[i][2], fa[i], A2); ffma2(accB[i][2], fa[i], B2); }
        }
    }
    #pragma unroll
    for (int i = 0; i < 4; i++) {
        int n = nb + ecg + 8 * i;
        if (n < N) {
            float* out = g_P + (size_t)n * 320;
            float x0, x1, x2, x3;
            upk2(accA[i][0], x0, x1); upk2(accA[i][1], x2, x3);
            *(float4*)(out + 4 * jcg) = make_float4(x0, x1, x2, x3);
            upk2(accB[i][0], x0, x1); upk2(accB[i][1], x2, x3);
            *(float4*)(out + 160 + 4 * jcg) = make_float4(x0, x1, x2, x3);
            if (jcg < 16) {
                upk2(accA[i][2], x0, x1);
                *(float2*)(out + 128 + 2 * jcg) = make_float2(x0, x1);
                upk2(accB[i][2], x0, x1);
                *(float2*)(out + 288 + 2 * jcg) = make_float2(x0, x1);
            }
        }
    }
}

// chunk loader: 16 rows x 160 cols of W -> tf32-rounded, stride-168 smem buffer
__device__ __forceinline__ void load_w_chunk_tf32(float* dstbuf, const float* __restrict__ W,
                                                  int k0, int tid) {
    #pragma unroll
    for (int i = 0; i < 3; i++) {
        int idx = tid + 256 * i;
        if (i < 2 || idx < 640) {
            int r = idx / 40, c4 = idx % 40;
            float4 v = __ldg((const float4*)(W + (size_t)(k0 + r) * 160 + 4 * c4));
            v.x = tf32f(v.x); v.y = tf32f(v.y); v.z = tf32f(v.z); v.w = tf32f(v.w);
            *(float4*)(dstbuf + r * 168 + 4 * c4) = v;
        }
    }
}

// ---------------- fused edge kernel (GEMM2 + tails on tf32 tensor cores) ----------------
__global__ void __launch_bounds__(256, 3) k_edge(
    const float* __restrict__ coords, const float* __restrict__ a,
    const int* __restrict__ src, const int* __restrict__ dst,
    const float* __restrict__ We1, const float* __restrict__ be1,
    const float* __restrict__ We2, const float* __restrict__ be2,
    const float* __restrict__ Wc, const float* __restrict__ Wa,
    int E)
{
    extern __shared__ float sm_e[];
    float* sm1  = sm_e;               // [64][164]
    float* sWA  = sm1 + 64 * 164;     // weight buffer A (2720 floats)
    float* sWB  = sWA + 2720;         // weight buffer B (2720 floats; GEMM2 stride 168, W9 stride 16)
    float* sA   = sWB + 2720;         // [64][16]
    float* sRad = sA + 64 * 16;       // [64]
    float* sDx  = sRad + 64;          // [64]
    float* sDy  = sDx + 64;
    float* sDz  = sDy + 64;
    int*   sSrc = (int*)(sDz + 64);   // [64]
    int*   sDst = sSrc + 64;          // [64]

    const int tid = threadIdx.x;
    const int eg = blockIdx.x * EB;
    const int warp = tid >> 5, lane = tid & 31;

    // ---- stage 0: gather edge extras + We1 tail into A (stride 160) + We2 chunk0 into B ----
    for (int e = warp; e < EB; e += 8) {
        int ed = eg + e; if (ed > E - 1) ed = E - 1;
        if (lane < 16) sA[e * 16 + lane] = __ldg(a + (size_t)ed * 16 + lane);
        if (lane == 0) {
            int si = src[ed], di = dst[ed];
            sSrc[e] = si; sDst[e] = di;
            float dx = coords[si * 3 + 0] - coords[di * 3 + 0];
            float dy = coords[si * 3 + 1] - coords[di * 3 + 1];
            float dz = coords[si * 3 + 2] - coords[di * 3 + 2];
            sRad[e] = dx * dx + dy * dy + dz * dz;
            sDx[e] = dx; sDy[e] = dy; sDz[e] = dz;
        }
    }
    // We1 rows 256..272 (17 x 160)
    #pragma unroll
    for (int i = 0; i < 3; i++) {
        int idx = tid + 256 * i;
        if (i < 2 || idx < 680) {
            int r = idx / 40, c4 = idx % 40;
            *(float4*)(sWA + r * 160 + 4 * c4) =
                __ldg((const float4*)(We1 + (size_t)(256 + r) * 160 + 4 * c4));
        }
    }
    load_w_chunk_tf32(sWB, We2, 0, tid);
    __syncthreads();

    const int ecg = tid >> 4;   // rows ecg + 16*i
    const int jcg = tid & 15;   // cols 4jcg..+3, 64+4jcg..+3, 128+2jcg,+1

    // ---- GEMM1-lite: m1 = silu(P1[src] + P2[dst] + [rad,a]@We1[256:273] + be1) ----
    // m1 is stored TF32-ROUNDED (only consumer is the tf32 GEMM2)
    {
        ull acc[4][5];
        #pragma unroll
        for (int i = 0; i < 4; i++) {
            int r = ecg + 16 * i;
            const float* Ps = g_P + (size_t)sSrc[r] * 320;
            const float* Pd = g_P + (size_t)sDst[r] * 320 + 160;
            float4 a0 = __ldg((const float4*)(Ps + 4 * jcg));
            float4 b0 = __ldg((const float4*)(Pd + 4 * jcg));
            acc[i][0] = pk2(a0.x + b0.x, a0.y + b0.y);
            acc[i][1] = pk2(a0.z + b0.z, a0.w + b0.w);
            float4 a1 = __ldg((const float4*)(Ps + 64 + 4 * jcg));
            float4 b1 = __ldg((const float4*)(Pd + 64 + 4 * jcg));
            acc[i][2] = pk2(a1.x + b1.x, a1.y + b1.y);
            acc[i][3] = pk2(a1.z + b1.z, a1.w + b1.w);
            float2 a2 = __ldg((const float2*)(Ps + 128 + 2 * jcg));
            float2 b2 = __ldg((const float2*)(Pd + 128 + 2 * jcg));
            acc[i][4] = pk2(a2.x + b2.x, a2.y + b2.y);
        }
        #pragma unroll 4
        for (int k = 0; k < 17; k++) {
            const float* wr = sWA + k * 160;
            ulonglong2 W0 = *(const ulonglong2*)(wr + 4 * jcg);
            ulonglong2 W1 = *(const ulonglong2*)(wr + 64 + 4 * jcg);
            ull W2 = *(const ull*)(wr + 128 + 2 * jcg);
            #pragma unroll
            for (int i = 0; i < 4; i++) {
                int r = ecg + 16 * i;
                float c = (k == 0) ? sRad[r] : sA[r * 16 + (k - 1)];
                ull fa = pk2(c, c);
                ffma2(acc[i][0], fa, W0.x); ffma2(acc[i][1], fa, W0.y);
                ffma2(acc[i][2], fa, W1.x); ffma2(acc[i][3], fa, W1.y);
                ffma2(acc[i][4], fa, W2);
            }
        }
        #pragma unroll
        for (int i = 0; i < 4; i++) {
            float* orow = sm1 + (ecg + 16 * i) * 164;
            float lo, hi;
            int c = 4 * jcg;
            upk2(acc[i][0], lo, hi);
            orow[c]   = tf32f(siluf(lo + __ldg(be1 + c)));
            orow[c+1] = tf32f(siluf(hi + __ldg(be1 + c + 1)));
            upk2(acc[i][1], lo, hi);
            orow[c+2] = tf32f(siluf(lo + __ldg(be1 + c + 2)));
            orow[c+3] = tf32f(siluf(hi + __ldg(be1 + c + 3)));
            c = 64 + 4 * jcg;
            upk2(acc[i][2], lo, hi);
            orow[c]   = tf32f(siluf(lo + __ldg(be1 + c)));
            orow[c+1] = tf32f(siluf(hi + __ldg(be1 + c + 1)));
            upk2(acc[i][3], lo, hi);
            orow[c+2] = tf32f(siluf(lo + __ldg(be1 + c + 2)));
            orow[c+3] = tf32f(siluf(hi + __ldg(be1 + c + 3)));
            c = 128 + 2 * jcg;
            upk2(acc[i][4], lo, hi);
            orow[c]   = tf32f(siluf(lo + __ldg(be1 + c)));
            orow[c+1] = tf32f(siluf(hi + __ldg(be1 + c + 1)));
        }
    }
    __syncthreads();

    // ---- GEMM2 via tf32 mma.sync: m = silu(m1 @ We2 + be2), in-place into sm1 ----
    {
        const int gid = lane >> 2, tig = lane & 3;
        const int mr  = (warp & 3) * 16;       // M-tile rows mr..mr+15
        const int nb0 = (warp >> 2) * 80;      // N half: 80 cols, 10 subtiles of 8
        float c[10][4];
        #pragma unroll
        for (int ns = 0; ns < 10; ns++)
            #pragma unroll
            for (int q = 0; q < 4; q++) c[ns][q] = 0.f;

        for (int ch = 0; ch < 10; ch++) {
            const float* wbuf = (ch & 1) ? sWA : sWB;     // stride 168
            if (ch < 9) {
                load_w_chunk_tf32((ch & 1) ? sWB : sWA, We2, 16 * (ch + 1), tid);
            } else {
                // ch==9 computes from sWA; sWB is free -> stage W9 = [Wa | Wc | 0] (160x16, stride 16)
                #pragma unroll
                for (int i = 0; i < 3; i++) {
                    int idx = tid + 256 * i;
                    if (idx < 640) {
                        int k = idx >> 2, c4 = idx & 3;
                        float4 v;
                        if (c4 < 2) {
                            float4 wa = __ldg((const float4*)(Wa + k * 8 + 4 * c4));
                            v = make_float4(tf32f(wa.x), tf32f(wa.y), tf32f(wa.z), tf32f(wa.w));
                        } else if (c4 == 2) {
                            v = make_float4(tf32f(__ldg(Wc + k)), 0.f, 0.f, 0.f);
                        } else {
                            v = make_float4(0.f, 0.f, 0.f, 0.f);
                        }
                        *(float4*)(sWB + k * 16 + 4 * c4) = v;
                    }
                }
            }
            #pragma unroll
            for (int ks = 0; ks < 2; ks++) {
                const float* ar = sm1 + (mr + gid) * 164 + ch * 16 + ks * 8;
                unsigned a0 = __float_as_uint(ar[tig]);
                unsigned a1 = __float_as_uint(ar[8 * 164 + tig]);
                unsigned a2 = __float_as_uint(ar[tig + 4]);
                unsigned a3 = __float_as_uint(ar[8 * 164 + tig + 4]);
                const float* br  = wbuf + (ks * 8 + tig) * 168 + nb0 + gid;
                const float* br2 = wbuf + (ks * 8 + tig + 4) * 168 + nb0 + gid;
                #pragma unroll
                for (int ns = 0; ns < 10; ns++) {
                    unsigned b0 = __float_as_uint(br[ns * 8]);
                    unsigned b1 = __float_as_uint(br2[ns * 8]);
                    mma_tf32(c[ns], a0, a1, a2, a3, b0, b1);
                }
            }
            __syncthreads();   // compute of ch done by all; prefetch of ch+1 / W9 visible
        }
        // epilogue: bias + silu, in-place store (all m1 reads drained by last sync)
        #pragma unroll
        for (int ns = 0; ns < 10; ns++) {
            int col = nb0 + ns * 8 + tig * 2;
            float b0v = __ldg(be2 + col), b1v = __ldg(be2 + col + 1);
            float* r0 = sm1 + (mr + gid) * 164 + col;
            float* r1 = sm1 + (mr + gid + 8) * 164 + col;
            r0[0] = siluf(c[ns][0] + b0v); r0[1] = siluf(c[ns][1] + b1v);
            r1[0] = siluf(c[ns][2] + b0v); r1[1] = siluf(c[ns][3] + b1v);
        }
    }
    __syncthreads();

    // ---- tails: warps 0-3 compute logits+coord via mma; warps 4-7 stream m to global ----
    if (warp < 4) {
        const int gid = lane >> 2, tig = lane & 3;
        const int mr = warp * 16;
        float c0[4] = {0.f, 0.f, 0.f, 0.f};   // cols 0-7  (logits)
        float c1[4] = {0.f, 0.f, 0.f, 0.f};   // cols 8-15 (col 8 = Wc)
        #pragma unroll
        for (int k0 = 0; k0 < INNER; k0 += 8) {
            const float* ar = sm1 + (mr + gid) * 164 + k0;
            unsigned a0 = __float_as_uint(tf32f(ar[tig]));
            unsigned a1 = __float_as_uint(tf32f(ar[8 * 164 + tig]));
            unsigned a2 = __float_as_uint(tf32f(ar[tig + 4]));
            unsigned a3 = __float_as_uint(tf32f(ar[8 * 164 + tig + 4]));
            const float* br  = sWB + (k0 + tig) * 16;
            const float* br2 = sWB + (k0 + tig + 4) * 16;
            unsigned b00 = __float_as_uint(br[gid]);
            unsigned b01 = __float_as_uint(br2[gid]);
            unsigned b10 = __float_as_uint(br[8 + gid]);
            unsigned b11 = __float_as_uint(br2[8 + gid]);
            mma_tf32(c0, a0, a1, a2, a3, b00, b01);
            mma_tf32(c1, a0, a1, a2, a3, b10, b11);
        }
        int e0 = mr + gid, e1 = mr + gid + 8;
        int ed0 = eg + e0, ed1 = eg + e1;
        if (ed0 < E)
            *(float2*)(g_logits + (size_t)ed0 * 8 + 2 * tig) = make_float2(c0[0], c0[1]);
        if (ed1 < E)
            *(float2*)(g_logits + (size_t)ed1 * 8 + 2 * tig) = make_float2(c0[2], c0[3]);
        if (tig == 0) {
            if (ed0 < E) {
                float s = c1[0] / (sqrtf(sRad[e0] + 1e-5f) + 1.0f);
                g_msgx[(size_t)ed0 * 3 + 0] = sDx[e0] * s;
                g_msgx[(size_t)ed0 * 3 + 1] = sDy[e0] * s;
                g_msgx[(size_t)ed0 * 3 + 2] = sDz[e0] * s;
            }
            if (ed1 < E) {
                float s = c1[2] / (sqrtf(sRad[e1] + 1e-5f) + 1.0f);
                g_msgx[(size_t)ed1 * 3 + 0] = sDx[e1] * s;
                g_msgx[(size_t)ed1 * 3 + 1] = sDy[e1] * s;
                g_msgx[(size_t)ed1 * 3 + 2] = sDz[e1] * s;
            }
        }
    } else {
        for (int idx = tid - 128; idx < 64 * 40; idx += 128) {
            int r = idx / 40, c4 = idx % 40;
            int ed = eg + r;
            if (ed < E)
                *(float4*)(g_m + (size_t)ed * 160 + 4 * c4) = *(const float4*)(sm1 + r * 164 + 4 * c4);
        }
    }
}

// ---------------- warp-per-node aggregation: in-place weights, streaming loop ----------------
__global__ void __launch_bounds__(256) k_agg(const float* __restrict__ coords,
                                             const float* __restrict__ Wv,
                                             float* __restrict__ out_coords, int N)
{
    __shared__ float sS[8][8][164];   // node, head, k
    const int tid = threadIdx.x;
    const int warp = tid >> 5, lane = tid & 31;
    const int nb = blockIdx.x * 8;
    const int n = nb + warp;
    const int le = lane >> 3, lh = lane & 7;

    if (n < N) {
        const int s0 = g_start[n];
        const int deg = g_start[n + 1] - s0;

        // --- phase 1: softmax stats, then overwrite g_logits with normalized weights ---
        float mx = -3.0e38f;
        for (int c = le; c < deg; c += 4) {
            int e = g_eid[s0 + c];
            mx = fmaxf(mx, __ldg(g_logits + (size_t)e * 8 + lh));
        }
        mx = fmaxf(mx, __shfl_xor_sync(~0u, mx, 8));
        mx = fmaxf(mx, __shfl_xor_sync(~0u, mx, 16));
        float den = 0.f;
        for (int c = le; c < deg; c += 4) {
            int e = g_eid[s0 + c];
            den += __expf(__ldg(g_logits + (size_t)e * 8 + lh) - mx);
        }
        den += __shfl_xor_sync(~0u, den, 8);
        den += __shfl_xor_sync(~0u, den, 16);
        float rden = 1.f / den;
        for (int c = le; c < deg; c += 4) {
            int e = g_eid[s0 + c];
            float w = __expf(__ldg(g_logits + (size_t)e * 8 + lh) - mx) * rden;
            g_logits[(size_t)e * 8 + lh] = w;     // this edge belongs only to this warp
        }
        __syncwarp();

        // --- phase 2: streaming accumulation, no barriers ---
        float acc[8][5];
        #pragma unroll
        for (int hh = 0; hh < 8; hh++)
            #pragma unroll
            for (int q = 0; q < 5; q++) acc[hh][q] = 0.f;

        for (int i = 0; i < deg; i++) {
            int e = g_eid[s0 + i];
            float4 wlo = __ldg((const float4*)(g_logits + (size_t)e * 8));
            float4 whi = __ldg((const float4*)(g_logits + (size_t)e * 8 + 4));
            float v[5];
            #pragma unroll
            for (int q = 0; q < 5; q++)
                v[q] = __ldg(g_m + (size_t)e * 160 + lane + 32 * q);
            #pragma unroll
            for (int q = 0; q < 5; q++) {
                acc[0][q] += v[q] * wlo.x; acc[1][q] += v[q] * wlo.y;
                acc[2][q] += v[q] * wlo.z; acc[3][q] += v[q] * wlo.w;
                acc[4][q] += v[q] * whi.x; acc[5][q] += v[q] * whi.y;
                acc[6][q] += v[q] * whi.z; acc[7][q] += v[q] * whi.w;
            }
        }
        #pragma unroll
        for (int hh = 0; hh < 8; hh++)
            #pragma unroll
            for (int q = 0; q < 5; q++)
                sS[warp][hh][lane + 32 * q] = acc[hh][q];

        // --- coordinate scatter-sum (lanes 0..2) ---
        if (lane < 3) {
            float cacc = 0.f;
            for (int i = 0; i < deg; i++)
                cacc += __ldg(g_msgx + (size_t)g_eid[s0 + i] * 3 + lane);
            out_coords[n * 3 + lane] = coords[n * 3 + lane] + cacc;
        }
    }
    __syncthreads();

    // --- batched Wv epilogue: h_agg[n][j] = sum_k sS[n][j>>4][k] * Wv[k][j] ---
    {
        const int j = tid & 127, grp = tid >> 7;     // grp 0..1, 4 nodes each
        const int head = j >> 4;
        #pragma unroll
        for (int r = 0; r < 4; r++) {
            int wn = grp * 4 + r;
            int n2 = nb + wn;
            if (n2 < N) {
                const float* sr = sS[wn][head];
                float hv = 0.f;
                #pragma unroll 8
                for (int k = 0; k < INNER; k++) hv += sr[k] * __ldg(Wv + k * 128 + j);
                g_hagg[(size_t)n2 * 128 + j] = hv;
            }
        }
    }
}

// ---------------- batched node GEMM helpers ----------------
template<int K, int NP, int C>
__device__ __forceinline__ void gemm_n(const float* __restrict__ sIn, int is,
                                       const float* __restrict__ W,
                                       ull (&acc)[4][NP][2]) {
    const int tid = threadIdx.x;
    const int ecg = tid >> 5, jcg = tid & 31;
    #pragma unroll
    for (int i = 0; i < 4; i++)
        #pragma unroll
        for (int p = 0; p < NP; p++) { acc[i][p][0] = 0; acc[i][p][1] = 0; }
    for (int k4 = 0; k4 < K; k4 += 4) {
        float4 av[4];
        #pragma unroll
        for (int i = 0; i < 4; i++) av[i] = *(const float4*)(sIn + (ecg + 8 * i) * is + k4);
        #pragma unroll
        for (int kk = 0; kk < 4; kk++) {
            ull fa[4];
            #pragma unroll
            for (int i = 0; i < 4; i++) { float c = getc(av[i], kk); fa[i] = pk2(c, c); }
            const float* wr = W + (k4 + kk) * C + 4 * jcg;
            #pragma unroll
            for (int p = 0; p < NP; p++) {
                if ((C % 128 == 0) || (128 * p + 4 * jcg < C)) {
                    ulonglong2 wv = __ldg((const ulonglong2*)(wr + 128 * p));
                    #pragma unroll
                    for (int i = 0; i < 4; i++) { ffma2(acc[i][p][0], fa[i], wv.x); ffma2(acc[i][p][1], fa[i], wv.y); }
                }
            }
        }
    }
}

template<int NP, int C>
__device__ __forceinline__ void store_acc(ull (&acc)[4][NP][2], float* sOut, int os,
                                          const float* bias, bool dosilu) {
    const int tid = threadIdx.x, ecg = tid >> 5, jcg = tid & 31;
    #pragma unroll
    for (int i = 0; i < 4; i++) {
        int r = ecg + 8 * i;
        #pragma unroll
        for (int p = 0; p < NP; p++) {
            int c0 = 128 * p + 4 * jcg;
            if ((C % 128 == 0) || (c0 < C)) {
                float v0, v1, v2, v3;
                upk2(acc[i][p][0], v0, v1); upk2(acc[i][p][1], v2, v3);
                if (bias) {
                    v0 += __ldg(bias + c0); v1 += __ldg(bias + c0 + 1);
                    v2 += __ldg(bias + c0 + 2); v3 += __ldg(bias + c0 + 3);
                }
                if (dosilu) { v0 = siluf(v0); v1 = siluf(v1); v2 = siluf(v2); v3 = siluf(v3); }
                *(float4*)(sOut + r * os + c0) = make_float4(v0, v1, v2, v3);
            }
        }
    }
}

__device__ __forceinline__ void film_store(ull (&acc)[4][2][2], float* sScale, float* sShift,
                                           const float* bias) {
    const int tid = threadIdx.x, ecg = tid >> 5, jcg = tid & 31;
    #pragma unroll
    for (int i = 0; i < 4; i++) {
        int r = ecg + 8 * i;
        int c0 = 4 * jcg;
        float v0, v1, v2, v3;
        upk2(acc[i][0][0], v0, v1); upk2(acc[i][0][1], v2, v3);
        v0 += __ldg(bias + c0); v1 += __ldg(bias + c0 + 1);
        v2 += __ldg(bias + c0 + 2); v3 += __ldg(bias + c0 + 3);
        *(float4*)(sScale + r * 132 + c0) = make_float4(v0, v1, v2, v3);
        upk2(acc[i][1][0], v0, v1); upk2(acc[i][1][1], v2, v3);
        v0 += __ldg(bias + 128 + c0); v1 += __ldg(bias + 128 + c0 + 1);
        v2 += __ldg(bias + 128 + c0 + 2); v3 += __ldg(bias + 128 + c0 + 3);
        *(float4*)(sShift + r * 164 + c0) = make_float4(v0, v1, v2, v3);
    }
}

__device__ __forceinline__ void ln_stats(const float* sX, float* sMu, float* sRs) {
    int w = threadIdx.x >> 5, lane = threadIdx.x & 31;
    #pragma unroll
    for (int rr = 0; rr < 4; rr++) {
        int r = w * 4 + rr;
        float4 v = *(const float4*)(sX + r * 132 + 4 * lane);
        float s = v.x + v.y + v.z + v.w;
        float q = v.x * v.x + v.y * v.y + v.z * v.z + v.w * v.w;
        #pragma unroll
        for (int o = 16; o; o >>= 1) {
            s += __shfl_xor_sync(~0u, s, o);
            q += __shfl_xor_sync(~0u, q, o);
        }
        if (lane == 0) {
            float mu = s * (1.f / 128.f);
            float var = q * (1.f / 128.f) - mu * mu;
            sMu[r] = mu; sRs[r] = rsqrtf(var + 1e-5f);
        }
    }
}

// ---------------- batched node kernel (32 nodes/block) ----------------
__global__ void __launch_bounds__(256, 2) k_node(
    const float* __restrict__ h, const float* __restrict__ res, const float* __restrict__ y,
    const float* __restrict__ Wo,
    const float* __restrict__ Wn1, const float* __restrict__ bn1,
    const float* __restrict__ Wn2, const float* __restrict__ bn2,
    const float* __restrict__ Wf1, const float* __restrict__ bf1,
    const float* __restrict__ Wf2, const float* __restrict__ bf2,
    float* __restrict__ out_h2, float* __restrict__ out_res2, int N)
{
    extern __shared__ float sm_n[];
    float* sA  = sm_n;                 // [32][164]
    float* sB  = sA + 32 * 164;        // [32][132]
    float* sC  = sB + 32 * 132;        // [32][132]
    float* sY  = sC + 32 * 132;        // [32][68]
    float* sMu = sY + 32 * 68;         // [32]
    float* sRs = sMu + 32;             // [32]

    const int nb = blockIdx.x * NB;
    const int tid = threadIdx.x;

    for (int idx = tid; idx < 32 * 128; idx += 256) {
        int r = idx >> 7, c = idx & 127;
        int n = min(nb + r, N - 1);
        sB[r * 132 + c] = g_hagg[(size_t)n * 128 + c];
    }
    for (int idx = tid; idx < 32 * 64; idx += 256) {
        int r = idx >> 6, c = idx & 63;
        int n = min(nb + r, N - 1);
        sY[r * 68 + c] = y[(size_t)n * 64 + c];
    }
    __syncthreads();

    {
        ull acc[4][1][2];
        gemm_n<128, 1, 128>(sB, 132, Wo, acc);
        store_acc<1, 128>(acc, sC, 132, nullptr, false);
    }
    __syncthreads();

    float f2r[16];
    #pragma unroll
    for (int t = 0; t < 16; t++) {
        int idx = tid + 256 * t;
        int r = idx >> 7, c = idx & 127;
        int n = min(nb + r, N - 1);
        float f2v = sC[r * 132 + c];
        f2r[t] = f2v;
        sB[r * 132 + c] = h[(size_t)n * 128 + c] + f2v;
    }
    __syncthreads();
    ln_stats(sB, sMu, sRs);
    __syncthreads();

    {
        ull acc[4][2][2];
        gemm_n<64, 2, 256>(sY, 68, Wf1, acc);
        film_store(acc, sC, sA, bf1);
    }
    __syncthreads();

    #pragma unroll
    for (int t = 0; t < 16; t++) {
        int idx = tid + 256 * t;
        int r = idx >> 7, c = idx & 127;
        float x = sB[r * 132 + c];
        float xn = (x - sMu[r]) * sRs[r];
        sB[r * 132 + c] = xn * (1.f + sC[r * 132 + c]) + sA[r * 164 + c];
    }
    __syncthreads();

    {
        ull acc[4][2][2];
        gemm_n<128, 2, 160>(sB, 132, Wn1, acc);
        store_acc<2, 160>(acc, sA, 164, bn1, true);
    }
    __syncthreads();

    {
        ull acc[4][1][2];
        gemm_n<160, 1, 128>(sA, 164, Wn2, acc);
        store_acc<1, 128>(acc, sC, 132, bn2, false);
    }
    __syncthreads();

    #pragma unroll
    for (int t = 0; t < 16; t++) {
        int idx = tid + 256 * t;
        int r = idx >> 7, c = idx & 127;
        float f3 = sC[r * 132 + c];
        int n = nb + r;
        if (n < N) out_res2[(size_t)n * 128 + c] = res[(size_t)n * 128 + c] + f2r[t] + f3;
        sB[r * 132 + c] += f3;
    }
    __syncthreads();
    ln_stats(sB, sMu, sRs);
    __syncthreads();

    {
        ull acc[4][2][2];
        gemm_n<64, 2, 256>(sY, 68, Wf2, acc);
        film_store(acc, sC, sA, bf2);
    }
    __syncthreads();

    #pragma unroll
    for (int t = 0; t < 16; t++) {
        int idx = tid + 256 * t;
        int r = idx >> 7, c = idx & 127;
        int n = nb + r;
        if (n < N) {
            float xn = (sB[r * 132 + c] - sMu[r]) * sRs[r];
            out_h2[(size_t)n * 128 + c] = xn * (1.f + sC[r * 132 + c]) + sA[r * 164 + c];
        }
    }
}

// ---------------- launch ----------------
extern "C" void kernel_launch(void* const* d_in, const int* in_sizes, int n_in,
                              void* d_out, int out_size) {
    const float* h      = (const float*)d_in[0];
    const float* coords = (const float*)d_in[1];
    const float* a      = (const float*)d_in[2];
    const float* y      = (const float*)d_in[3];
    const float* res    = (const float*)d_in[4];
    const int*   src    = (const int*)d_in[5];
    const int*   dst    = (const int*)d_in[6];
    const float* We1 = (const float*)d_in[7];
    const float* be1 = (const float*)d_in[8];
    const float* We2 = (const float*)d_in[9];
    const float* be2 = (const float*)d_in[10];
    const float* Wc  = (const float*)d_in[11];
    const float* Wv  = (const float*)d_in[12];
    const float* Wa  = (const float*)d_in[13];
    const float* Wo  = (const float*)d_in[14];
    const float* Wn1 = (const float*)d_in[15];
    const float* bn1 = (const float*)d_in[16];
    const float* Wn2 = (const float*)d_in[17];
    const float* bn2 = (const float*)d_in[18];
    const float* Wf1 = (const float*)d_in[19];
    const float* bf1 = (const float*)d_in[20];
    const float* Wf2 = (const float*)d_in[21];
    const float* bf2 = (const float*)d_in[22];

    const int N = in_sizes[0] / HID;
    const int E = in_sizes[5];

    float* out = (float*)d_out;
    float* out_h2 = out;
    float* out_coords = out + (size_t)N * HID;
    float* out_res2 = out + (size_t)N * HID + (size_t)N * 3;

    const int SMEM_E = (64 * 164 + 2 * 2720 + 64 * 16 + 64 * 6) * (int)sizeof(float);
    const int SMEM_N = (32 * 164 + 32 * 132 * 2 + 32 * 68 + 64) * (int)sizeof(float);
    cudaFuncSetAttribute(k_edge, cudaFuncAttributeMaxDynamicSharedMemorySize, SMEM_E);
    cudaFuncSetAttribute(k_node, cudaFuncAttributeMaxDynamicSharedMemorySize, SMEM_N);

    k_zero<<<(N + 255) / 256, 256>>>(N);
    k_deg<<<(E + 255) / 256, 256>>>(dst, E);
    k_pre<<<(N + 31) / 32, 256>>>(h, We1, N);
    // k_edge 4th: the ncu window captures launch #4
    k_edge<<<(E + EB - 1) / EB, 256, SMEM_E>>>(coords, a, src, dst,
                                               We1, be1, We2, be2, Wc, Wa, E);
    k_scan<<<1, 1024>>>(N);
    k_fill<<<(E + 255) / 256, 256>>>(dst, E);
    k_agg<<<(N + 7) / 8, 256>>>(coords, Wv, out_coords, N);
    k_node<<<(N + NB - 1) / NB, 256, SMEM_N>>>(h, res, y, Wo, Wn1, bn1, Wn2, bn2,
                                               Wf1, bf1, Wf2, bf2, out_h2, out_res2, N);
}

// round 13
// speedup vs baseline: 1.6426x; 1.1140x over previous
#include <cuda_runtime.h>
#include <math.h>

#define NMAX 25000
#define EMAX 400000
#define HID 128
#define INNER 160
#define EB 64      // edges per block
#define NB 32      // nodes per block (k_node)

// ---------------- scratch ----------------
__device__ float g_m[(size_t)EMAX * 160];      // per-edge message m
__device__ float g_logits[(size_t)EMAX * 8];   // logits, later overwritten with softmax weights
__device__ float g_msgx[(size_t)EMAX * 3];
__device__ float g_hagg[(size_t)NMAX * 128];
__device__ float g_P[(size_t)NMAX * 320];      // precomputed h@We1 (src half | dst half)
__device__ int g_deg[NMAX];
__device__ int g_cursor[NMAX];
__device__ int g_start[NMAX + 1];
__device__ int g_eid[EMAX];

// ---------------- helpers ----------------
typedef unsigned long long ull;
__device__ __forceinline__ ull pk2(float a, float b) {
    ull r;
    asm("mov.b64 %0, {%1, %2};" : "=l"(r) : "r"(__float_as_uint(a)), "r"(__float_as_uint(b)));
    return r;
}
__device__ __forceinline__ void upk2(ull v, float &a, float &b) {
    unsigned int lo, hi;
    asm("mov.b64 {%0, %1}, %2;" : "=r"(lo), "=r"(hi) : "l"(v));
    a = __uint_as_float(lo); b = __uint_as_float(hi);
}
__device__ __forceinline__ void ffma2(ull &d, ull a, ull b) {
    asm("fma.rn.f32x2 %0, %1, %2, %3;" : "=l"(d) : "l"(a), "l"(b), "l"(d));
}
__device__ __forceinline__ float siluf(float x) { return x / (1.0f + __expf(-x)); }
__device__ __forceinline__ float getc(const float4& v, int kk) {
    return kk == 0 ? v.x : kk == 1 ? v.y : kk == 2 ? v.z : v.w;
}
// round fp32 -> tf32 (rna), keep as fp32 bit pattern
__device__ __forceinline__ float tf32f(float x) {
    unsigned r;
    asm("cvt.rna.tf32.f32 %0, %1;" : "=r"(r) : "f"(x));
    return __uint_as_float(r);
}
__device__ __forceinline__ float4 tf32x4(float4 v) {
    v.x = tf32f(v.x); v.y = tf32f(v.y); v.z = tf32f(v.z); v.w = tf32f(v.w);
    return v;
}
__device__ __forceinline__ void mma_tf32(float* c, unsigned a0, unsigned a1,
                                         unsigned a2, unsigned a3,
                                         unsigned b0, unsigned b1) {
    asm volatile(
        "mma.sync.aligned.m16n8k8.row.col.f32.tf32.tf32.f32 "
        "{%0,%1,%2,%3}, {%4,%5,%6,%7}, {%8,%9}, {%0,%1,%2,%3};"
        : "+f"(c[0]), "+f"(c[1]), "+f"(c[2]), "+f"(c[3])
        : "r"(a0), "r"(a1), "r"(a2), "r"(a3), "r"(b0), "r"(b1));
}

// ---------------- CSR build ----------------
__global__ void k_zero(int n) {
    int i = blockIdx.x * blockDim.x + threadIdx.x;
    if (i < n) { g_deg[i] = 0; g_cursor[i] = 0; }
}
__global__ void k_deg(const int* __restrict__ dst, int E) {
    int e = blockIdx.x * blockDim.x + threadIdx.x;
    if (e < E) atomicAdd(&g_deg[dst[e]], 1);
}
__global__ void k_scan(int n) {
    __shared__ int sh[1024];
    int carry = 0;
    for (int base = 0; base < n; base += 1024) {
        int i = base + threadIdx.x;
        int x = (i < n) ? g_deg[i] : 0;
        sh[threadIdx.x] = x;
        __syncthreads();
        for (int off = 1; off < 1024; off <<= 1) {
            int v = (threadIdx.x >= off) ? sh[threadIdx.x - off] : 0;
            __syncthreads();
            sh[threadIdx.x] += v;
            __syncthreads();
        }
        if (i < n) g_start[i] = carry + sh[threadIdx.x] - x;
        carry += sh[1023];
        __syncthreads();
    }
    if (threadIdx.x == 0) g_start[n] = carry;
}
__global__ void k_fill(const int* __restrict__ dst, int E) {
    int e = blockIdx.x * blockDim.x + threadIdx.x;
    if (e < E) {
        int d = dst[e];
        int p = atomicAdd(&g_cursor[d], 1);
        g_eid[g_start[d] + p] = e;
    }
}

// ---------------- k_pre: P = h @ [We1 rows 0:128 | rows 128:256] via tf32 mma ----------------
// One 32x128x320 GEMM per block. Chunk loader stitches the two We1 row-halves side by side.
__global__ void __launch_bounds__(256, 3) k_pre(const float* __restrict__ h,
                                                const float* __restrict__ We1, int N)
{
    extern __shared__ float smp[];
    float* sH  = smp;                 // [32][132]
    float* sW0 = sH + 32 * 132;       // [16][328]
    float* sW1 = sW0 + 16 * 328;      // [16][328]

    const int nb = blockIdx.x * 32;
    const int tid = threadIdx.x;
    for (int idx = tid; idx < 32 * 128; idx += 256) {
        int r = idx >> 7, c = idx & 127;
        int n = min(nb + r, N - 1);
        sH[r * 132 + c] = h[(size_t)n * 128 + c];
    }
    // prefetch chunk 0
    for (int idx = tid; idx < 16 * 80; idx += 256) {
        int r = idx / 80, c4 = idx % 80;
        const float* srcp = (c4 < 40) ? We1 + (size_t)r * 160 + 4 * c4
                                      : We1 + (size_t)(128 + r) * 160 + 4 * (c4 - 40);
        *(float4*)(sW0 + r * 328 + 4 * c4) = tf32x4(__ldg((const float4*)srcp));
    }
    __syncthreads();

    const int warp = tid >> 5, lane = tid & 31;
    const int gid = lane >> 2, tig = lane & 3;
    const int mr = (warp & 1) * 16;
    const int nc0 = (warp >> 1) * 80;
    float acc[10][4];
    #pragma unroll
    for (int ns = 0; ns < 10; ns++)
        #pragma unroll
        for (int q = 0; q < 4; q++) acc[ns][q] = 0.f;

    for (int ch = 0; ch < 8; ch++) {
        const float* wbuf = (ch & 1) ? sW1 : sW0;
        if (ch < 7) {
            float* nbuf = (ch & 1) ? sW0 : sW1;
            int k0 = 16 * (ch + 1);
            for (int idx = tid; idx < 16 * 80; idx += 256) {
                int r = idx / 80, c4 = idx % 80;
                const float* srcp = (c4 < 40) ? We1 + (size_t)(k0 + r) * 160 + 4 * c4
                                              : We1 + (size_t)(128 + k0 + r) * 160 + 4 * (c4 - 40);
                *(float4*)(nbuf + r * 328 + 4 * c4) = tf32x4(__ldg((const float4*)srcp));
            }
        }
        #pragma unroll
        for (int ks = 0; ks < 2; ks++) {
            const float* ar = sH + (mr + gid) * 132 + ch * 16 + ks * 8;
            unsigned a0 = __float_as_uint(tf32f(ar[tig]));
            unsigned a1 = __float_as_uint(tf32f(ar[8 * 132 + tig]));
            unsigned a2 = __float_as_uint(tf32f(ar[tig + 4]));
            unsigned a3 = __float_as_uint(tf32f(ar[8 * 132 + tig + 4]));
            const float* br  = wbuf + (ks * 8 + tig) * 328 + nc0 + gid;
            const float* br2 = wbuf + (ks * 8 + tig + 4) * 328 + nc0 + gid;
            #pragma unroll
            for (int ns = 0; ns < 10; ns++)
                mma_tf32(acc[ns], a0, a1, a2, a3,
                         __float_as_uint(br[ns * 8]), __float_as_uint(br2[ns * 8]));
        }
        __syncthreads();
    }
    // epilogue -> g_P
    int n0 = nb + mr + gid, n1 = n0 + 8;
    #pragma unroll
    for (int ns = 0; ns < 10; ns++) {
        int col = nc0 + ns * 8 + tig * 2;
        if (n0 < N)
            *(float2*)(g_P + (size_t)n0 * 320 + col) = make_float2(acc[ns][0], acc[ns][1]);
        if (n1 < N)
            *(float2*)(g_P + (size_t)n1 * 320 + col) = make_float2(acc[ns][2], acc[ns][3]);
    }
}

// chunk loader: 16 rows x 160 cols of W -> tf32-rounded, stride-168 smem buffer
__device__ __forceinline__ void load_w_chunk_tf32(float* dstbuf, const float* __restrict__ W,
                                                  int k0, int tid) {
    #pragma unroll
    for (int i = 0; i < 3; i++) {
        int idx = tid + 256 * i;
        if (i < 2 || idx < 640) {
            int r = idx / 40, c4 = idx % 40;
            float4 v = __ldg((const float4*)(W + (size_t)(k0 + r) * 160 + 4 * c4));
            *(float4*)(dstbuf + r * 168 + 4 * c4) = tf32x4(v);
        }
    }
}

// ---------------- fused edge kernel (GEMM2 + tails on tf32 tensor cores) ----------------
__global__ void __launch_bounds__(256, 3) k_edge(
    const float* __restrict__ coords, const float* __restrict__ a,
    const int* __restrict__ src, const int* __restrict__ dst,
    const float* __restrict__ We1, const float* __restrict__ be1,
    const float* __restrict__ We2, const float* __restrict__ be2,
    const float* __restrict__ Wc, const float* __restrict__ Wa,
    int E)
{
    extern __shared__ float sm_e[];
    float* sm1  = sm_e;               // [64][164]
    float* sWA  = sm1 + 64 * 164;     // weight buffer A (2720 floats)
    float* sWB  = sWA + 2720;         // weight buffer B (2720 floats; GEMM2 stride 168, W9 stride 16)
    float* sA   = sWB + 2720;         // [64][16]
    float* sRad = sA + 64 * 16;       // [64]
    float* sDx  = sRad + 64;          // [64]
    float* sDy  = sDx + 64;
    float* sDz  = sDy + 64;
    int*   sSrc = (int*)(sDz + 64);   // [64]
    int*   sDst = sSrc + 64;          // [64]

    const int tid = threadIdx.x;
    const int eg = blockIdx.x * EB;
    const int warp = tid >> 5, lane = tid & 31;

    // ---- stage 0: gather edge extras + We1 tail into A (stride 160) + We2 chunk0 into B ----
    for (int e = warp; e < EB; e += 8) {
        int ed = eg + e; if (ed > E - 1) ed = E - 1;
        if (lane < 16) sA[e * 16 + lane] = __ldg(a + (size_t)ed * 16 + lane);
        if (lane == 0) {
            int si = src[ed], di = dst[ed];
            sSrc[e] = si; sDst[e] = di;
            float dx = coords[si * 3 + 0] - coords[di * 3 + 0];
            float dy = coords[si * 3 + 1] - coords[di * 3 + 1];
            float dz = coords[si * 3 + 2] - coords[di * 3 + 2];
            sRad[e] = dx * dx + dy * dy + dz * dz;
            sDx[e] = dx; sDy[e] = dy; sDz[e] = dz;
        }
    }
    // We1 rows 256..272 (17 x 160)
    #pragma unroll
    for (int i = 0; i < 3; i++) {
        int idx = tid + 256 * i;
        if (i < 2 || idx < 680) {
            int r = idx / 40, c4 = idx % 40;
            *(float4*)(sWA + r * 160 + 4 * c4) =
                __ldg((const float4*)(We1 + (size_t)(256 + r) * 160 + 4 * c4));
        }
    }
    load_w_chunk_tf32(sWB, We2, 0, tid);
    __syncthreads();

    const int ecg = tid >> 4;   // rows ecg + 16*i
    const int jcg = tid & 15;   // cols 4jcg..+3, 64+4jcg..+3, 128+2jcg,+1

    // ---- GEMM1-lite: m1 = silu(P1[src] + P2[dst] + [rad,a]@We1[256:273] + be1) ----
    {
        ull acc[4][5];
        #pragma unroll
        for (int i = 0; i < 4; i++) {
            int r = ecg + 16 * i;
            const float* Ps = g_P + (size_t)sSrc[r] * 320;
            const float* Pd = g_P + (size_t)sDst[r] * 320 + 160;
            float4 a0 = __ldg((const float4*)(Ps + 4 * jcg));
            float4 b0 = __ldg((const float4*)(Pd + 4 * jcg));
            acc[i][0] = pk2(a0.x + b0.x, a0.y + b0.y);
            acc[i][1] = pk2(a0.z + b0.z, a0.w + b0.w);
            float4 a1 = __ldg((const float4*)(Ps + 64 + 4 * jcg));
            float4 b1 = __ldg((const float4*)(Pd + 64 + 4 * jcg));
            acc[i][2] = pk2(a1.x + b1.x, a1.y + b1.y);
            acc[i][3] = pk2(a1.z + b1.z, a1.w + b1.w);
            float2 a2 = __ldg((const float2*)(Ps + 128 + 2 * jcg));
            float2 b2 = __ldg((const float2*)(Pd + 128 + 2 * jcg));
            acc[i][4] = pk2(a2.x + b2.x, a2.y + b2.y);
        }
        #pragma unroll 4
        for (int k = 0; k < 17; k++) {
            const float* wr = sWA + k * 160;
            ulonglong2 W0 = *(const ulonglong2*)(wr + 4 * jcg);
            ulonglong2 W1 = *(const ulonglong2*)(wr + 64 + 4 * jcg);
            ull W2 = *(const ull*)(wr + 128 + 2 * jcg);
            #pragma unroll
            for (int i = 0; i < 4; i++) {
                int r = ecg + 16 * i;
                float c = (k == 0) ? sRad[r] : sA[r * 16 + (k - 1)];
                ull fa = pk2(c, c);
                ffma2(acc[i][0], fa, W0.x); ffma2(acc[i][1], fa, W0.y);
                ffma2(acc[i][2], fa, W1.x); ffma2(acc[i][3], fa, W1.y);
                ffma2(acc[i][4], fa, W2);
            }
        }
        #pragma unroll
        for (int i = 0; i < 4; i++) {
            float* orow = sm1 + (ecg + 16 * i) * 164;
            float lo, hi;
            int c = 4 * jcg;
            upk2(acc[i][0], lo, hi);
            orow[c]   = tf32f(siluf(lo + __ldg(be1 + c)));
            orow[c+1] = tf32f(siluf(hi + __ldg(be1 + c + 1)));
            upk2(acc[i][1], lo, hi);
            orow[c+2] = tf32f(siluf(lo + __ldg(be1 + c + 2)));
            orow[c+3] = tf32f(siluf(hi + __ldg(be1 + c + 3)));
            c = 64 + 4 * jcg;
            upk2(acc[i][2], lo, hi);
            orow[c]   = tf32f(siluf(lo + __ldg(be1 + c)));
            orow[c+1] = tf32f(siluf(hi + __ldg(be1 + c + 1)));
            upk2(acc[i][3], lo, hi);
            orow[c+2] = tf32f(siluf(lo + __ldg(be1 + c + 2)));
            orow[c+3] = tf32f(siluf(hi + __ldg(be1 + c + 3)));
            c = 128 + 2 * jcg;
            upk2(acc[i][4], lo, hi);
            orow[c]   = tf32f(siluf(lo + __ldg(be1 + c)));
            orow[c+1] = tf32f(siluf(hi + __ldg(be1 + c + 1)));
        }
    }
    __syncthreads();

    // ---- GEMM2 via tf32 mma.sync: m = silu(m1 @ We2 + be2), in-place into sm1 ----
    {
        const int gid = lane >> 2, tig = lane & 3;
        const int mr  = (warp & 3) * 16;       // M-tile rows mr..mr+15
        const int nb0 = (warp >> 2) * 80;      // N half: 80 cols, 10 subtiles of 8
        float c[10][4];
        #pragma unroll
        for (int ns = 0; ns < 10; ns++)
            #pragma unroll
            for (int q = 0; q < 4; q++) c[ns][q] = 0.f;

        for (int ch = 0; ch < 10; ch++) {
            const float* wbuf = (ch & 1) ? sWA : sWB;     // stride 168
            if (ch < 9) {
                load_w_chunk_tf32((ch & 1) ? sWB : sWA, We2, 16 * (ch + 1), tid);
            } else {
                // ch==9 computes from sWA; sWB is free -> stage W9 = [Wa | Wc | 0] (160x16, stride 16)
                #pragma unroll
                for (int i = 0; i < 3; i++) {
                    int idx = tid + 256 * i;
                    if (idx < 640) {
                        int k = idx >> 2, c4 = idx & 3;
                        float4 v;
                        if (c4 < 2) {
                            float4 wa = __ldg((const float4*)(Wa + k * 8 + 4 * c4));
                            v = make_float4(tf32f(wa.x), tf32f(wa.y), tf32f(wa.z), tf32f(wa.w));
                        } else if (c4 == 2) {
                            v = make_float4(tf32f(__ldg(Wc + k)), 0.f, 0.f, 0.f);
                        } else {
                            v = make_float4(0.f, 0.f, 0.f, 0.f);
                        }
                        *(float4*)(sWB + k * 16 + 4 * c4) = v;
                    }
                }
            }
            #pragma unroll
            for (int ks = 0; ks < 2; ks++) {
                const float* ar = sm1 + (mr + gid) * 164 + ch * 16 + ks * 8;
                unsigned a0 = __float_as_uint(ar[tig]);
                unsigned a1 = __float_as_uint(ar[8 * 164 + tig]);
                unsigned a2 = __float_as_uint(ar[tig + 4]);
                unsigned a3 = __float_as_uint(ar[8 * 164 + tig + 4]);
                const float* br  = wbuf + (ks * 8 + tig) * 168 + nb0 + gid;
                const float* br2 = wbuf + (ks * 8 + tig + 4) * 168 + nb0 + gid;
                #pragma unroll
                for (int ns = 0; ns < 10; ns++) {
                    unsigned b0 = __float_as_uint(br[ns * 8]);
                    unsigned b1 = __float_as_uint(br2[ns * 8]);
                    mma_tf32(c[ns], a0, a1, a2, a3, b0, b1);
                }
            }
            __syncthreads();   // compute of ch done by all; prefetch of ch+1 / W9 visible
        }
        // epilogue: bias + silu, in-place store (all m1 reads drained by last sync)
        #pragma unroll
        for (int ns = 0; ns < 10; ns++) {
            int col = nb0 + ns * 8 + tig * 2;
            float b0v = __ldg(be2 + col), b1v = __ldg(be2 + col + 1);
            float* r0 = sm1 + (mr + gid) * 164 + col;
            float* r1 = sm1 + (mr + gid + 8) * 164 + col;
            r0[0] = siluf(c[ns][0] + b0v); r0[1] = siluf(c[ns][1] + b1v);
            r1[0] = siluf(c[ns][2] + b0v); r1[1] = siluf(c[ns][3] + b1v);
        }
    }
    __syncthreads();

    // ---- tails: warps 0-3 compute logits+coord via mma; warps 4-7 stream m to global ----
    if (warp < 4) {
        const int gid = lane >> 2, tig = lane & 3;
        const int mr = warp * 16;
        float c0[4] = {0.f, 0.f, 0.f, 0.f};   // cols 0-7  (logits)
        float c1[4] = {0.f, 0.f, 0.f, 0.f};   // cols 8-15 (col 8 = Wc)
        #pragma unroll
        for (int k0 = 0; k0 < INNER; k0 += 8) {
            const float* ar = sm1 + (mr + gid) * 164 + k0;
            unsigned a0 = __float_as_uint(tf32f(ar[tig]));
            unsigned a1 = __float_as_uint(tf32f(ar[8 * 164 + tig]));
            unsigned a2 = __float_as_uint(tf32f(ar[tig + 4]));
            unsigned a3 = __float_as_uint(tf32f(ar[8 * 164 + tig + 4]));
            const float* br  = sWB + (k0 + tig) * 16;
            const float* br2 = sWB + (k0 + tig + 4) * 16;
            unsigned b00 = __float_as_uint(br[gid]);
            unsigned b01 = __float_as_uint(br2[gid]);
            unsigned b10 = __float_as_uint(br[8 + gid]);
            unsigned b11 = __float_as_uint(br2[8 + gid]);
            mma_tf32(c0, a0, a1, a2, a3, b00, b01);
            mma_tf32(c1, a0, a1, a2, a3, b10, b11);
        }
        int e0 = mr + gid, e1 = mr + gid + 8;
        int ed0 = eg + e0, ed1 = eg + e1;
        if (ed0 < E)
            *(float2*)(g_logits + (size_t)ed0 * 8 + 2 * tig) = make_float2(c0[0], c0[1]);
        if (ed1 < E)
            *(float2*)(g_logits + (size_t)ed1 * 8 + 2 * tig) = make_float2(c0[2], c0[3]);
        if (tig == 0) {
            if (ed0 < E) {
                float s = c1[0] / (sqrtf(sRad[e0] + 1e-5f) + 1.0f);
                g_msgx[(size_t)ed0 * 3 + 0] = sDx[e0] * s;
                g_msgx[(size_t)ed0 * 3 + 1] = sDy[e0] * s;
                g_msgx[(size_t)ed0 * 3 + 2] = sDz[e0] * s;
            }
            if (ed1 < E) {
                float s = c1[2] / (sqrtf(sRad[e1] + 1e-5f) + 1.0f);
                g_msgx[(size_t)ed1 * 3 + 0] = sDx[e1] * s;
                g_msgx[(size_t)ed1 * 3 + 1] = sDy[e1] * s;
                g_msgx[(size_t)ed1 * 3 + 2] = sDz[e1] * s;
            }
        }
    } else {
        for (int idx = tid - 128; idx < 64 * 40; idx += 128) {
            int r = idx / 40, c4 = idx % 40;
            int ed = eg + r;
            if (ed < E)
                *(float4*)(g_m + (size_t)ed * 160 + 4 * c4) = *(const float4*)(sm1 + r * 164 + 4 * c4);
        }
    }
}

// ---------------- warp-per-node aggregation: in-place weights, streaming loop ----------------
__global__ void __launch_bounds__(256) k_agg(const float* __restrict__ coords,
                                             const float* __restrict__ Wv,
                                             float* __restrict__ out_coords, int N)
{
    __shared__ float sS[8][8][164];   // node, head, k
    const int tid = threadIdx.x;
    const int warp = tid >> 5, lane = tid & 31;
    const int nb = blockIdx.x * 8;
    const int n = nb + warp;
    const int le = lane >> 3, lh = lane & 7;

    if (n < N) {
        const int s0 = g_start[n];
        const int deg = g_start[n + 1] - s0;

        // --- phase 1: softmax stats, then overwrite g_logits with normalized weights ---
        float mx = -3.0e38f;
        for (int c = le; c < deg; c += 4) {
            int e = g_eid[s0 + c];
            mx = fmaxf(mx, __ldg(g_logits + (size_t)e * 8 + lh));
        }
        mx = fmaxf(mx, __shfl_xor_sync(~0u, mx, 8));
        mx = fmaxf(mx, __shfl_xor_sync(~0u, mx, 16));
        float den = 0.f;
        for (int c = le; c < deg; c += 4) {
            int e = g_eid[s0 + c];
            den += __expf(__ldg(g_logits + (size_t)e * 8 + lh) - mx);
        }
        den += __shfl_xor_sync(~0u, den, 8);
        den += __shfl_xor_sync(~0u, den, 16);
        float rden = 1.f / den;
        for (int c = le; c < deg; c += 4) {
            int e = g_eid[s0 + c];
            float w = __expf(__ldg(g_logits + (size_t)e * 8 + lh) - mx) * rden;
            g_logits[(size_t)e * 8 + lh] = w;     // this edge belongs only to this warp
        }
        __syncwarp();

        // --- phase 2: streaming accumulation, no barriers ---
        float acc[8][5];
        #pragma unroll
        for (int hh = 0; hh < 8; hh++)
            #pragma unroll
            for (int q = 0; q < 5; q++) acc[hh][q] = 0.f;

        for (int i = 0; i < deg; i++) {
            int e = g_eid[s0 + i];
            float4 wlo = __ldg((const float4*)(g_logits + (size_t)e * 8));
            float4 whi = __ldg((const float4*)(g_logits + (size_t)e * 8 + 4));
            float v[5];
            #pragma unroll
            for (int q = 0; q < 5; q++)
                v[q] = __ldg(g_m + (size_t)e * 160 + lane + 32 * q);
            #pragma unroll
            for (int q = 0; q < 5; q++) {
                acc[0][q] += v[q] * wlo.x; acc[1][q] += v[q] * wlo.y;
                acc[2][q] += v[q] * wlo.z; acc[3][q] += v[q] * wlo.w;
                acc[4][q] += v[q] * whi.x; acc[5][q] += v[q] * whi.y;
                acc[6][q] += v[q] * whi.z; acc[7][q] += v[q] * whi.w;
            }
        }
        #pragma unroll
        for (int hh = 0; hh < 8; hh++)
            #pragma unroll
            for (int q = 0; q < 5; q++)
                sS[warp][hh][lane + 32 * q] = acc[hh][q];

        // --- coordinate scatter-sum (lanes 0..2) ---
        if (lane < 3) {
            float cacc = 0.f;
            for (int i = 0; i < deg; i++)
                cacc += __ldg(g_msgx + (size_t)g_eid[s0 + i] * 3 + lane);
            out_coords[n * 3 + lane] = coords[n * 3 + lane] + cacc;
        }
    }
    __syncthreads();

    // --- batched Wv epilogue: h_agg[n][j] = sum_k sS[n][j>>4][k] * Wv[k][j] ---
    {
        const int j = tid & 127, grp = tid >> 7;     // grp 0..1, 4 nodes each
        const int head = j >> 4;
        #pragma unroll
        for (int r = 0; r < 4; r++) {
            int wn = grp * 4 + r;
            int n2 = nb + wn;
            if (n2 < N) {
                const float* sr = sS[wn][head];
                float hv = 0.f;
                #pragma unroll 8
                for (int k = 0; k < INNER; k++) hv += sr[k] * __ldg(Wv + k * 128 + j);
                g_hagg[(size_t)n2 * 128 + j] = hv;
            }
        }
    }
}

// ---------------- k_node tf32 GEMM: 32 rows x C cols, K contraction, chunked weights ----------------
template<int K, int C, bool DOSILU, bool HASBIAS>
__device__ __forceinline__ void gemm_tf32_node(
    const float* sIn, int is, const float* __restrict__ W,
    const float* __restrict__ bias, float* sOut, int os,
    float* sW0, float* sW1)
{
    const int tid = threadIdx.x, warp = tid >> 5, lane = tid & 31;
    const int gid = lane >> 2, tig = lane & 3;
    const int mr = (warp & 1) * 16;
    constexpr int NS = C / 32;
    constexpr int CS = C + 8;
    constexpr int NCH = K / 16;
    const int nc0 = (warp >> 1) * (C / 4);
    float acc[NS][4];
    #pragma unroll
    for (int ns = 0; ns < NS; ns++)
        #pragma unroll
        for (int q = 0; q < 4; q++) acc[ns][q] = 0.f;

    // prefetch chunk 0
    for (int idx = tid; idx < 4 * C; idx += 256) {
        int r = idx / (C / 4), c4 = idx % (C / 4);
        *(float4*)(sW0 + r * CS + 4 * c4) =
            tf32x4(__ldg((const float4*)(W + (size_t)r * C + 4 * c4)));
    }
    __syncthreads();

    for (int ch = 0; ch < NCH; ch++) {
        const float* wbuf = (ch & 1) ? sW1 : sW0;
        if (ch < NCH - 1) {
            float* nbuf = (ch & 1) ? sW0 : sW1;
            int k0 = 16 * (ch + 1);
            for (int idx = tid; idx < 4 * C; idx += 256) {
                int r = idx / (C / 4), c4 = idx % (C / 4);
                *(float4*)(nbuf + r * CS + 4 * c4) =
                    tf32x4(__ldg((const float4*)(W + (size_t)(k0 + r) * C + 4 * c4)));
            }
        }
        #pragma unroll
        for (int ks = 0; ks < 2; ks++) {
            const float* ar = sIn + (mr + gid) * is + ch * 16 + ks * 8;
            unsigned a0 = __float_as_uint(tf32f(ar[tig]));
            unsigned a1 = __float_as_uint(tf32f(ar[8 * is + tig]));
            unsigned a2 = __float_as_uint(tf32f(ar[tig + 4]));
            unsigned a3 = __float_as_uint(tf32f(ar[8 * is + tig + 4]));
            const float* br  = wbuf + (ks * 8 + tig) * CS + nc0 + gid;
            const float* br2 = wbuf + (ks * 8 + tig + 4) * CS + nc0 + gid;
            #pragma unroll
            for (int ns = 0; ns < NS; ns++)
                mma_tf32(acc[ns], a0, a1, a2, a3,
                         __float_as_uint(br[ns * 8]), __float_as_uint(br2[ns * 8]));
        }
        __syncthreads();
    }
    // epilogue
    #pragma unroll
    for (int ns = 0; ns < NS; ns++) {
        int col = nc0 + ns * 8 + tig * 2;
        float b0 = HASBIAS ? __ldg(bias + col) : 0.f;
        float b1 = HASBIAS ? __ldg(bias + col + 1) : 0.f;
        float v00 = acc[ns][0] + b0, v01 = acc[ns][1] + b1;
        float v10 = acc[ns][2] + b0, v11 = acc[ns][3] + b1;
        if (DOSILU) { v00 = siluf(v00); v01 = siluf(v01); v10 = siluf(v10); v11 = siluf(v11); }
        float* r0 = sOut + (mr + gid) * os + col;
        float* r1 = sOut + (mr + gid + 8) * os + col;
        r0[0] = v00; r0[1] = v01;
        r1[0] = v10; r1[1] = v11;
    }
}

// ---------------- scalar FiLM GEMM helpers (unchanged) ----------------
template<int K, int NP, int C>
__device__ __forceinline__ void gemm_n(const float* __restrict__ sIn, int is,
                                       const float* __restrict__ W,
                                       ull (&acc)[4][NP][2]) {
    const int tid = threadIdx.x;
    const int ecg = tid >> 5, jcg = tid & 31;
    #pragma unroll
    for (int i = 0; i < 4; i++)
        #pragma unroll
        for (int p = 0; p < NP; p++) { acc[i][p][0] = 0; acc[i][p][1] = 0; }
    for (int k4 = 0; k4 < K; k4 += 4) {
        float4 av[4];
        #pragma unroll
        for (int i = 0; i < 4; i++) av[i] = *(const float4*)(sIn + (ecg + 8 * i) * is + k4);
        #pragma unroll
        for (int kk = 0; kk < 4; kk++) {
            ull fa[4];
            #pragma unroll
            for (int i = 0; i < 4; i++) { float c = getc(av[i], kk); fa[i] = pk2(c, c); }
            const float* wr = W + (k4 + kk) * C + 4 * jcg;
            #pragma unroll
            for (int p = 0; p < NP; p++) {
                if ((C % 128 == 0) || (128 * p + 4 * jcg < C)) {
                    ulonglong2 wv = __ldg((const ulonglong2*)(wr + 128 * p));
                    #pragma unroll
                    for (int i = 0; i < 4; i++) { ffma2(acc[i][p][0], fa[i], wv.x); ffma2(acc[i][p][1], fa[i], wv.y); }
                }
            }
        }
    }
}

__device__ __forceinline__ void film_store(ull (&acc)[4][2][2], float* sScale, float* sShift,
                                           const float* bias) {
    const int tid = threadIdx.x, ecg = tid >> 5, jcg = tid & 31;
    #pragma unroll
    for (int i = 0; i < 4; i++) {
        int r = ecg + 8 * i;
        int c0 = 4 * jcg;
        float v0, v1, v2, v3;
        upk2(acc[i][0][0], v0, v1); upk2(acc[i][0][1], v2, v3);
        v0 += __ldg(bias + c0); v1 += __ldg(bias + c0 + 1);
        v2 += __ldg(bias + c0 + 2); v3 += __ldg(bias + c0 + 3);
        *(float4*)(sScale + r * 132 + c0) = make_float4(v0, v1, v2, v3);
        upk2(acc[i][1][0], v0, v1); upk2(acc[i][1][1], v2, v3);
        v0 += __ldg(bias + 128 + c0); v1 += __ldg(bias + 128 + c0 + 1);
        v2 += __ldg(bias + 128 + c0 + 2); v3 += __ldg(bias + 128 + c0 + 3);
        *(float4*)(sShift + r * 164 + c0) = make_float4(v0, v1, v2, v3);
    }
}

__device__ __forceinline__ void ln_stats(const float* sX, float* sMu, float* sRs) {
    int w = threadIdx.x >> 5, lane = threadIdx.x & 31;
    #pragma unroll
    for (int rr = 0; rr < 4; rr++) {
        int r = w * 4 + rr;
        float4 v = *(const float4*)(sX + r * 132 + 4 * lane);
        float s = v.x + v.y + v.z + v.w;
        float q = v.x * v.x + v.y * v.y + v.z * v.z + v.w * v.w;
        #pragma unroll
        for (int o = 16; o; o >>= 1) {
            s += __shfl_xor_sync(~0u, s, o);
            q += __shfl_xor_sync(~0u, q, o);
        }
        if (lane == 0) {
            float mu = s * (1.f / 128.f);
            float var = q * (1.f / 128.f) - mu * mu;
            sMu[r] = mu; sRs[r] = rsqrtf(var + 1e-5f);
        }
    }
}

// ---------------- batched node kernel (32 nodes/block, tf32 GEMMs) ----------------
__global__ void __launch_bounds__(256, 2) k_node(
    const float* __restrict__ h, const float* __restrict__ res, const float* __restrict__ y,
    const float* __restrict__ Wo,
    const float* __restrict__ Wn1, const float* __restrict__ bn1,
    const float* __restrict__ Wn2, const float* __restrict__ bn2,
    const float* __restrict__ Wf1, const float* __restrict__ bf1,
    const float* __restrict__ Wf2, const float* __restrict__ bf2,
    float* __restrict__ out_h2, float* __restrict__ out_res2, int N)
{
    extern __shared__ float sm_n[];
    float* sA  = sm_n;                 // [32][164]
    float* sB  = sA + 32 * 164;        // [32][132]
    float* sC  = sB + 32 * 132;        // [32][132]
    float* sY  = sC + 32 * 132;        // [32][68]
    float* sMu = sY + 32 * 68;         // [32]
    float* sRs = sMu + 32;             // [32]
    float* sW0 = sRs + 32;             // [16][168]
    float* sW1 = sW0 + 16 * 168;       // [16][168]

    const int nb = blockIdx.x * NB;
    const int tid = threadIdx.x;

    for (int idx = tid; idx < 32 * 128; idx += 256) {
        int r = idx >> 7, c = idx & 127;
        int n = min(nb + r, N - 1);
        sB[r * 132 + c] = g_hagg[(size_t)n * 128 + c];
    }
    for (int idx = tid; idx < 32 * 64; idx += 256) {
        int r = idx >> 6, c = idx & 63;
        int n = min(nb + r, N - 1);
        sY[r * 68 + c] = y[(size_t)n * 64 + c];
    }
    __syncthreads();

    // f2 = h_agg @ Wo (tf32)
    gemm_tf32_node<128, 128, false, false>(sB, 132, Wo, nullptr, sC, 132, sW0, sW1);
    __syncthreads();

    float f2r[16];
    #pragma unroll
    for (int t = 0; t < 16; t++) {
        int idx = tid + 256 * t;
        int r = idx >> 7, c = idx & 127;
        int n = min(nb + r, N - 1);
        float f2v = sC[r * 132 + c];
        f2r[t] = f2v;
        sB[r * 132 + c] = h[(size_t)n * 128 + c] + f2v;
    }
    __syncthreads();
    ln_stats(sB, sMu, sRs);
    __syncthreads();

    {
        ull acc[4][2][2];
        gemm_n<64, 2, 256>(sY, 68, Wf1, acc);
        film_store(acc, sC, sA, bf1);
    }
    __syncthreads();

    #pragma unroll
    for (int t = 0; t < 16; t++) {
        int idx = tid + 256 * t;
        int r = idx >> 7, c = idx & 127;
        float x = sB[r * 132 + c];
        float xn = (x - sMu[r]) * sRs[r];
        sB[r * 132 + c] = xn * (1.f + sC[r * 132 + c]) + sA[r * 164 + c];
    }
    __syncthreads();

    // t = silu(h1 @ Wn1 + bn1) (tf32)
    gemm_tf32_node<128, 160, true, true>(sB, 132, Wn1, bn1, sA, 164, sW0, sW1);
    __syncthreads();

    // f3 = t @ Wn2 + bn2 (tf32)
    gemm_tf32_node<160, 128, false, true>(sA, 164, Wn2, bn2, sC, 132, sW0, sW1);
    __syncthreads();

    #pragma unroll
    for (int t = 0; t < 16; t++) {
        int idx = tid + 256 * t;
        int r = idx >> 7, c = idx & 127;
        float f3 = sC[r * 132 + c];
        int n = nb + r;
        if (n < N) out_res2[(size_t)n * 128 + c] = res[(size_t)n * 128 + c] + f2r[t] + f3;
        sB[r * 132 + c] += f3;
    }
    __syncthreads();
    ln_stats(sB, sMu, sRs);
    __syncthreads();

    {
        ull acc[4][2][2];
        gemm_n<64, 2, 256>(sY, 68, Wf2, acc);
        film_store(acc, sC, sA, bf2);
    }
    __syncthreads();

    #pragma unroll
    for (int t = 0; t < 16; t++) {
        int idx = tid + 256 * t;
        int r = idx >> 7, c = idx & 127;
        int n = nb + r;
        if (n < N) {
            float xn = (sB[r * 132 + c] - sMu[r]) * sRs[r];
            out_h2[(size_t)n * 128 + c] = xn * (1.f + sC[r * 132 + c]) + sA[r * 164 + c];
        }
    }
}

// ---------------- launch ----------------
extern "C" void kernel_launch(void* const* d_in, const int* in_sizes, int n_in,
                              void* d_out, int out_size) {
    const float* h      = (const float*)d_in[0];
    const float* coords = (const float*)d_in[1];
    const float* a      = (const float*)d_in[2];
    const float* y      = (const float*)d_in[3];
    const float* res    = (const float*)d_in[4];
    const int*   src    = (const int*)d_in[5];
    const int*   dst    = (const int*)d_in[6];
    const float* We1 = (const float*)d_in[7];
    const float* be1 = (const float*)d_in[8];
    const float* We2 = (const float*)d_in[9];
    const float* be2 = (const float*)d_in[10];
    const float* Wc  = (const float*)d_in[11];
    const float* Wv  = (const float*)d_in[12];
    const float* Wa  = (const float*)d_in[13];
    const float* Wo  = (const float*)d_in[14];
    const float* Wn1 = (const float*)d_in[15];
    const float* bn1 = (const float*)d_in[16];
    const float* Wn2 = (const float*)d_in[17];
    const float* bn2 = (const float*)d_in[18];
    const float* Wf1 = (const float*)d_in[19];
    const float* bf1 = (const float*)d_in[20];
    const float* Wf2 = (const float*)d_in[21];
    const float* bf2 = (const float*)d_in[22];

    const int N = in_sizes[0] / HID;
    const int E = in_sizes[5];

    float* out = (float*)d_out;
    float* out_h2 = out;
    float* out_coords = out + (size_t)N * HID;
    float* out_res2 = out + (size_t)N * HID + (size_t)N * 3;

    const int SMEM_E = (64 * 164 + 2 * 2720 + 64 * 16 + 64 * 6) * (int)sizeof(float);
    const int SMEM_N = (32 * 164 + 32 * 132 * 2 + 32 * 68 + 64 + 2 * 16 * 168) * (int)sizeof(float);
    const int SMEM_P = (32 * 132 + 2 * 16 * 328) * (int)sizeof(float);
    cudaFuncSetAttribute(k_edge, cudaFuncAttributeMaxDynamicSharedMemorySize, SMEM_E);
    cudaFuncSetAttribute(k_node, cudaFuncAttributeMaxDynamicSharedMemorySize, SMEM_N);
    cudaFuncSetAttribute(k_pre,  cudaFuncAttributeMaxDynamicSharedMemorySize, SMEM_P);

    k_zero<<<(N + 255) / 256, 256>>>(N);
    k_deg<<<(E + 255) / 256, 256>>>(dst, E);
    k_pre<<<(N + 31) / 32, 256, SMEM_P>>>(h, We1, N);
    // k_edge 4th: the ncu window captures launch #4
    k_edge<<<(E + EB - 1) / EB, 256, SMEM_E>>>(coords, a, src, dst,
                                               We1, be1, We2, be2, Wc, Wa, E);
    k_scan<<<1, 1024>>>(N);
    k_fill<<<(E + 255) / 256, 256>>>(dst, E);
    k_agg<<<(N + 7) / 8, 256>>>(coords, Wv, out_coords, N);
    k_node<<<(N + NB - 1) / NB, 256, SMEM_N>>>(h, res, y, Wo, Wn1, bn1, Wn2, bn2,
                                               Wf1, bf1, Wf2, bf2, out_h2, out_res2, N);
}

// round 14
// speedup vs baseline: 1.7048x; 1.0379x over previous
#include <cuda_runtime.h>
#include <math.h>

#define NMAX 25000
#define EMAX 400000
#define HID 128
#define INNER 160
#define EB 64      // edges per block
#define NB 32      // nodes per block (k_node)

// ---------------- scratch ----------------
__device__ float g_m[(size_t)EMAX * 160];      // per-edge message m
__device__ float g_logits[(size_t)EMAX * 8];   // logits, later overwritten with unnormalized exp
__device__ float g_msgx[(size_t)EMAX * 3];
__device__ float g_hagg[(size_t)NMAX * 128];
__device__ float g_P[(size_t)NMAX * 320];      // precomputed h@We1 (src half | dst half)
__device__ int g_deg[NMAX];
__device__ int g_cursor[NMAX];
__device__ int g_start[NMAX + 1];
__device__ int g_eid[EMAX];

// ---------------- helpers ----------------
typedef unsigned long long ull;
__device__ __forceinline__ ull pk2(float a, float b) {
    ull r;
    asm("mov.b64 %0, {%1, %2};" : "=l"(r) : "r"(__float_as_uint(a)), "r"(__float_as_uint(b)));
    return r;
}
__device__ __forceinline__ void upk2(ull v, float &a, float &b) {
    unsigned int lo, hi;
    asm("mov.b64 {%0, %1}, %2;" : "=r"(lo), "=r"(hi) : "l"(v));
    a = __uint_as_float(lo); b = __uint_as_float(hi);
}
__device__ __forceinline__ void ffma2(ull &d, ull a, ull b) {
    asm("fma.rn.f32x2 %0, %1, %2, %3;" : "=l"(d) : "l"(a), "l"(b), "l"(d));
}
__device__ __forceinline__ float siluf(float x) { return x / (1.0f + __expf(-x)); }
__device__ __forceinline__ float getc(const float4& v, int kk) {
    return kk == 0 ? v.x : kk == 1 ? v.y : kk == 2 ? v.z : v.w;
}
// round fp32 -> tf32 (rna), keep as fp32 bit pattern
__device__ __forceinline__ float tf32f(float x) {
    unsigned r;
    asm("cvt.rna.tf32.f32 %0, %1;" : "=r"(r) : "f"(x));
    return __uint_as_float(r);
}
__device__ __forceinline__ float4 tf32x4(float4 v) {
    v.x = tf32f(v.x); v.y = tf32f(v.y); v.z = tf32f(v.z); v.w = tf32f(v.w);
    return v;
}
__device__ __forceinline__ void mma_tf32(float* c, unsigned a0, unsigned a1,
                                         unsigned a2, unsigned a3,
                                         unsigned b0, unsigned b1) {
    asm volatile(
        "mma.sync.aligned.m16n8k8.row.col.f32.tf32.tf32.f32 "
        "{%0,%1,%2,%3}, {%4,%5,%6,%7}, {%8,%9}, {%0,%1,%2,%3};"
        : "+f"(c[0]), "+f"(c[1]), "+f"(c[2]), "+f"(c[3])
        : "r"(a0), "r"(a1), "r"(a2), "r"(a3), "r"(b0), "r"(b1));
}

// ---------------- CSR build ----------------
__global__ void k_zero(int n) {
    int i = blockIdx.x * blockDim.x + threadIdx.x;
    if (i < n) { g_deg[i] = 0; g_cursor[i] = 0; }
}
__global__ void k_deg(const int* __restrict__ dst, int E) {
    int e = blockIdx.x * blockDim.x + threadIdx.x;
    if (e < E) atomicAdd(&g_deg[dst[e]], 1);
}
__global__ void k_scan(int n) {
    __shared__ int sh[1024];
    int carry = 0;
    for (int base = 0; base < n; base += 1024) {
        int i = base + threadIdx.x;
        int x = (i < n) ? g_deg[i] : 0;
        sh[threadIdx.x] = x;
        __syncthreads();
        for (int off = 1; off < 1024; off <<= 1) {
            int v = (threadIdx.x >= off) ? sh[threadIdx.x - off] : 0;
            __syncthreads();
            sh[threadIdx.x] += v;
            __syncthreads();
        }
        if (i < n) g_start[i] = carry + sh[threadIdx.x] - x;
        carry += sh[1023];
        __syncthreads();
    }
    if (threadIdx.x == 0) g_start[n] = carry;
}
__global__ void k_fill(const int* __restrict__ dst, int E) {
    int e = blockIdx.x * blockDim.x + threadIdx.x;
    if (e < E) {
        int d = dst[e];
        int p = atomicAdd(&g_cursor[d], 1);
        g_eid[g_start[d] + p] = e;
    }
}

// ---------------- k_pre: P = h @ [We1 rows 0:128 | rows 128:256] via tf32 mma ----------------
__global__ void __launch_bounds__(256, 3) k_pre(const float* __restrict__ h,
                                                const float* __restrict__ We1, int N)
{
    extern __shared__ float smp[];
    float* sH  = smp;                 // [32][132]
    float* sW0 = sH + 32 * 132;       // [16][328]
    float* sW1 = sW0 + 16 * 328;      // [16][328]

    const int nb = blockIdx.x * 32;
    const int tid = threadIdx.x;
    for (int idx = tid; idx < 32 * 128; idx += 256) {
        int r = idx >> 7, c = idx & 127;
        int n = min(nb + r, N - 1);
        sH[r * 132 + c] = h[(size_t)n * 128 + c];
    }
    for (int idx = tid; idx < 16 * 80; idx += 256) {
        int r = idx / 80, c4 = idx % 80;
        const float* srcp = (c4 < 40) ? We1 + (size_t)r * 160 + 4 * c4
                                      : We1 + (size_t)(128 + r) * 160 + 4 * (c4 - 40);
        *(float4*)(sW0 + r * 328 + 4 * c4) = tf32x4(__ldg((const float4*)srcp));
    }
    __syncthreads();

    const int warp = tid >> 5, lane = tid & 31;
    const int gid = lane >> 2, tig = lane & 3;
    const int mr = (warp & 1) * 16;
    const int nc0 = (warp >> 1) * 80;
    float acc[10][4];
    #pragma unroll
    for (int ns = 0; ns < 10; ns++)
        #pragma unroll
        for (int q = 0; q < 4; q++) acc[ns][q] = 0.f;

    for (int ch = 0; ch < 8; ch++) {
        const float* wbuf = (ch & 1) ? sW1 : sW0;
        if (ch < 7) {
            float* nbuf = (ch & 1) ? sW0 : sW1;
            int k0 = 16 * (ch + 1);
            for (int idx = tid; idx < 16 * 80; idx += 256) {
                int r = idx / 80, c4 = idx % 80;
                const float* srcp = (c4 < 40) ? We1 + (size_t)(k0 + r) * 160 + 4 * c4
                                              : We1 + (size_t)(128 + k0 + r) * 160 + 4 * (c4 - 40);
                *(float4*)(nbuf + r * 328 + 4 * c4) = tf32x4(__ldg((const float4*)srcp));
            }
        }
        #pragma unroll
        for (int ks = 0; ks < 2; ks++) {
            const float* ar = sH + (mr + gid) * 132 + ch * 16 + ks * 8;
            unsigned a0 = __float_as_uint(tf32f(ar[tig]));
            unsigned a1 = __float_as_uint(tf32f(ar[8 * 132 + tig]));
            unsigned a2 = __float_as_uint(tf32f(ar[tig + 4]));
            unsigned a3 = __float_as_uint(tf32f(ar[8 * 132 + tig + 4]));
            const float* br  = wbuf + (ks * 8 + tig) * 328 + nc0 + gid;
            const float* br2 = wbuf + (ks * 8 + tig + 4) * 328 + nc0 + gid;
            #pragma unroll
            for (int ns = 0; ns < 10; ns++)
                mma_tf32(acc[ns], a0, a1, a2, a3,
                         __float_as_uint(br[ns * 8]), __float_as_uint(br2[ns * 8]));
        }
        __syncthreads();
    }
    int n0 = nb + mr + gid, n1 = n0 + 8;
    #pragma unroll
    for (int ns = 0; ns < 10; ns++) {
        int col = nc0 + ns * 8 + tig * 2;
        if (n0 < N)
            *(float2*)(g_P + (size_t)n0 * 320 + col) = make_float2(acc[ns][0], acc[ns][1]);
        if (n1 < N)
            *(float2*)(g_P + (size_t)n1 * 320 + col) = make_float2(acc[ns][2], acc[ns][3]);
    }
}

// chunk loader: 16 rows x 160 cols of W -> tf32-rounded, stride-168 smem buffer
__device__ __forceinline__ void load_w_chunk_tf32(float* dstbuf, const float* __restrict__ W,
                                                  int k0, int tid) {
    #pragma unroll
    for (int i = 0; i < 3; i++) {
        int idx = tid + 256 * i;
        if (i < 2 || idx < 640) {
            int r = idx / 40, c4 = idx % 40;
            float4 v = __ldg((const float4*)(W + (size_t)(k0 + r) * 160 + 4 * c4));
            *(float4*)(dstbuf + r * 168 + 4 * c4) = tf32x4(v);
        }
    }
}

// ---------------- fused edge kernel (GEMM2 + tails on tf32 tensor cores) ----------------
__global__ void __launch_bounds__(256, 3) k_edge(
    const float* __restrict__ coords, const float* __restrict__ a,
    const int* __restrict__ src, const int* __restrict__ dst,
    const float* __restrict__ We1, const float* __restrict__ be1,
    const float* __restrict__ We2, const float* __restrict__ be2,
    const float* __restrict__ Wc, const float* __restrict__ Wa,
    int E)
{
    extern __shared__ float sm_e[];
    float* sm1  = sm_e;               // [64][164]
    float* sWA  = sm1 + 64 * 164;     // weight buffer A (2720 floats)
    float* sWB  = sWA + 2720;         // weight buffer B (2720 floats)
    float* sA   = sWB + 2720;         // [64][16]
    float* sRad = sA + 64 * 16;       // [64]
    float* sDx  = sRad + 64;          // [64]
    float* sDy  = sDx + 64;
    float* sDz  = sDy + 64;
    int*   sSrc = (int*)(sDz + 64);   // [64]
    int*   sDst = sSrc + 64;          // [64]

    const int tid = threadIdx.x;
    const int eg = blockIdx.x * EB;
    const int warp = tid >> 5, lane = tid & 31;

    for (int e = warp; e < EB; e += 8) {
        int ed = eg + e; if (ed > E - 1) ed = E - 1;
        if (lane < 16) sA[e * 16 + lane] = __ldg(a + (size_t)ed * 16 + lane);
        if (lane == 0) {
            int si = src[ed], di = dst[ed];
            sSrc[e] = si; sDst[e] = di;
            float dx = coords[si * 3 + 0] - coords[di * 3 + 0];
            float dy = coords[si * 3 + 1] - coords[di * 3 + 1];
            float dz = coords[si * 3 + 2] - coords[di * 3 + 2];
            sRad[e] = dx * dx + dy * dy + dz * dz;
            sDx[e] = dx; sDy[e] = dy; sDz[e] = dz;
        }
    }
    #pragma unroll
    for (int i = 0; i < 3; i++) {
        int idx = tid + 256 * i;
        if (i < 2 || idx < 680) {
            int r = idx / 40, c4 = idx % 40;
            *(float4*)(sWA + r * 160 + 4 * c4) =
                __ldg((const float4*)(We1 + (size_t)(256 + r) * 160 + 4 * c4));
        }
    }
    load_w_chunk_tf32(sWB, We2, 0, tid);
    __syncthreads();

    const int ecg = tid >> 4;
    const int jcg = tid & 15;

    // ---- GEMM1-lite ----
    {
        ull acc[4][5];
        #pragma unroll
        for (int i = 0; i < 4; i++) {
            int r = ecg + 16 * i;
            const float* Ps = g_P + (size_t)sSrc[r] * 320;
            const float* Pd = g_P + (size_t)sDst[r] * 320 + 160;
            float4 a0 = __ldg((const float4*)(Ps + 4 * jcg));
            float4 b0 = __ldg((const float4*)(Pd + 4 * jcg));
            acc[i][0] = pk2(a0.x + b0.x, a0.y + b0.y);
            acc[i][1] = pk2(a0.z + b0.z, a0.w + b0.w);
            float4 a1 = __ldg((const float4*)(Ps + 64 + 4 * jcg));
            float4 b1 = __ldg((const float4*)(Pd + 64 + 4 * jcg));
            acc[i][2] = pk2(a1.x + b1.x, a1.y + b1.y);
            acc[i][3] = pk2(a1.z + b1.z, a1.w + b1.w);
            float2 a2 = __ldg((const float2*)(Ps + 128 + 2 * jcg));
            float2 b2 = __ldg((const float2*)(Pd + 128 + 2 * jcg));
            acc[i][4] = pk2(a2.x + b2.x, a2.y + b2.y);
        }
        #pragma unroll 4
        for (int k = 0; k < 17; k++) {
            const float* wr = sWA + k * 160;
            ulonglong2 W0 = *(const ulonglong2*)(wr + 4 * jcg);
            ulonglong2 W1 = *(const ulonglong2*)(wr + 64 + 4 * jcg);
            ull W2 = *(const ull*)(wr + 128 + 2 * jcg);
            #pragma unroll
            for (int i = 0; i < 4; i++) {
                int r = ecg + 16 * i;
                float c = (k == 0) ? sRad[r] : sA[r * 16 + (k - 1)];
                ull fa = pk2(c, c);
                ffma2(acc[i][0], fa, W0.x); ffma2(acc[i][1], fa, W0.y);
                ffma2(acc[i][2], fa, W1.x); ffma2(acc[i][3], fa, W1.y);
                ffma2(acc[i][4], fa, W2);
            }
        }
        #pragma unroll
        for (int i = 0; i < 4; i++) {
            float* orow = sm1 + (ecg + 16 * i) * 164;
            float lo, hi;
            int c = 4 * jcg;
            upk2(acc[i][0], lo, hi);
            orow[c]   = tf32f(siluf(lo + __ldg(be1 + c)));
            orow[c+1] = tf32f(siluf(hi + __ldg(be1 + c + 1)));
            upk2(acc[i][1], lo, hi);
            orow[c+2] = tf32f(siluf(lo + __ldg(be1 + c + 2)));
            orow[c+3] = tf32f(siluf(hi + __ldg(be1 + c + 3)));
            c = 64 + 4 * jcg;
            upk2(acc[i][2], lo, hi);
            orow[c]   = tf32f(siluf(lo + __ldg(be1 + c)));
            orow[c+1] = tf32f(siluf(hi + __ldg(be1 + c + 1)));
            upk2(acc[i][3], lo, hi);
            orow[c+2] = tf32f(siluf(lo + __ldg(be1 + c + 2)));
            orow[c+3] = tf32f(siluf(hi + __ldg(be1 + c + 3)));
            c = 128 + 2 * jcg;
            upk2(acc[i][4], lo, hi);
            orow[c]   = tf32f(siluf(lo + __ldg(be1 + c)));
            orow[c+1] = tf32f(siluf(hi + __ldg(be1 + c + 1)));
        }
    }
    __syncthreads();

    // ---- GEMM2 via tf32 mma ----
    {
        const int gid = lane >> 2, tig = lane & 3;
        const int mr  = (warp & 3) * 16;
        const int nb0 = (warp >> 2) * 80;
        float c[10][4];
        #pragma unroll
        for (int ns = 0; ns < 10; ns++)
            #pragma unroll
            for (int q = 0; q < 4; q++) c[ns][q] = 0.f;

        for (int ch = 0; ch < 10; ch++) {
            const float* wbuf = (ch & 1) ? sWA : sWB;
            if (ch < 9) {
                load_w_chunk_tf32((ch & 1) ? sWB : sWA, We2, 16 * (ch + 1), tid);
            } else {
                #pragma unroll
                for (int i = 0; i < 3; i++) {
                    int idx = tid + 256 * i;
                    if (idx < 640) {
                        int k = idx >> 2, c4 = idx & 3;
                        float4 v;
                        if (c4 < 2) {
                            float4 wa = __ldg((const float4*)(Wa + k * 8 + 4 * c4));
                            v = make_float4(tf32f(wa.x), tf32f(wa.y), tf32f(wa.z), tf32f(wa.w));
                        } else if (c4 == 2) {
                            v = make_float4(tf32f(__ldg(Wc + k)), 0.f, 0.f, 0.f);
                        } else {
                            v = make_float4(0.f, 0.f, 0.f, 0.f);
                        }
                        *(float4*)(sWB + k * 16 + 4 * c4) = v;
                    }
                }
            }
            #pragma unroll
            for (int ks = 0; ks < 2; ks++) {
                const float* ar = sm1 + (mr + gid) * 164 + ch * 16 + ks * 8;
                unsigned a0 = __float_as_uint(ar[tig]);
                unsigned a1 = __float_as_uint(ar[8 * 164 + tig]);
                unsigned a2 = __float_as_uint(ar[tig + 4]);
                unsigned a3 = __float_as_uint(ar[8 * 164 + tig + 4]);
                const float* br  = wbuf + (ks * 8 + tig) * 168 + nb0 + gid;
                const float* br2 = wbuf + (ks * 8 + tig + 4) * 168 + nb0 + gid;
                #pragma unroll
                for (int ns = 0; ns < 10; ns++) {
                    unsigned b0 = __float_as_uint(br[ns * 8]);
                    unsigned b1 = __float_as_uint(br2[ns * 8]);
                    mma_tf32(c[ns], a0, a1, a2, a3, b0, b1);
                }
            }
            __syncthreads();
        }
        #pragma unroll
        for (int ns = 0; ns < 10; ns++) {
            int col = nb0 + ns * 8 + tig * 2;
            float b0v = __ldg(be2 + col), b1v = __ldg(be2 + col + 1);
            float* r0 = sm1 + (mr + gid) * 164 + col;
            float* r1 = sm1 + (mr + gid + 8) * 164 + col;
            r0[0] = siluf(c[ns][0] + b0v); r0[1] = siluf(c[ns][1] + b1v);
            r1[0] = siluf(c[ns][2] + b0v); r1[1] = siluf(c[ns][3] + b1v);
        }
    }
    __syncthreads();

    // ---- tails ----
    if (warp < 4) {
        const int gid = lane >> 2, tig = lane & 3;
        const int mr = warp * 16;
        float c0[4] = {0.f, 0.f, 0.f, 0.f};
        float c1[4] = {0.f, 0.f, 0.f, 0.f};
        #pragma unroll
        for (int k0 = 0; k0 < INNER; k0 += 8) {
            const float* ar = sm1 + (mr + gid) * 164 + k0;
            unsigned a0 = __float_as_uint(tf32f(ar[tig]));
            unsigned a1 = __float_as_uint(tf32f(ar[8 * 164 + tig]));
            unsigned a2 = __float_as_uint(tf32f(ar[tig + 4]));
            unsigned a3 = __float_as_uint(tf32f(ar[8 * 164 + tig + 4]));
            const float* br  = sWB + (k0 + tig) * 16;
            const float* br2 = sWB + (k0 + tig + 4) * 16;
            unsigned b00 = __float_as_uint(br[gid]);
            unsigned b01 = __float_as_uint(br2[gid]);
            unsigned b10 = __float_as_uint(br[8 + gid]);
            unsigned b11 = __float_as_uint(br2[8 + gid]);
            mma_tf32(c0, a0, a1, a2, a3, b00, b01);
            mma_tf32(c1, a0, a1, a2, a3, b10, b11);
        }
        int e0 = mr + gid, e1 = mr + gid + 8;
        int ed0 = eg + e0, ed1 = eg + e1;
        if (ed0 < E)
            *(float2*)(g_logits + (size_t)ed0 * 8 + 2 * tig) = make_float2(c0[0], c0[1]);
        if (ed1 < E)
            *(float2*)(g_logits + (size_t)ed1 * 8 + 2 * tig) = make_float2(c0[2], c0[3]);
        if (tig == 0) {
            if (ed0 < E) {
                float s = c1[0] / (sqrtf(sRad[e0] + 1e-5f) + 1.0f);
                g_msgx[(size_t)ed0 * 3 + 0] = sDx[e0] * s;
                g_msgx[(size_t)ed0 * 3 + 1] = sDy[e0] * s;
                g_msgx[(size_t)ed0 * 3 + 2] = sDz[e0] * s;
            }
            if (ed1 < E) {
                float s = c1[2] / (sqrtf(sRad[e1] + 1e-5f) + 1.0f);
                g_msgx[(size_t)ed1 * 3 + 0] = sDx[e1] * s;
                g_msgx[(size_t)ed1 * 3 + 1] = sDy[e1] * s;
                g_msgx[(size_t)ed1 * 3 + 2] = sDz[e1] * s;
            }
        }
    } else {
        for (int idx = tid - 128; idx < 64 * 40; idx += 128) {
            int r = idx / 40, c4 = idx % 40;
            int ed = eg + r;
            if (ed < E)
                *(float4*)(g_m + (size_t)ed * 160 + 4 * c4) = *(const float4*)(sm1 + r * 164 + 4 * c4);
        }
    }
}

// ---------------- warp-per-node aggregation: 2-pass softmax, f32x2 packed ----------------
__global__ void __launch_bounds__(256) k_agg(const float* __restrict__ coords,
                                             const float* __restrict__ Wv,
                                             float* __restrict__ out_coords, int N)
{
    __shared__ float sS[8][8][164];   // node, head, k
    const int tid = threadIdx.x;
    const int warp = tid >> 5, lane = tid & 31;
    const int nb = blockIdx.x * 8;
    const int n = nb + warp;
    const int le = lane >> 3, lh = lane & 7;

    if (n < N) {
        const int s0 = g_start[n];
        const int deg = g_start[n + 1] - s0;

        // --- pass 1: per-head max ---
        float mx = -3.0e38f;
        for (int c = le; c < deg; c += 4) {
            int e = g_eid[s0 + c];
            mx = fmaxf(mx, __ldg(g_logits + (size_t)e * 8 + lh));
        }
        mx = fmaxf(mx, __shfl_xor_sync(~0u, mx, 8));
        mx = fmaxf(mx, __shfl_xor_sync(~0u, mx, 16));
        // --- pass 2: write unnormalized exp, accumulate denominator ---
        float den = 0.f;
        for (int c = le; c < deg; c += 4) {
            int e = g_eid[s0 + c];
            float ev = __expf(__ldg(g_logits + (size_t)e * 8 + lh) - mx);
            g_logits[(size_t)e * 8 + lh] = ev;    // edge owned solely by this warp's node
            den += ev;
        }
        den += __shfl_xor_sync(~0u, den, 8);
        den += __shfl_xor_sync(~0u, den, 16);
        float rden = 1.f / den;
        __syncwarp();

        // --- phase 2: streaming accumulation, f32x2-packed head pairs ---
        ull acc2[4][5];
        #pragma unroll
        for (int p = 0; p < 4; p++)
            #pragma unroll
            for (int q = 0; q < 5; q++) acc2[p][q] = 0ull;

        for (int i = 0; i < deg; i++) {
            int e = g_eid[s0 + i];
            float4 wlo = __ldg((const float4*)(g_logits + (size_t)e * 8));
            float4 whi = __ldg((const float4*)(g_logits + (size_t)e * 8 + 4));
            ull w01 = pk2(wlo.x, wlo.y), w23 = pk2(wlo.z, wlo.w);
            ull w45 = pk2(whi.x, whi.y), w67 = pk2(whi.z, whi.w);
            #pragma unroll
            for (int q = 0; q < 5; q++) {
                float v = __ldg(g_m + (size_t)e * 160 + lane + 32 * q);
                ull fa = pk2(v, v);
                ffma2(acc2[0][q], fa, w01); ffma2(acc2[1][q], fa, w23);
                ffma2(acc2[2][q], fa, w45); ffma2(acc2[3][q], fa, w67);
            }
        }
        // deferred normalization at store: rden for head h lives in lane h
        #pragma unroll
        for (int p = 0; p < 4; p++) {
            float r0 = __shfl_sync(~0u, rden, 2 * p);
            float r1 = __shfl_sync(~0u, rden, 2 * p + 1);
            #pragma unroll
            for (int q = 0; q < 5; q++) {
                float lo, hi; upk2(acc2[p][q], lo, hi);
                sS[warp][2 * p][lane + 32 * q]     = lo * r0;
                sS[warp][2 * p + 1][lane + 32 * q] = hi * r1;
            }
        }

        // --- coordinate scatter-sum (lanes 0..2) ---
        if (lane < 3) {
            float cacc = 0.f;
            for (int i = 0; i < deg; i++)
                cacc += __ldg(g_msgx + (size_t)g_eid[s0 + i] * 3 + lane);
            out_coords[n * 3 + lane] = coords[n * 3 + lane] + cacc;
        }
    }
    __syncthreads();

    // --- Wv epilogue: one node per thread-group, f32x2, coalesced Wv rows ---
    {
        const int wn = tid >> 5;        // node 0..7
        const int j4 = lane;            // cols 4*j4 .. 4*j4+3
        const int head = j4 >> 2;
        const int n2 = nb + wn;
        if (n2 < N) {
            const float* sr = sS[wn][head];
            ull a01 = 0ull, a23 = 0ull;
            #pragma unroll 8
            for (int k = 0; k < INNER; k++) {
                float s = sr[k];
                ull fa = pk2(s, s);
                ulonglong2 w = __ldg((const ulonglong2*)(Wv + (size_t)k * 128 + 4 * j4));
                ffma2(a01, fa, w.x); ffma2(a23, fa, w.y);
            }
            float x0, x1, x2, x3;
            upk2(a01, x0, x1); upk2(a23, x2, x3);
            *(float4*)(g_hagg + (size_t)n2 * 128 + 4 * j4) = make_float4(x0, x1, x2, x3);
        }
    }
}

// ---------------- k_node tf32 GEMM ----------------
template<int K, int C, bool DOSILU, bool HASBIAS>
__device__ __forceinline__ void gemm_tf32_node(
    const float* sIn, int is, const float* __restrict__ W,
    const float* __restrict__ bias, float* sOut, int os,
    float* sW0, float* sW1)
{
    const int tid = threadIdx.x, warp = tid >> 5, lane = tid & 31;
    const int gid = lane >> 2, tig = lane & 3;
    const int mr = (warp & 1) * 16;
    constexpr int NS = C / 32;
    constexpr int CS = C + 8;
    constexpr int NCH = K / 16;
    const int nc0 = (warp >> 1) * (C / 4);
    float acc[NS][4];
    #pragma unroll
    for (int ns = 0; ns < NS; ns++)
        #pragma unroll
        for (int q = 0; q < 4; q++) acc[ns][q] = 0.f;

    for (int idx = tid; idx < 4 * C; idx += 256) {
        int r = idx / (C / 4), c4 = idx % (C / 4);
        *(float4*)(sW0 + r * CS + 4 * c4) =
            tf32x4(__ldg((const float4*)(W + (size_t)r * C + 4 * c4)));
    }
    __syncthreads();

    for (int ch = 0; ch < NCH; ch++) {
        const float* wbuf = (ch & 1) ? sW1 : sW0;
        if (ch < NCH - 1) {
            float* nbuf = (ch & 1) ? sW0 : sW1;
            int k0 = 16 * (ch + 1);
            for (int idx = tid; idx < 4 * C; idx += 256) {
                int r = idx / (C / 4), c4 = idx % (C / 4);
                *(float4*)(nbuf + r * CS + 4 * c4) =
                    tf32x4(__ldg((const float4*)(W + (size_t)(k0 + r) * C + 4 * c4)));
            }
        }
        #pragma unroll
        for (int ks = 0; ks < 2; ks++) {
            const float* ar = sIn + (mr + gid) * is + ch * 16 + ks * 8;
            unsigned a0 = __float_as_uint(tf32f(ar[tig]));
            unsigned a1 = __float_as_uint(tf32f(ar[8 * is + tig]));
            unsigned a2 = __float_as_uint(tf32f(ar[tig + 4]));
            unsigned a3 = __float_as_uint(tf32f(ar[8 * is + tig + 4]));
            const float* br  = wbuf + (ks * 8 + tig) * CS + nc0 + gid;
            const float* br2 = wbuf + (ks * 8 + tig + 4) * CS + nc0 + gid;
            #pragma unroll
            for (int ns = 0; ns < NS; ns++)
                mma_tf32(acc[ns], a0, a1, a2, a3,
                         __float_as_uint(br[ns * 8]), __float_as_uint(br2[ns * 8]));
        }
        __syncthreads();
    }
    #pragma unroll
    for (int ns = 0; ns < NS; ns++) {
        int col = nc0 + ns * 8 + tig * 2;
        float b0 = HASBIAS ? __ldg(bias + col) : 0.f;
        float b1 = HASBIAS ? __ldg(bias + col + 1) : 0.f;
        float v00 = acc[ns][0] + b0, v01 = acc[ns][1] + b1;
        float v10 = acc[ns][2] + b0, v11 = acc[ns][3] + b1;
        if (DOSILU) { v00 = siluf(v00); v01 = siluf(v01); v10 = siluf(v10); v11 = siluf(v11); }
        float* r0 = sOut + (mr + gid) * os + col;
        float* r1 = sOut + (mr + gid + 8) * os + col;
        r0[0] = v00; r0[1] = v01;
        r1[0] = v10; r1[1] = v11;
    }
}

// ---------------- scalar FiLM GEMM helpers ----------------
template<int K, int NP, int C>
__device__ __forceinline__ void gemm_n(const float* __restrict__ sIn, int is,
                                       const float* __restrict__ W,
                                       ull (&acc)[4][NP][2]) {
    const int tid = threadIdx.x;
    const int ecg = tid >> 5, jcg = tid & 31;
    #pragma unroll
    for (int i = 0; i < 4; i++)
        #pragma unroll
        for (int p = 0; p < NP; p++) { acc[i][p][0] = 0; acc[i][p][1] = 0; }
    for (int k4 = 0; k4 < K; k4 += 4) {
        float4 av[4];
        #pragma unroll
        for (int i = 0; i < 4; i++) av[i] = *(const float4*)(sIn + (ecg + 8 * i) * is + k4);
        #pragma unroll
        for (int kk = 0; kk < 4; kk++) {
            ull fa[4];
            #pragma unroll
            for (int i = 0; i < 4; i++) { float c = getc(av[i], kk); fa[i] = pk2(c, c); }
            const float* wr = W + (k4 + kk) * C + 4 * jcg;
            #pragma unroll
            for (int p = 0; p < NP; p++) {
                if ((C % 128 == 0) || (128 * p + 4 * jcg < C)) {
                    ulonglong2 wv = __ldg((const ulonglong2*)(wr + 128 * p));
                    #pragma unroll
                    for (int i = 0; i < 4; i++) { ffma2(acc[i][p][0], fa[i], wv.x); ffma2(acc[i][p][1], fa[i], wv.y); }
                }
            }
        }
    }
}

__device__ __forceinline__ void film_store(ull (&acc)[4][2][2], float* sScale, float* sShift,
                                           const float* bias) {
    const int tid = threadIdx.x, ecg = tid >> 5, jcg = tid & 31;
    #pragma unroll
    for (int i = 0; i < 4; i++) {
        int r = ecg + 8 * i;
        int c0 = 4 * jcg;
        float v0, v1, v2, v3;
        upk2(acc[i][0][0], v0, v1); upk2(acc[i][0][1], v2, v3);
        v0 += __ldg(bias + c0); v1 += __ldg(bias + c0 + 1);
        v2 += __ldg(bias + c0 + 2); v3 += __ldg(bias + c0 + 3);
        *(float4*)(sScale + r * 132 + c0) = make_float4(v0, v1, v2, v3);
        upk2(acc[i][1][0], v0, v1); upk2(acc[i][1][1], v2, v3);
        v0 += __ldg(bias + 128 + c0); v1 += __ldg(bias + 128 + c0 + 1);
        v2 += __ldg(bias + 128 + c0 + 2); v3 += __ldg(bias + 128 + c0 + 3);
        *(float4*)(sShift + r * 164 + c0) = make_float4(v0, v1, v2, v3);
    }
}

__device__ __forceinline__ void ln_stats(const float* sX, float* sMu, float* sRs) {
    int w = threadIdx.x >> 5, lane = threadIdx.x & 31;
    #pragma unroll
    for (int rr = 0; rr < 4; rr++) {
        int r = w * 4 + rr;
        float4 v = *(const float4*)(sX + r * 132 + 4 * lane);
        float s = v.x + v.y + v.z + v.w;
        float q = v.x * v.x + v.y * v.y + v.z * v.z + v.w * v.w;
        #pragma unroll
        for (int o = 16; o; o >>= 1) {
            s += __shfl_xor_sync(~0u, s, o);
            q += __shfl_xor_sync(~0u, q, o);
        }
        if (lane == 0) {
            float mu = s * (1.f / 128.f);
            float var = q * (1.f / 128.f) - mu * mu;
            sMu[r] = mu; sRs[r] = rsqrtf(var + 1e-5f);
        }
    }
}

// ---------------- batched node kernel (32 nodes/block, tf32 GEMMs) ----------------
__global__ void __launch_bounds__(256, 2) k_node(
    const float* __restrict__ h, const float* __restrict__ res, const float* __restrict__ y,
    const float* __restrict__ Wo,
    const float* __restrict__ Wn1, const float* __restrict__ bn1,
    const float* __restrict__ Wn2, const float* __restrict__ bn2,
    const float* __restrict__ Wf1, const float* __restrict__ bf1,
    const float* __restrict__ Wf2, const float* __restrict__ bf2,
    float* __restrict__ out_h2, float* __restrict__ out_res2, int N)
{
    extern __shared__ float sm_n[];
    float* sA  = sm_n;                 // [32][164]
    float* sB  = sA + 32 * 164;        // [32][132]
    float* sC  = sB + 32 * 132;        // [32][132]
    float* sY  = sC + 32 * 132;        // [32][68]
    float* sMu = sY + 32 * 68;         // [32]
    float* sRs = sMu + 32;             // [32]
    float* sW0 = sRs + 32;             // [16][168]
    float* sW1 = sW0 + 16 * 168;       // [16][168]

    const int nb = blockIdx.x * NB;
    const int tid = threadIdx.x;

    for (int idx = tid; idx < 32 * 128; idx += 256) {
        int r = idx >> 7, c = idx & 127;
        int n = min(nb + r, N - 1);
        sB[r * 132 + c] = g_hagg[(size_t)n * 128 + c];
    }
    for (int idx = tid; idx < 32 * 64; idx += 256) {
        int r = idx >> 6, c = idx & 63;
        int n = min(nb + r, N - 1);
        sY[r * 68 + c] = y[(size_t)n * 64 + c];
    }
    __syncthreads();

    gemm_tf32_node<128, 128, false, false>(sB, 132, Wo, nullptr, sC, 132, sW0, sW1);
    __syncthreads();

    float f2r[16];
    #pragma unroll
    for (int t = 0; t < 16; t++) {
        int idx = tid + 256 * t;
        int r = idx >> 7, c = idx & 127;
        int n = min(nb + r, N - 1);
        float f2v = sC[r * 132 + c];
        f2r[t] = f2v;
        sB[r * 132 + c] = h[(size_t)n * 128 + c] + f2v;
    }
    __syncthreads();
    ln_stats(sB, sMu, sRs);
    __syncthreads();

    {
        ull acc[4][2][2];
        gemm_n<64, 2, 256>(sY, 68, Wf1, acc);
        film_store(acc, sC, sA, bf1);
    }
    __syncthreads();

    #pragma unroll
    for (int t = 0; t < 16; t++) {
        int idx = tid + 256 * t;
        int r = idx >> 7, c = idx & 127;
        float x = sB[r * 132 + c];
        float xn = (x - sMu[r]) * sRs[r];
        sB[r * 132 + c] = xn * (1.f + sC[r * 132 + c]) + sA[r * 164 + c];
    }
    __syncthreads();

    gemm_tf32_node<128, 160, true, true>(sB, 132, Wn1, bn1, sA, 164, sW0, sW1);
    __syncthreads();

    gemm_tf32_node<160, 128, false, true>(sA, 164, Wn2, bn2, sC, 132, sW0, sW1);
    __syncthreads();

    #pragma unroll
    for (int t = 0; t < 16; t++) {
        int idx = tid + 256 * t;
        int r = idx >> 7, c = idx & 127;
        float f3 = sC[r * 132 + c];
        int n = nb + r;
        if (n < N) out_res2[(size_t)n * 128 + c] = res[(size_t)n * 128 + c] + f2r[t] + f3;
        sB[r * 132 + c] += f3;
    }
    __syncthreads();
    ln_stats(sB, sMu, sRs);
    __syncthreads();

    {
        ull acc[4][2][2];
        gemm_n<64, 2, 256>(sY, 68, Wf2, acc);
        film_store(acc, sC, sA, bf2);
    }
    __syncthreads();

    #pragma unroll
    for (int t = 0; t < 16; t++) {
        int idx = tid + 256 * t;
        int r = idx >> 7, c = idx & 127;
        int n = nb + r;
        if (n < N) {
            float xn = (sB[r * 132 + c] - sMu[r]) * sRs[r];
            out_h2[(size_t)n * 128 + c] = xn * (1.f + sC[r * 132 + c]) + sA[r * 164 + c];
        }
    }
}

// ---------------- launch ----------------
extern "C" void kernel_launch(void* const* d_in, const int* in_sizes, int n_in,
                              void* d_out, int out_size) {
    const float* h      = (const float*)d_in[0];
    const float* coords = (const float*)d_in[1];
    const float* a      = (const float*)d_in[2];
    const float* y      = (const float*)d_in[3];
    const float* res    = (const float*)d_in[4];
    const int*   src    = (const int*)d_in[5];
    const int*   dst    = (const int*)d_in[6];
    const float* We1 = (const float*)d_in[7];
    const float* be1 = (const float*)d_in[8];
    const float* We2 = (const float*)d_in[9];
    const float* be2 = (const float*)d_in[10];
    const float* Wc  = (const float*)d_in[11];
    const float* Wv  = (const float*)d_in[12];
    const float* Wa  = (const float*)d_in[13];
    const float* Wo  = (const float*)d_in[14];
    const float* Wn1 = (const float*)d_in[15];
    const float* bn1 = (const float*)d_in[16];
    const float* Wn2 = (const float*)d_in[17];
    const float* bn2 = (const float*)d_in[18];
    const float* Wf1 = (const float*)d_in[19];
    const float* bf1 = (const float*)d_in[20];
    const float* Wf2 = (const float*)d_in[21];
    const float* bf2 = (const float*)d_in[22];

    const int N = in_sizes[0] / HID;
    const int E = in_sizes[5];

    float* out = (float*)d_out;
    float* out_h2 = out;
    float* out_coords = out + (size_t)N * HID;
    float* out_res2 = out + (size_t)N * HID + (size_t)N * 3;

    const int SMEM_E = (64 * 164 + 2 * 2720 + 64 * 16 + 64 * 6) * (int)sizeof(float);
    const int SMEM_N = (32 * 164 + 32 * 132 * 2 + 32 * 68 + 64 + 2 * 16 * 168) * (int)sizeof(float);
    const int SMEM_P = (32 * 132 + 2 * 16 * 328) * (int)sizeof(float);
    cudaFuncSetAttribute(k_edge, cudaFuncAttributeMaxDynamicSharedMemorySize, SMEM_E);
    cudaFuncSetAttribute(k_node, cudaFuncAttributeMaxDynamicSharedMemorySize, SMEM_N);
    cudaFuncSetAttribute(k_pre,  cudaFuncAttributeMaxDynamicSharedMemorySize, SMEM_P);

    k_zero<<<(N + 255) / 256, 256>>>(N);
    k_deg<<<(E + 255) / 256, 256>>>(dst, E);
    k_pre<<<(N + 31) / 32, 256, SMEM_P>>>(h, We1, N);
    // k_edge 4th: the ncu window captures launch #4
    k_edge<<<(E + EB - 1) / EB, 256, SMEM_E>>>(coords, a, src, dst,
                                               We1, be1, We2, be2, Wc, Wa, E);
    k_scan<<<1, 1024>>>(N);
    k_fill<<<(E + 255) / 256, 256>>>(dst, E);
    k_agg<<<(N + 7) / 8, 256>>>(coords, Wv, out_coords, N);
    k_node<<<(N + NB - 1) / NB, 256, SMEM_N>>>(h, res, y, Wo, Wn1, bn1, Wn2, bn2,
                                               Wf1, bf1, Wf2, bf2, out_h2, out_res2, N);
}